// round 8
// baseline (speedup 1.0000x reference)
#include <cuda_runtime.h>
#include <math.h>
#include <stdint.h>

#define N_ 8192
#define E_ 131072
#define M_ (E_ + N_)          // 139264 edges incl self loops
#define H_ 128
#define K_ 4096
#define WCAP_ 3000000

#define AROWS 6
#define ABLOCKS ((N_ + AROWS - 1)/AROWS)
#define PSH_BYTES (6*K_*4)    // lo: 4 floats/k (rows 0-3), hi: 2 floats/k (rows 4-5)

// ---------------- device scratch ----------------
static __device__ float g_bufA[(size_t)N_*H_];
static __device__ float g_bufB[(size_t)N_*H_];
static __device__ float g_bufC[(size_t)N_*H_];
static __device__ float g_bufT[(size_t)N_*H_];
static __device__ int   g_cnt[N_];
static __device__ int   g_ocnt[N_];
static __device__ int   g_fill[N_];
static __device__ int   g_ofill[N_];
static __device__ int   g_rowptr[N_+1];     // CSR by dst
static __device__ int   g_orowptr[N_+1];    // CSR by src
static __device__ int2  g_adj[M_];          // per dst-CSR pos: (src, norm bits)
static __device__ int   g_oadj[M_];         // per src-CSR pos: dst
static __device__ float g_alpha[M_];        // per dst-CSR pos
static __device__ float g_aq[N_];
static __device__ float g_ah[N_];
static __device__ float g_cl1[N_], g_cl2[N_], g_cl3[N_];
static __device__ float g_fit[N_];
static __device__ int   g_sel[N_];
static __device__ int   g_col[N_];
static __device__ int   g_ncol[K_];
static __device__ float g_xp[(size_t)K_*H_];
static __device__ int   g_scnt[N_];
static __device__ int   g_srowptr[N_+1];
static __device__ int2  g_sp[M_];            // packed (col k, alpha bits), CSR by src
static __device__ int   g_wcnt[N_];
static __device__ int   g_wrowptr[N_+1];
static __device__ int2  g_W[WCAP_];          // W = A*S rows
static __device__ float g_Ac[(size_t)K_*K_];

// ---------------- helpers ----------------
__device__ __forceinline__ int esrc_f(const int* __restrict__ e0, int e){ return (e < E_) ? e0[e] : (e - E_); }
__device__ __forceinline__ int edst_f(const int* __restrict__ e1, int e){ return (e < E_) ? e1[e] : (e - E_); }

// ---------------- small utility kernels ----------------
__global__ void k_init0(){
    int i = blockIdx.x*blockDim.x + threadIdx.x;
    if (i < N_){ g_cnt[i]=0; g_ocnt[i]=0; g_fill[i]=0; g_ofill[i]=0; g_scnt[i]=0; }
}
__global__ void k_zeroN(int* __restrict__ p){
    int i = blockIdx.x*blockDim.x + threadIdx.x;
    if (i < N_) p[i]=0;
}
__global__ void k_count(const int* __restrict__ e0, const int* __restrict__ e1){
    int e = blockIdx.x*blockDim.x + threadIdx.x;
    if (e < M_){
        atomicAdd(&g_cnt[edst_f(e1,e)], 1);
        atomicAdd(&g_ocnt[esrc_f(e0,e)], 1);
    }
}
// exclusive scan of exactly 8192 ints with 1024 threads (shfl-based)
__device__ __forceinline__ void scan8192_body(const int* __restrict__ in, int* __restrict__ out){
    __shared__ int wsum[32];
    int tid=threadIdx.x, lane=tid&31, wid=tid>>5;
    int4 a=((const int4*)in)[tid*2], b=((const int4*)in)[tid*2+1];
    int l[8]={a.x,a.y,a.z,a.w,b.x,b.y,b.z,b.w};
    int s=0;
    #pragma unroll
    for(int q=0;q<8;q++) s+=l[q];
    int inc=s;
    #pragma unroll
    for(int o=1;o<32;o<<=1){ int t=__shfl_up_sync(0xffffffffu,inc,o); if(lane>=o) inc+=t; }
    if(lane==31) wsum[wid]=inc;
    __syncthreads();
    if (wid==0){
        int v = wsum[lane];
        #pragma unroll
        for(int o=1;o<32;o<<=1){ int t=__shfl_up_sync(0xffffffffu,v,o); if(lane>=o) v+=t; }
        wsum[lane]=v;
    }
    __syncthreads();
    int r = inc - s + (wid? wsum[wid-1]:0);
    int4 o1,o2;
    o1.x=r; r+=l[0]; o1.y=r; r+=l[1]; o1.z=r; r+=l[2]; o1.w=r; r+=l[3];
    o2.x=r; r+=l[4]; o2.y=r; r+=l[5]; o2.z=r; r+=l[6]; o2.w=r; r+=l[7];
    ((int4*)out)[tid*2]=o1; ((int4*)out)[tid*2+1]=o2;
    if (tid==1023) out[8192]=r;
}
__global__ void k_scan8192(const int* __restrict__ in, int* __restrict__ out){
    scan8192_body(in, out);
}
__global__ void k_scan2(){
    if (blockIdx.x == 0) scan8192_body(g_cnt, g_rowptr);
    else                 scan8192_body(g_ocnt, g_orowptr);
}
// build positional adjacency with folded norm (dis computed inline)
__global__ void k_fill(const int* __restrict__ e0, const int* __restrict__ e1){
    int e = blockIdx.x*blockDim.x + threadIdx.x;
    if (e < M_){
        int s = esrc_f(e0,e);
        int d = edst_f(e1,e);
        float nm = rsqrtf((float)g_cnt[s]) * rsqrtf((float)g_cnt[d]);
        int pos = g_rowptr[d] + atomicAdd(&g_fill[d],1);
        g_adj[pos] = make_int2(s, __float_as_int(nm));
        int opos = g_orowptr[s] + atomicAdd(&g_ofill[s],1);
        g_oadj[opos] = d;
    }
}

// ---------------- 8192x128 @ 128x128 GEMM ----------------
__global__ void k_gemm(const float* __restrict__ x, const float* __restrict__ w, float* __restrict__ y){
    __shared__ __align__(16) float xs[128*64];   // [kk][r]
    int r0 = blockIdx.x*64;
    int tid = threadIdx.x;
    for (int idx=tid; idx<64*128; idx+=256){
        int r = idx >> 7;
        int kk = idx & 127;
        xs[kk*64 + r] = x[(size_t)(r0+r)*128 + kk];
    }
    __syncthreads();
    int cg = tid & 31;
    int rg = tid >> 5;
    float acc[8][4];
    #pragma unroll
    for(int r=0;r<8;r++){ acc[r][0]=0.f;acc[r][1]=0.f;acc[r][2]=0.f;acc[r][3]=0.f; }
    #pragma unroll 4
    for(int kk=0;kk<128;kk++){
        float4 wv = *(const float4*)(w + kk*128 + cg*4);
        float4 x0 = *(const float4*)(xs + kk*64 + rg*8);
        float4 x1 = *(const float4*)(xs + kk*64 + rg*8 + 4);
        float xv[8] = {x0.x,x0.y,x0.z,x0.w,x1.x,x1.y,x1.z,x1.w};
        #pragma unroll
        for(int r=0;r<8;r++){
            acc[r][0] += xv[r]*wv.x; acc[r][1] += xv[r]*wv.y;
            acc[r][2] += xv[r]*wv.z; acc[r][3] += xv[r]*wv.w;
        }
    }
    #pragma unroll
    for(int r=0;r<8;r++){
        float4 o = make_float4(acc[r][0],acc[r][1],acc[r][2],acc[r][3]);
        *(float4*)(y + (size_t)(r0+rg*8+r)*128 + cg*4) = o;
    }
}

// ---------------- GCN aggregation: warp per dst, float4 lanes ----------------
__global__ void k_aggr(const float* __restrict__ y, const float* __restrict__ b,
                       float* __restrict__ out, int dotanh){
    int d = blockIdx.x*8 + (threadIdx.x>>5);
    int lane = threadIdx.x & 31;
    const float4* y4 = (const float4*)y;
    float4 acc = ((const float4*)b)[lane];
    int beg = g_rowptr[d], end = g_rowptr[d+1];
    int p = beg;
    for (; p+1 < end; p += 2){
        int2 a0 = g_adj[p], a1 = g_adj[p+1];
        float n0 = __int_as_float(a0.y), n1 = __int_as_float(a1.y);
        float4 v0 = y4[(size_t)a0.x*32 + lane];
        float4 v1 = y4[(size_t)a1.x*32 + lane];
        acc.x += n0*v0.x + n1*v1.x;
        acc.y += n0*v0.y + n1*v1.y;
        acc.z += n0*v0.z + n1*v1.z;
        acc.w += n0*v0.w + n1*v1.w;
    }
    if (p < end){
        int2 a0 = g_adj[p];
        float n0 = __int_as_float(a0.y);
        float4 v0 = y4[(size_t)a0.x*32 + lane];
        acc.x += n0*v0.x; acc.y += n0*v0.y; acc.z += n0*v0.z; acc.w += n0*v0.w;
    }
    if (dotanh){
        acc.x = tanhf(acc.x); acc.y = tanhf(acc.y);
        acc.z = tanhf(acc.z); acc.w = tanhf(acc.w);
    }
    ((float4*)out)[(size_t)d*32 + lane] = acc;
}

__global__ void k_segmax(const float* __restrict__ h, float* __restrict__ out){
    int d = blockIdx.x*8 + (threadIdx.x>>5);
    int lane = threadIdx.x & 31;
    const float4* h4 = (const float4*)h;
    float4 acc = make_float4(-INFINITY,-INFINITY,-INFINITY,-INFINITY);
    int beg = g_rowptr[d], end = g_rowptr[d+1];
    for (int p=beg; p<end; p++){
        float4 v = h4[(size_t)g_adj[p].x*32 + lane];
        acc.x = fmaxf(acc.x,v.x); acc.y = fmaxf(acc.y,v.y);
        acc.z = fmaxf(acc.z,v.z); acc.w = fmaxf(acc.w,v.w);
    }
    ((float4*)out)[(size_t)d*32 + lane] = acc;
}

__global__ void k_dots(const float* __restrict__ xq, const float* __restrict__ h,
                       const float* __restrict__ att, const float* __restrict__ bq){
    int node = blockIdx.x*8 + (threadIdx.x>>5);
    int lane = threadIdx.x & 31;
    const float4* xq4 = (const float4*)xq;
    const float4* h4  = (const float4*)h;
    const float4* at4 = (const float4*)att;
    const float4* bq4 = (const float4*)bq;
    float4 a1 = at4[lane], a2 = at4[32+lane];
    float4 xv = xq4[(size_t)node*32+lane], bv = bq4[lane], hv = h4[(size_t)node*32+lane];
    float s1 = a1.x*(xv.x+bv.x) + a1.y*(xv.y+bv.y) + a1.z*(xv.z+bv.z) + a1.w*(xv.w+bv.w);
    float s2 = a2.x*hv.x + a2.y*hv.y + a2.z*hv.z + a2.w*hv.w;
    #pragma unroll
    for (int o=16;o;o>>=1){ s1 += __shfl_down_sync(0xffffffffu,s1,o); s2 += __shfl_down_sync(0xffffffffu,s2,o); }
    if (!lane){ g_aq[node]=s1; g_ah[node]=s2; }
}

// per-dst softmax over in-edges (positional alpha) + cluster rep cx
__global__ void k_softcx(const float* __restrict__ h, float* __restrict__ cx){
    __shared__ float red[128];
    __shared__ float cache[1024];
    __shared__ int   scache[1024];
    int d = blockIdx.x, t = threadIdx.x;
    int beg = g_rowptr[d], end = g_rowptr[d+1];
    float aqd = g_aq[d];
    float mx = -INFINITY;
    for (int s=beg+t; s<end; s+=128){
        int src = g_adj[s].x;
        float sc = aqd + g_ah[src];
        sc = sc > 0.f ? sc : 0.2f*sc;
        if (s-beg < 1024){ cache[s-beg] = sc; scache[s-beg] = src; }
        mx = fmaxf(mx, sc);
    }
    red[t]=mx; __syncthreads();
    for (int o=64;o;o>>=1){ if(t<o) red[t]=fmaxf(red[t],red[t+o]); __syncthreads(); }
    mx = red[0]; __syncthreads();
    float sm = 0.f;
    for (int s=beg+t; s<end; s+=128){
        float sc;
        if (s-beg < 1024) sc = cache[s-beg];
        else { float v = aqd + g_ah[g_adj[s].x]; sc = v>0.f? v : 0.2f*v; }
        float ee = __expf(sc - mx);
        if (s-beg < 1024) cache[s-beg] = ee;
        sm += ee;
    }
    red[t]=sm; __syncthreads();
    for (int o=64;o;o>>=1){ if(t<o) red[t]+=red[t+o]; __syncthreads(); }
    float inv = 1.f/red[0];
    for (int s=beg+t; s<end; s+=128){
        float ee;
        if (s-beg < 1024) ee = cache[s-beg];
        else { float v = aqd + g_ah[g_adj[s].x]; v = v>0.f? v:0.2f*v; ee = __expf(v-mx); }
        float a = ee*inv;
        g_alpha[s] = a;
        if (s-beg < 1024) cache[s-beg] = a;
    }
    __syncthreads();
    float acc = 0.f;
    for (int s=beg; s<end; s++){
        float a; int src;
        if (s-beg < 1024){ a = cache[s-beg]; src = scache[s-beg]; }
        else { a = g_alpha[s]; src = g_adj[s].x; }
        acc += a * h[(size_t)src*128 + t];
    }
    cx[(size_t)d*128 + t] = acc;
}

__global__ void k_le(const float* __restrict__ cx, const float* __restrict__ lw1,
                     const float* __restrict__ lw2, const float* __restrict__ lw3){
    int node = blockIdx.x*8 + (threadIdx.x>>5);
    int lane = threadIdx.x & 31;
    const float4* c4 = (const float4*)cx;
    const float4* w14 = (const float4*)lw1;
    const float4* w24 = (const float4*)lw2;
    const float4* w34 = (const float4*)lw3;
    float4 v = c4[(size_t)node*32+lane];
    float4 w1v = w14[lane], w2v = w24[lane], w3v = w34[lane];
    float s1 = v.x*w1v.x + v.y*w1v.y + v.z*w1v.z + v.w*w1v.w;
    float s2 = v.x*w2v.x + v.y*w2v.y + v.z*w2v.z + v.w*w2v.w;
    float s3 = v.x*w3v.x + v.y*w3v.y + v.z*w3v.z + v.w*w3v.w;
    #pragma unroll
    for (int o=16;o;o>>=1){
        s1 += __shfl_down_sync(0xffffffffu,s1,o);
        s2 += __shfl_down_sync(0xffffffffu,s2,o);
        s3 += __shfl_down_sync(0xffffffffu,s3,o);
    }
    if (!lane){ g_cl1[node]=s1; g_cl2[node]=s2; g_cl3[node]=s3; }
}
__global__ void k_fit(const float* __restrict__ lb1){
    int d = blockIdx.x*blockDim.x + threadIdx.x;
    if (d >= N_) return;
    int beg=g_rowptr[d], end=g_rowptr[d+1];
    float s = 0.f;
    for (int q=beg;q<end;q++) s += g_cl3[g_adj[q].x];
    float aggr = (float)(end-beg)*g_cl2[d] - s;
    float z = g_cl1[d] + lb1[0] + aggr;
    g_fit[d] = 1.f/(1.f + __expf(-z));
}

// ---------------- top-K via 4x8-bit histogram radix select ----------------
__global__ void k_topk(){
    __shared__ int hist[256];
    __shared__ int wred[8];
    __shared__ unsigned s_pref;
    __shared__ int s_need;
    int tid=threadIdx.x, lane=tid&31, wid=tid>>5;
    if (tid==0){ s_pref=0u; s_need=K_; }
    unsigned keys[32];
    #pragma unroll
    for (int q=0;q<32;q++){
        unsigned u=__float_as_uint(g_fit[tid*32+q]);
        keys[q] = (u & 0x80000000u) ? ~u : (u | 0x80000000u);
    }
    __syncthreads();
    for (int round=0; round<4; round++){
        int shift = 24 - 8*round;
        hist[tid]=0;
        __syncthreads();
        unsigned pref = s_pref;
        #pragma unroll
        for (int q=0;q<32;q++){
            unsigned k = keys[q];
            bool match = (round==0) || ((k >> (shift+8)) == (pref >> (shift+8)));
            if (match) atomicAdd(&hist[(k>>shift)&0xFFu], 1);
        }
        __syncthreads();
        int mine = hist[255-tid];
        int v = mine;
        #pragma unroll
        for (int o=1;o<32;o<<=1){ int t2=__shfl_up_sync(0xffffffffu,v,o); if(lane>=o) v+=t2; }
        if (lane==31) wred[wid]=v;
        __syncthreads();
        int woff=0;
        #pragma unroll
        for (int w=0;w<8;w++) if (w<wid) woff+=wred[w];
        v += woff;
        int need0 = s_need;
        int vex = v - mine;
        if (v >= need0 && vex < need0){
            s_pref = s_pref | ((unsigned)(255-tid) << shift);
            s_need = need0 - vex;
        }
        __syncthreads();
    }
    unsigned thr = s_pref;
    int need = s_need;
    int tcnt=0;
    #pragma unroll
    for (int q=0;q<32;q++) tcnt += (keys[q]==thr);
    int v=tcnt;
    #pragma unroll
    for (int o=1;o<32;o<<=1){ int t2=__shfl_up_sync(0xffffffffu,v,o); if(lane>=o) v+=t2; }
    if (lane==31) wred[wid]=v;
    __syncthreads();
    int woff=0;
    #pragma unroll
    for (int w=0;w<8;w++) if (w<wid) woff+=wred[w];
    int rank = v - tcnt + woff;
    int scnt=0;
    int selq[32];
    #pragma unroll
    for (int q=0;q<32;q++){
        unsigned k=keys[q];
        bool eq = (k==thr);
        int s = (k>thr) || (eq && rank < need);
        if (eq) rank++;
        selq[q]=s;
        g_sel[tid*32+q]=s;
        scnt+=s;
    }
    __syncthreads();
    v=scnt;
    #pragma unroll
    for (int o=1;o<32;o<<=1){ int t2=__shfl_up_sync(0xffffffffu,v,o); if(lane>=o) v+=t2; }
    if (lane==31) wred[wid]=v;
    __syncthreads();
    woff=0;
    #pragma unroll
    for (int w=0;w<8;w++) if (w<wid) woff+=wred[w];
    int base = v - scnt + woff;
    #pragma unroll
    for (int q=0;q<32;q++){
        int i = tid*32+q;
        if (selq[q]){ g_col[i]=base; g_ncol[base]=i; base++; }
        else g_col[i]=-1;
    }
}

__global__ void k_xp(const float* __restrict__ cx){
    int i = blockIdx.x, t = threadIdx.x;
    if (!g_sel[i]) return;
    g_xp[(size_t)g_col[i]*128 + t] = cx[(size_t)i*128 + t] * g_fit[i];
}

// ---------------- S CSR (by source): count + fill from dst rows ----------------
__global__ void k_scount(){
    int d = blockIdx.x*blockDim.x + threadIdx.x;
    if (d >= N_ || !g_sel[d]) return;
    int beg=g_rowptr[d], end=g_rowptr[d+1];
    for (int p=beg;p<end;p++) atomicAdd(&g_scnt[g_adj[p].x], 1);
}
__global__ void k_sfill(){
    int d = blockIdx.x*blockDim.x + threadIdx.x;
    if (d >= N_ || !g_sel[d]) return;
    int colk = g_col[d];
    int beg=g_rowptr[d], end=g_rowptr[d+1];
    for (int p=beg;p<end;p++){
        int s = g_adj[p].x;
        int pos = g_srowptr[s] + atomicAdd(&g_fill[s],1);
        g_sp[pos] = make_int2(colk, __float_as_int(g_alpha[p]));
    }
}

// ---------------- W = A*S (sparse rows): count, fill ----------------
__global__ void k_wcount(){
    int s = blockIdx.x*blockDim.x + threadIdx.x;
    if (s >= N_) return;
    int ob=g_orowptr[s], oe=g_orowptr[s+1];
    int total=0;
    for (int f=ob;f<oe;f++){
        int j = g_oadj[f];
        total += g_srowptr[j+1]-g_srowptr[j];
    }
    g_wcnt[s]=total;
}
// warp per source: copy S_j lists into W row
__global__ void k_wfill(){
    int s = blockIdx.x*8 + (threadIdx.x>>5);
    int lane = threadIdx.x & 31;
    int wpos = g_wrowptr[s];
    int ob=g_orowptr[s], oe=g_orowptr[s+1];
    for (int f=ob;f<oe;f++){
        int j = g_oadj[f];
        int sb=g_srowptr[j], len=g_srowptr[j+1]-sb;
        for (int q=lane;q<len;q+=32) g_W[wpos+q]=g_sp[sb+q];
        wpos += len;
    }
}

// ---------------- Ac row gather with smem accumulator (flat W rows) ----------------
__global__ void k_AcRow(){
    __shared__ __align__(16) float acc[K_];
    int k = blockIdx.x, tid = threadIdx.x;
    int lane = tid & 31, w = tid >> 5, nw = blockDim.x >> 5;
    {
        float4 z = make_float4(0,0,0,0);
        float4* a4 = (float4*)acc;
        #pragma unroll
        for (int m=0;m<4;m++) a4[tid + m*256] = z;
    }
    __syncthreads();
    int d = g_ncol[k];
    int ib = g_rowptr[d], ie = g_rowptr[d+1];
    for (int p=ib+w; p<ie; p+=nw){
        int s = g_adj[p].x;
        float ae = g_alpha[p];
        int wb = g_wrowptr[s], we = g_wrowptr[s+1];
        int q = wb + lane;
        for (; q+32 < we; q += 64){
            int2 e0 = g_W[q];
            int2 e1 = g_W[q+32];
            atomicAdd(&acc[e0.x], ae*__int_as_float(e0.y));
            atomicAdd(&acc[e1.x], ae*__int_as_float(e1.y));
        }
        if (q < we){
            int2 e0 = g_W[q];
            atomicAdd(&acc[e0.x], ae*__int_as_float(e0.y));
        }
    }
    __syncthreads();
    float4* orow = (float4*)&g_Ac[(size_t)k*K_];
    const float4* a4 = (const float4*)acc;
    #pragma unroll
    for (int m=0;m<4;m++) orow[tid + m*256] = a4[tid + m*256];
}

// ---------------- fused: build 6 P-rows -> smem, then adj = P S^T ----------------
// 512 threads, 96KB smem -> 2 blocks/SM so one block's LDS j-loop overlaps the
// other's L2 P-build. Psh: lo4[k]=float4 rows0-3 (64KB), hi2[k]=float2 rows4-5 (32KB).
__global__ void __launch_bounds__(512, 2) k_adjF(float* __restrict__ adj){
    extern __shared__ __align__(16) float Psh[];
    int i0 = blockIdx.x*AROWS, tid = threadIdx.x;
    float* lo = Psh;            // 4*K_ floats
    float* hi = Psh + 4*K_;     // 2*K_ floats
    #pragma unroll 1
    for (int r=0;r<AROWS;r++){
        float acc[8];
        #pragma unroll
        for (int m=0;m<8;m++) acc[m]=0.f;
        int i = i0+r;
        if (i < N_){
            int qb=g_srowptr[i], qe=g_srowptr[i+1];
            for (int q=qb;q<qe;q++){
                int2 kp = g_sp[q];
                float a = __int_as_float(kp.y);
                const float* row = g_Ac + (size_t)kp.x*K_ + tid;
                #pragma unroll
                for (int m=0;m<8;m++) acc[m] += a*row[m*512];
            }
        }
        if (r < 4){
            #pragma unroll
            for (int m=0;m<8;m++) lo[4*(tid + 512*m) + r] = acc[m];
        } else {
            #pragma unroll
            for (int m=0;m<8;m++) hi[2*(tid + 512*m) + (r-4)] = acc[m];
        }
    }
    __syncthreads();
    const float4* lo4 = (const float4*)lo;
    const float2* hi2 = (const float2*)hi;
    int nval = N_ - i0; if (nval > AROWS) nval = AROWS;
    for (int j=tid; j<N_; j+=512){
        float b0=0,b1=0,b2=0,b3=0,b4=0,b5=0;
        int qb = g_srowptr[j], qe = g_srowptr[j+1];
        for (int q=qb;q<qe;q++){
            int2 kp = g_sp[q];
            float a = __int_as_float(kp.y);
            float4 p0 = lo4[kp.x];
            float2 p1 = hi2[kp.x];
            b0 += a*p0.x; b1 += a*p0.y; b2 += a*p0.z; b3 += a*p0.w;
            b4 += a*p1.x; b5 += a*p1.y;
        }
        float bs[6] = {b0,b1,b2,b3,b4,b5};
        #pragma unroll
        for (int r=0;r<AROWS;r++)
            if (r < nval) adj[(size_t)(i0+r)*N_ + j] = bs[r];
    }
}

// x_out[i,:] = sum over S row i: alpha*xp[k,:]  (warp per row, float4)
__global__ void k_xout(float* __restrict__ out){
    int i = blockIdx.x*8 + (threadIdx.x>>5);
    int lane = threadIdx.x & 31;
    const float4* xp4 = (const float4*)g_xp;
    float4 acc = make_float4(0,0,0,0);
    int beg=g_srowptr[i], end=g_srowptr[i+1];
    for (int q=beg;q<end;q++){
        int2 kp = g_sp[q];
        float a = __int_as_float(kp.y);
        float4 v = xp4[(size_t)kp.x*32 + lane];
        acc.x += a*v.x; acc.y += a*v.y; acc.z += a*v.z; acc.w += a*v.w;
    }
    ((float4*)out)[(size_t)i*32 + lane] = acc;
}

// ---------------- host ----------------
static cudaStream_t get_s2(){
    static cudaStream_t s = 0;
    if (!s) cudaStreamCreate(&s);
    return s;
}
static cudaEvent_t get_ev(int which){
    static cudaEvent_t ev[4] = {0,0,0,0};
    if (!ev[which]) cudaEventCreateWithFlags(&ev[which], cudaEventDisableTiming);
    return ev[which];
}

extern "C" void kernel_launch(void* const* d_in, const int* in_sizes, int n_in,
                              void* d_out, int out_size){
    const float* nodes = (const float*)d_in[0];
    const int*   edges = (const int*)d_in[1];
    const int* e0 = edges;
    const int* e1 = edges + E_;
    const float* w1 = (const float*)d_in[3];  const float* b1 = (const float*)d_in[4];
    const float* w2 = (const float*)d_in[5];  const float* b2 = (const float*)d_in[6];
    const float* w3 = (const float*)d_in[7];  const float* b3 = (const float*)d_in[8];
    const float* w4 = (const float*)d_in[9];  const float* b4 = (const float*)d_in[10];
    const float* w5 = (const float*)d_in[11]; const float* b5 = (const float*)d_in[12];
    const float* wq = (const float*)d_in[13]; const float* bq = (const float*)d_in[14];
    const float* att = (const float*)d_in[15];
    const float* lw1 = (const float*)d_in[16]; const float* lb1 = (const float*)d_in[17];
    const float* lw2 = (const float*)d_in[18]; const float* lw3 = (const float*)d_in[19];

    float* out = (float*)d_out;
    float* x2out = out;
    float* adj  = out + (size_t)N_*H_;

    float *A,*B,*C,*T; int *scnt,*srowptr,*wcnt,*wrowptr,*fill;
    cudaGetSymbolAddress((void**)&A, g_bufA);
    cudaGetSymbolAddress((void**)&B, g_bufB);
    cudaGetSymbolAddress((void**)&C, g_bufC);
    cudaGetSymbolAddress((void**)&T, g_bufT);
    cudaGetSymbolAddress((void**)&scnt, g_scnt);
    cudaGetSymbolAddress((void**)&srowptr, g_srowptr);
    cudaGetSymbolAddress((void**)&wcnt, g_wcnt);
    cudaGetSymbolAddress((void**)&wrowptr, g_wrowptr);
    cudaGetSymbolAddress((void**)&fill, g_fill);

    const int TB = 256;
    const int MB = (M_ + TB - 1)/TB;
    const int NB = (N_ + TB - 1)/TB;

    cudaStream_t s2 = get_s2();
    cudaEvent_t evF0 = get_ev(0), evJ0 = get_ev(1), evF1 = get_ev(2), evJ1 = get_ev(3);

    // fork 0: first gemm (depends only on inputs) overlaps graph prep
    cudaEventRecord(evF0, 0);
    cudaStreamWaitEvent(s2, evF0, 0);
    k_gemm<<<128,256,0,s2>>>(nodes, w1, T);
    cudaEventRecord(evJ0, s2);

    // graph prep: dst-CSR + src-CSR with folded norms (main stream)
    k_init0<<<NB, TB>>>();
    k_count<<<MB, TB>>>(e0, e1);
    k_scan2<<<2,1024>>>();
    k_fill<<<MB, TB>>>(e0, e1);

    // encoder (needs gemm1 result)
    cudaStreamWaitEvent(0, evJ0, 0);
    k_aggr<<<N_/8,256>>>(T, b1, A, 1);
    k_gemm<<<128,256>>>(A, w2, T);
    k_aggr<<<N_/8,256>>>(T, b2, B, 1);       // B = h

    // pooling
    k_segmax<<<N_/8,256>>>(B, A);
    k_gemm<<<128,256>>>(A, wq, T);
    k_dots<<<N_/8,256>>>(T, B, att, bq);
    k_softcx<<<N_,128>>>(B, C);              // C = cx, writes positional g_alpha
    k_le<<<N_/8,256>>>(C, lw1, lw2, lw3);
    k_fit<<<NB, TB>>>(lb1);
    k_topk<<<1,256>>>();
    k_xp<<<N_,128>>>(C);

    // S CSR (by source)
    k_scount<<<NB, TB>>>();
    k_scan8192<<<1,1024>>>(scnt, srowptr);
    k_zeroN<<<NB, TB>>>(fill);
    k_sfill<<<NB, TB>>>();

    // fork 1: decoder branch (s2) overlaps W-build + AcRow + adjF (main)
    cudaEventRecord(evF1, 0);
    cudaStreamWaitEvent(s2, evF1, 0);
    k_xout<<<N_/8,256,0,s2>>>(A);            // A = x_out
    k_gemm<<<128,256,0,s2>>>(A, w3, T);
    k_aggr<<<N_/8,256,0,s2>>>(T, b3, B, 1);
    k_gemm<<<128,256,0,s2>>>(B, w4, T);
    k_aggr<<<N_/8,256,0,s2>>>(T, b4, A, 1);
    k_gemm<<<128,256,0,s2>>>(A, w5, T);
    k_aggr<<<N_/8,256,0,s2>>>(T, b5, x2out, 0);
    cudaEventRecord(evJ1, s2);

    // main: W = A*S sparse rows, Ac, adj
    k_wcount<<<NB, TB>>>();
    k_scan8192<<<1,1024>>>(wcnt, wrowptr);
    k_wfill<<<N_/8, 256>>>();
    k_AcRow<<<K_, 256>>>();
    cudaFuncSetAttribute(k_adjF, cudaFuncAttributeMaxDynamicSharedMemorySize, PSH_BYTES);
    k_adjF<<<ABLOCKS, 512, PSH_BYTES>>>(adj);

    // join decoder branch
    cudaStreamWaitEvent(0, evJ1, 0);
}

// round 9
// speedup vs baseline: 1.0386x; 1.0386x over previous
#include <cuda_runtime.h>
#include <math.h>
#include <stdint.h>

#define N_ 8192
#define E_ 131072
#define M_ (E_ + N_)          // 139264 edges incl self loops
#define H_ 128
#define K_ 4096
#define WCAP_ 3000000

#define SCACHE 1024
#define PSH_TOTAL (8*K_*4 + SCACHE*8)   // 128KB P + 8KB S-entry cache

// ---------------- device scratch ----------------
static __device__ float g_bufA[(size_t)N_*H_];
static __device__ float g_bufB[(size_t)N_*H_];
static __device__ float g_bufC[(size_t)N_*H_];
static __device__ float g_bufT[(size_t)N_*H_];
static __device__ int   g_cnt[N_];
static __device__ int   g_ocnt[N_];
static __device__ int   g_fill[N_];
static __device__ int   g_ofill[N_];
static __device__ int   g_rowptr[N_+1];     // CSR by dst
static __device__ int   g_orowptr[N_+1];    // CSR by src
static __device__ int2  g_adj[M_];          // per dst-CSR pos: (src, norm bits)
static __device__ int   g_oadj[M_];         // per src-CSR pos: dst
static __device__ float g_alpha[M_];        // per dst-CSR pos
static __device__ float g_aq[N_];
static __device__ float g_ah[N_];
static __device__ float g_cl1[N_], g_cl2[N_], g_cl3[N_];
static __device__ float g_fit[N_];
static __device__ int   g_sel[N_];
static __device__ int   g_col[N_];
static __device__ int   g_ncol[K_];
static __device__ float g_xp[(size_t)K_*H_];
static __device__ int   g_scnt[N_];
static __device__ int   g_srowptr[N_+1];
static __device__ int2  g_sp[M_];            // packed (col k, alpha bits), CSR by src
static __device__ int   g_wcnt[N_];
static __device__ int   g_wrowptr[N_+1];
static __device__ int2  g_W[WCAP_];          // W = A*S rows
static __device__ float g_Ac[(size_t)K_*K_];

// ---------------- helpers ----------------
__device__ __forceinline__ int esrc_f(const int* __restrict__ e0, int e){ return (e < E_) ? e0[e] : (e - E_); }
__device__ __forceinline__ int edst_f(const int* __restrict__ e1, int e){ return (e < E_) ? e1[e] : (e - E_); }

// ---------------- small utility kernels ----------------
__global__ void k_init0(){
    int i = blockIdx.x*blockDim.x + threadIdx.x;
    if (i < N_){ g_cnt[i]=0; g_ocnt[i]=0; g_fill[i]=0; g_ofill[i]=0; g_scnt[i]=0; }
}
__global__ void k_zeroN(int* __restrict__ p){
    int i = blockIdx.x*blockDim.x + threadIdx.x;
    if (i < N_) p[i]=0;
}
__global__ void k_count(const int* __restrict__ e0, const int* __restrict__ e1){
    int e = blockIdx.x*blockDim.x + threadIdx.x;
    if (e < M_){
        atomicAdd(&g_cnt[edst_f(e1,e)], 1);
        atomicAdd(&g_ocnt[esrc_f(e0,e)], 1);
    }
}
// exclusive scan of exactly 8192 ints with 1024 threads (shfl-based)
__device__ __forceinline__ void scan8192_body(const int* __restrict__ in, int* __restrict__ out){
    __shared__ int wsum[32];
    int tid=threadIdx.x, lane=tid&31, wid=tid>>5;
    int4 a=((const int4*)in)[tid*2], b=((const int4*)in)[tid*2+1];
    int l[8]={a.x,a.y,a.z,a.w,b.x,b.y,b.z,b.w};
    int s=0;
    #pragma unroll
    for(int q=0;q<8;q++) s+=l[q];
    int inc=s;
    #pragma unroll
    for(int o=1;o<32;o<<=1){ int t=__shfl_up_sync(0xffffffffu,inc,o); if(lane>=o) inc+=t; }
    if(lane==31) wsum[wid]=inc;
    __syncthreads();
    if (wid==0){
        int v = wsum[lane];
        #pragma unroll
        for(int o=1;o<32;o<<=1){ int t=__shfl_up_sync(0xffffffffu,v,o); if(lane>=o) v+=t; }
        wsum[lane]=v;
    }
    __syncthreads();
    int r = inc - s + (wid? wsum[wid-1]:0);
    int4 o1,o2;
    o1.x=r; r+=l[0]; o1.y=r; r+=l[1]; o1.z=r; r+=l[2]; o1.w=r; r+=l[3];
    o2.x=r; r+=l[4]; o2.y=r; r+=l[5]; o2.z=r; r+=l[6]; o2.w=r; r+=l[7];
    ((int4*)out)[tid*2]=o1; ((int4*)out)[tid*2+1]=o2;
    if (tid==1023) out[8192]=r;
}
__global__ void k_scan8192(const int* __restrict__ in, int* __restrict__ out){
    scan8192_body(in, out);
}
__global__ void k_scan2(){
    if (blockIdx.x == 0) scan8192_body(g_cnt, g_rowptr);
    else                 scan8192_body(g_ocnt, g_orowptr);
}
// build positional adjacency with folded norm (dis computed inline)
__global__ void k_fill(const int* __restrict__ e0, const int* __restrict__ e1){
    int e = blockIdx.x*blockDim.x + threadIdx.x;
    if (e < M_){
        int s = esrc_f(e0,e);
        int d = edst_f(e1,e);
        float nm = rsqrtf((float)g_cnt[s]) * rsqrtf((float)g_cnt[d]);
        int pos = g_rowptr[d] + atomicAdd(&g_fill[d],1);
        g_adj[pos] = make_int2(s, __float_as_int(nm));
        int opos = g_orowptr[s] + atomicAdd(&g_ofill[s],1);
        g_oadj[opos] = d;
    }
}

// ---------------- 8192x128 @ 128x128 GEMM ----------------
__global__ void k_gemm(const float* __restrict__ x, const float* __restrict__ w, float* __restrict__ y){
    __shared__ __align__(16) float xs[128*64];   // [kk][r]
    int r0 = blockIdx.x*64;
    int tid = threadIdx.x;
    for (int idx=tid; idx<64*128; idx+=256){
        int r = idx >> 7;
        int kk = idx & 127;
        xs[kk*64 + r] = x[(size_t)(r0+r)*128 + kk];
    }
    __syncthreads();
    int cg = tid & 31;
    int rg = tid >> 5;
    float acc[8][4];
    #pragma unroll
    for(int r=0;r<8;r++){ acc[r][0]=0.f;acc[r][1]=0.f;acc[r][2]=0.f;acc[r][3]=0.f; }
    #pragma unroll 4
    for(int kk=0;kk<128;kk++){
        float4 wv = *(const float4*)(w + kk*128 + cg*4);
        float4 x0 = *(const float4*)(xs + kk*64 + rg*8);
        float4 x1 = *(const float4*)(xs + kk*64 + rg*8 + 4);
        float xv[8] = {x0.x,x0.y,x0.z,x0.w,x1.x,x1.y,x1.z,x1.w};
        #pragma unroll
        for(int r=0;r<8;r++){
            acc[r][0] += xv[r]*wv.x; acc[r][1] += xv[r]*wv.y;
            acc[r][2] += xv[r]*wv.z; acc[r][3] += xv[r]*wv.w;
        }
    }
    #pragma unroll
    for(int r=0;r<8;r++){
        float4 o = make_float4(acc[r][0],acc[r][1],acc[r][2],acc[r][3]);
        *(float4*)(y + (size_t)(r0+rg*8+r)*128 + cg*4) = o;
    }
}

// ---------------- GCN aggregation: warp per dst, float4 lanes ----------------
__global__ void k_aggr(const float* __restrict__ y, const float* __restrict__ b,
                       float* __restrict__ out, int dotanh){
    int d = blockIdx.x*8 + (threadIdx.x>>5);
    int lane = threadIdx.x & 31;
    const float4* y4 = (const float4*)y;
    float4 acc = ((const float4*)b)[lane];
    int beg = g_rowptr[d], end = g_rowptr[d+1];
    int p = beg;
    for (; p+1 < end; p += 2){
        int2 a0 = g_adj[p], a1 = g_adj[p+1];
        float n0 = __int_as_float(a0.y), n1 = __int_as_float(a1.y);
        float4 v0 = y4[(size_t)a0.x*32 + lane];
        float4 v1 = y4[(size_t)a1.x*32 + lane];
        acc.x += n0*v0.x + n1*v1.x;
        acc.y += n0*v0.y + n1*v1.y;
        acc.z += n0*v0.z + n1*v1.z;
        acc.w += n0*v0.w + n1*v1.w;
    }
    if (p < end){
        int2 a0 = g_adj[p];
        float n0 = __int_as_float(a0.y);
        float4 v0 = y4[(size_t)a0.x*32 + lane];
        acc.x += n0*v0.x; acc.y += n0*v0.y; acc.z += n0*v0.z; acc.w += n0*v0.w;
    }
    if (dotanh){
        acc.x = tanhf(acc.x); acc.y = tanhf(acc.y);
        acc.z = tanhf(acc.z); acc.w = tanhf(acc.w);
    }
    ((float4*)out)[(size_t)d*32 + lane] = acc;
}

__global__ void k_segmax(const float* __restrict__ h, float* __restrict__ out){
    int d = blockIdx.x*8 + (threadIdx.x>>5);
    int lane = threadIdx.x & 31;
    const float4* h4 = (const float4*)h;
    float4 acc = make_float4(-INFINITY,-INFINITY,-INFINITY,-INFINITY);
    int beg = g_rowptr[d], end = g_rowptr[d+1];
    for (int p=beg; p<end; p++){
        float4 v = h4[(size_t)g_adj[p].x*32 + lane];
        acc.x = fmaxf(acc.x,v.x); acc.y = fmaxf(acc.y,v.y);
        acc.z = fmaxf(acc.z,v.z); acc.w = fmaxf(acc.w,v.w);
    }
    ((float4*)out)[(size_t)d*32 + lane] = acc;
}

__global__ void k_dots(const float* __restrict__ xq, const float* __restrict__ h,
                       const float* __restrict__ att, const float* __restrict__ bq){
    int node = blockIdx.x*8 + (threadIdx.x>>5);
    int lane = threadIdx.x & 31;
    const float4* xq4 = (const float4*)xq;
    const float4* h4  = (const float4*)h;
    const float4* at4 = (const float4*)att;
    const float4* bq4 = (const float4*)bq;
    float4 a1 = at4[lane], a2 = at4[32+lane];
    float4 xv = xq4[(size_t)node*32+lane], bv = bq4[lane], hv = h4[(size_t)node*32+lane];
    float s1 = a1.x*(xv.x+bv.x) + a1.y*(xv.y+bv.y) + a1.z*(xv.z+bv.z) + a1.w*(xv.w+bv.w);
    float s2 = a2.x*hv.x + a2.y*hv.y + a2.z*hv.z + a2.w*hv.w;
    #pragma unroll
    for (int o=16;o;o>>=1){ s1 += __shfl_down_sync(0xffffffffu,s1,o); s2 += __shfl_down_sync(0xffffffffu,s2,o); }
    if (!lane){ g_aq[node]=s1; g_ah[node]=s2; }
}

// per-dst softmax over in-edges (positional alpha) + cluster rep cx
__global__ void k_softcx(const float* __restrict__ h, float* __restrict__ cx){
    __shared__ float red[128];
    __shared__ float cache[1024];
    __shared__ int   scache[1024];
    int d = blockIdx.x, t = threadIdx.x;
    int beg = g_rowptr[d], end = g_rowptr[d+1];
    float aqd = g_aq[d];
    float mx = -INFINITY;
    for (int s=beg+t; s<end; s+=128){
        int src = g_adj[s].x;
        float sc = aqd + g_ah[src];
        sc = sc > 0.f ? sc : 0.2f*sc;
        if (s-beg < 1024){ cache[s-beg] = sc; scache[s-beg] = src; }
        mx = fmaxf(mx, sc);
    }
    red[t]=mx; __syncthreads();
    for (int o=64;o;o>>=1){ if(t<o) red[t]=fmaxf(red[t],red[t+o]); __syncthreads(); }
    mx = red[0]; __syncthreads();
    float sm = 0.f;
    for (int s=beg+t; s<end; s+=128){
        float sc;
        if (s-beg < 1024) sc = cache[s-beg];
        else { float v = aqd + g_ah[g_adj[s].x]; sc = v>0.f? v : 0.2f*v; }
        float ee = __expf(sc - mx);
        if (s-beg < 1024) cache[s-beg] = ee;
        sm += ee;
    }
    red[t]=sm; __syncthreads();
    for (int o=64;o;o>>=1){ if(t<o) red[t]+=red[t+o]; __syncthreads(); }
    float inv = 1.f/red[0];
    for (int s=beg+t; s<end; s+=128){
        float ee;
        if (s-beg < 1024) ee = cache[s-beg];
        else { float v = aqd + g_ah[g_adj[s].x]; v = v>0.f? v:0.2f*v; ee = __expf(v-mx); }
        float a = ee*inv;
        g_alpha[s] = a;
        if (s-beg < 1024) cache[s-beg] = a;
    }
    __syncthreads();
    float acc = 0.f;
    for (int s=beg; s<end; s++){
        float a; int src;
        if (s-beg < 1024){ a = cache[s-beg]; src = scache[s-beg]; }
        else { a = g_alpha[s]; src = g_adj[s].x; }
        acc += a * h[(size_t)src*128 + t];
    }
    cx[(size_t)d*128 + t] = acc;
}

__global__ void k_le(const float* __restrict__ cx, const float* __restrict__ lw1,
                     const float* __restrict__ lw2, const float* __restrict__ lw3){
    int node = blockIdx.x*8 + (threadIdx.x>>5);
    int lane = threadIdx.x & 31;
    const float4* c4 = (const float4*)cx;
    const float4* w14 = (const float4*)lw1;
    const float4* w24 = (const float4*)lw2;
    const float4* w34 = (const float4*)lw3;
    float4 v = c4[(size_t)node*32+lane];
    float4 w1v = w14[lane], w2v = w24[lane], w3v = w34[lane];
    float s1 = v.x*w1v.x + v.y*w1v.y + v.z*w1v.z + v.w*w1v.w;
    float s2 = v.x*w2v.x + v.y*w2v.y + v.z*w2v.z + v.w*w2v.w;
    float s3 = v.x*w3v.x + v.y*w3v.y + v.z*w3v.z + v.w*w3v.w;
    #pragma unroll
    for (int o=16;o;o>>=1){
        s1 += __shfl_down_sync(0xffffffffu,s1,o);
        s2 += __shfl_down_sync(0xffffffffu,s2,o);
        s3 += __shfl_down_sync(0xffffffffu,s3,o);
    }
    if (!lane){ g_cl1[node]=s1; g_cl2[node]=s2; g_cl3[node]=s3; }
}
__global__ void k_fit(const float* __restrict__ lb1){
    int d = blockIdx.x*blockDim.x + threadIdx.x;
    if (d >= N_) return;
    int beg=g_rowptr[d], end=g_rowptr[d+1];
    float s = 0.f;
    for (int q=beg;q<end;q++) s += g_cl3[g_adj[q].x];
    float aggr = (float)(end-beg)*g_cl2[d] - s;
    float z = g_cl1[d] + lb1[0] + aggr;
    g_fit[d] = 1.f/(1.f + __expf(-z));
}

// ---------------- top-K via 4x8-bit histogram radix select ----------------
__global__ void k_topk(){
    __shared__ int hist[256];
    __shared__ int wred[8];
    __shared__ unsigned s_pref;
    __shared__ int s_need;
    int tid=threadIdx.x, lane=tid&31, wid=tid>>5;
    if (tid==0){ s_pref=0u; s_need=K_; }
    unsigned keys[32];
    #pragma unroll
    for (int q=0;q<32;q++){
        unsigned u=__float_as_uint(g_fit[tid*32+q]);
        keys[q] = (u & 0x80000000u) ? ~u : (u | 0x80000000u);
    }
    __syncthreads();
    for (int round=0; round<4; round++){
        int shift = 24 - 8*round;
        hist[tid]=0;
        __syncthreads();
        unsigned pref = s_pref;
        #pragma unroll
        for (int q=0;q<32;q++){
            unsigned k = keys[q];
            bool match = (round==0) || ((k >> (shift+8)) == (pref >> (shift+8)));
            if (match) atomicAdd(&hist[(k>>shift)&0xFFu], 1);
        }
        __syncthreads();
        int mine = hist[255-tid];
        int v = mine;
        #pragma unroll
        for (int o=1;o<32;o<<=1){ int t2=__shfl_up_sync(0xffffffffu,v,o); if(lane>=o) v+=t2; }
        if (lane==31) wred[wid]=v;
        __syncthreads();
        int woff=0;
        #pragma unroll
        for (int w=0;w<8;w++) if (w<wid) woff+=wred[w];
        v += woff;
        int need0 = s_need;
        int vex = v - mine;
        if (v >= need0 && vex < need0){
            s_pref = s_pref | ((unsigned)(255-tid) << shift);
            s_need = need0 - vex;
        }
        __syncthreads();
    }
    unsigned thr = s_pref;
    int need = s_need;
    int tcnt=0;
    #pragma unroll
    for (int q=0;q<32;q++) tcnt += (keys[q]==thr);
    int v=tcnt;
    #pragma unroll
    for (int o=1;o<32;o<<=1){ int t2=__shfl_up_sync(0xffffffffu,v,o); if(lane>=o) v+=t2; }
    if (lane==31) wred[wid]=v;
    __syncthreads();
    int woff=0;
    #pragma unroll
    for (int w=0;w<8;w++) if (w<wid) woff+=wred[w];
    int rank = v - tcnt + woff;
    int scnt=0;
    int selq[32];
    #pragma unroll
    for (int q=0;q<32;q++){
        unsigned k=keys[q];
        bool eq = (k==thr);
        int s = (k>thr) || (eq && rank < need);
        if (eq) rank++;
        selq[q]=s;
        g_sel[tid*32+q]=s;
        scnt+=s;
    }
    __syncthreads();
    v=scnt;
    #pragma unroll
    for (int o=1;o<32;o<<=1){ int t2=__shfl_up_sync(0xffffffffu,v,o); if(lane>=o) v+=t2; }
    if (lane==31) wred[wid]=v;
    __syncthreads();
    woff=0;
    #pragma unroll
    for (int w=0;w<8;w++) if (w<wid) woff+=wred[w];
    int base = v - scnt + woff;
    #pragma unroll
    for (int q=0;q<32;q++){
        int i = tid*32+q;
        if (selq[q]){ g_col[i]=base; g_ncol[base]=i; base++; }
        else g_col[i]=-1;
    }
}

__global__ void k_xp(const float* __restrict__ cx){
    int i = blockIdx.x, t = threadIdx.x;
    if (!g_sel[i]) return;
    g_xp[(size_t)g_col[i]*128 + t] = cx[(size_t)i*128 + t] * g_fit[i];
}

// ---------------- S CSR (by source): count + fill from dst rows ----------------
__global__ void k_scount(){
    int d = blockIdx.x*blockDim.x + threadIdx.x;
    if (d >= N_ || !g_sel[d]) return;
    int beg=g_rowptr[d], end=g_rowptr[d+1];
    for (int p=beg;p<end;p++) atomicAdd(&g_scnt[g_adj[p].x], 1);
}
__global__ void k_sfill(){
    int d = blockIdx.x*blockDim.x + threadIdx.x;
    if (d >= N_ || !g_sel[d]) return;
    int colk = g_col[d];
    int beg=g_rowptr[d], end=g_rowptr[d+1];
    for (int p=beg;p<end;p++){
        int s = g_adj[p].x;
        int pos = g_srowptr[s] + atomicAdd(&g_fill[s],1);
        g_sp[pos] = make_int2(colk, __float_as_int(g_alpha[p]));
    }
}

// ---------------- W = A*S (sparse rows): count, fill ----------------
__global__ void k_wcount(){
    int s = blockIdx.x*blockDim.x + threadIdx.x;
    if (s >= N_) return;
    int ob=g_orowptr[s], oe=g_orowptr[s+1];
    int total=0;
    for (int f=ob;f<oe;f++){
        int j = g_oadj[f];
        total += g_srowptr[j+1]-g_srowptr[j];
    }
    g_wcnt[s]=total;
}
// warp per source: copy S_j lists into W row
__global__ void k_wfill(){
    int s = blockIdx.x*8 + (threadIdx.x>>5);
    int lane = threadIdx.x & 31;
    int wpos = g_wrowptr[s];
    int ob=g_orowptr[s], oe=g_orowptr[s+1];
    for (int f=ob;f<oe;f++){
        int j = g_oadj[f];
        int sb=g_srowptr[j], len=g_srowptr[j+1]-sb;
        for (int q=lane;q<len;q+=32) g_W[wpos+q]=g_sp[sb+q];
        wpos += len;
    }
}

// ---------------- Ac row gather with smem accumulator (flat W rows) ----------------
__global__ void k_AcRow(){
    __shared__ __align__(16) float acc[K_];
    int k = blockIdx.x, tid = threadIdx.x;
    int lane = tid & 31, w = tid >> 5, nw = blockDim.x >> 5;
    {
        float4 z = make_float4(0,0,0,0);
        float4* a4 = (float4*)acc;
        #pragma unroll
        for (int m=0;m<4;m++) a4[tid + m*256] = z;
    }
    __syncthreads();
    int d = g_ncol[k];
    int ib = g_rowptr[d], ie = g_rowptr[d+1];
    for (int p=ib+w; p<ie; p+=nw){
        int s = g_adj[p].x;
        float ae = g_alpha[p];
        int wb = g_wrowptr[s], we = g_wrowptr[s+1];
        int q = wb + lane;
        for (; q+32 < we; q += 64){
            int2 e0 = g_W[q];
            int2 e1 = g_W[q+32];
            atomicAdd(&acc[e0.x], ae*__int_as_float(e0.y));
            atomicAdd(&acc[e1.x], ae*__int_as_float(e1.y));
        }
        if (q < we){
            int2 e0 = g_W[q];
            atomicAdd(&acc[e0.x], ae*__int_as_float(e0.y));
        }
    }
    __syncthreads();
    float4* orow = (float4*)&g_Ac[(size_t)k*K_];
    const float4* a4 = (const float4*)acc;
    #pragma unroll
    for (int m=0;m<4;m++) orow[tid + m*256] = a4[tid + m*256];
}

// ---------------- fused: build 8 P-rows -> smem (S entries cached), adj = P S^T ----------------
// 1024 threads, 136KB smem. Psh: [4k+r] rows0-3, [4K+4k+(r-4)] rows4-7.
// The block's 8 S-rows are contiguous in CSR: cache [srowptr[i0], srowptr[i0+8]) in smem.
__global__ void __launch_bounds__(1024, 1) k_adjF(float* __restrict__ adj){
    extern __shared__ __align__(16) float Psh[];
    int2* sc = (int2*)(Psh + 8*K_);
    int i0 = blockIdx.x*8, tid = threadIdx.x;
    const float4* Ac4 = (const float4*)g_Ac;

    int qb0 = g_srowptr[i0];
    int qend = g_srowptr[i0+8];
    int total = qend - qb0;
    int ncache = total < SCACHE ? total : SCACHE;
    for (int q=tid; q<ncache; q+=1024) sc[q] = g_sp[qb0+q];
    __syncthreads();

    #pragma unroll 1
    for (int r=0;r<8;r++){
        float4 a0 = make_float4(0,0,0,0);
        int qb=g_srowptr[i0+r], qe=g_srowptr[i0+r+1];
        if (qe - qb0 <= ncache){
            int base = qb - qb0, len = qe - qb;
            #pragma unroll 4
            for (int q=0;q<len;q++){
                int2 kp = sc[base+q];
                float a = __int_as_float(kp.y);
                float4 v0 = Ac4[(size_t)kp.x*(K_/4) + tid];
                a0.x += a*v0.x; a0.y += a*v0.y; a0.z += a*v0.z; a0.w += a*v0.w;
            }
        } else {
            for (int q=qb;q<qe;q++){
                int2 kp = g_sp[q];
                float a = __int_as_float(kp.y);
                float4 v0 = Ac4[(size_t)kp.x*(K_/4) + tid];
                a0.x += a*v0.x; a0.y += a*v0.y; a0.z += a*v0.z; a0.w += a*v0.w;
            }
        }
        float* half = Psh + ((r>=4) ? 4*K_ : 0);
        int rr = r & 3;
        half[16*tid + 0 + rr] = a0.x; half[16*tid + 4 + rr] = a0.y;
        half[16*tid + 8 + rr] = a0.z; half[16*tid +12 + rr] = a0.w;
    }
    __syncthreads();
    for (int j=tid; j<N_; j+=1024){
        float b0=0,b1=0,b2=0,b3=0,b4=0,b5=0,b6=0,b7=0;
        int qb = g_srowptr[j], qe = g_srowptr[j+1];
        #pragma unroll 2
        for (int q=qb;q<qe;q++){
            int2 kp = g_sp[q];
            float a = __int_as_float(kp.y);
            float4 p0 = *(const float4*)&Psh[4*kp.x];
            float4 p1 = *(const float4*)&Psh[4*K_ + 4*kp.x];
            b0 += a*p0.x; b1 += a*p0.y; b2 += a*p0.z; b3 += a*p0.w;
            b4 += a*p1.x; b5 += a*p1.y; b6 += a*p1.z; b7 += a*p1.w;
        }
        adj[(size_t)(i0+0)*N_ + j]=b0; adj[(size_t)(i0+1)*N_ + j]=b1;
        adj[(size_t)(i0+2)*N_ + j]=b2; adj[(size_t)(i0+3)*N_ + j]=b3;
        adj[(size_t)(i0+4)*N_ + j]=b4; adj[(size_t)(i0+5)*N_ + j]=b5;
        adj[(size_t)(i0+6)*N_ + j]=b6; adj[(size_t)(i0+7)*N_ + j]=b7;
    }
}

// x_out[i,:] = sum over S row i: alpha*xp[k,:]  (warp per row, float4)
__global__ void k_xout(float* __restrict__ out){
    int i = blockIdx.x*8 + (threadIdx.x>>5);
    int lane = threadIdx.x & 31;
    const float4* xp4 = (const float4*)g_xp;
    float4 acc = make_float4(0,0,0,0);
    int beg=g_srowptr[i], end=g_srowptr[i+1];
    for (int q=beg;q<end;q++){
        int2 kp = g_sp[q];
        float a = __int_as_float(kp.y);
        float4 v = xp4[(size_t)kp.x*32 + lane];
        acc.x += a*v.x; acc.y += a*v.y; acc.z += a*v.z; acc.w += a*v.w;
    }
    ((float4*)out)[(size_t)i*32 + lane] = acc;
}

// ---------------- host ----------------
static cudaStream_t get_s2(){
    static cudaStream_t s = 0;
    if (!s) cudaStreamCreate(&s);
    return s;
}
static cudaEvent_t get_ev(int which){
    static cudaEvent_t ev[4] = {0,0,0,0};
    if (!ev[which]) cudaEventCreateWithFlags(&ev[which], cudaEventDisableTiming);
    return ev[which];
}

extern "C" void kernel_launch(void* const* d_in, const int* in_sizes, int n_in,
                              void* d_out, int out_size){
    const float* nodes = (const float*)d_in[0];
    const int*   edges = (const int*)d_in[1];
    const int* e0 = edges;
    const int* e1 = edges + E_;
    const float* w1 = (const float*)d_in[3];  const float* b1 = (const float*)d_in[4];
    const float* w2 = (const float*)d_in[5];  const float* b2 = (const float*)d_in[6];
    const float* w3 = (const float*)d_in[7];  const float* b3 = (const float*)d_in[8];
    const float* w4 = (const float*)d_in[9];  const float* b4 = (const float*)d_in[10];
    const float* w5 = (const float*)d_in[11]; const float* b5 = (const float*)d_in[12];
    const float* wq = (const float*)d_in[13]; const float* bq = (const float*)d_in[14];
    const float* att = (const float*)d_in[15];
    const float* lw1 = (const float*)d_in[16]; const float* lb1 = (const float*)d_in[17];
    const float* lw2 = (const float*)d_in[18]; const float* lw3 = (const float*)d_in[19];

    float* out = (float*)d_out;
    float* x2out = out;
    float* adj  = out + (size_t)N_*H_;

    float *A,*B,*C,*T; int *scnt,*srowptr,*wcnt,*wrowptr,*fill;
    cudaGetSymbolAddress((void**)&A, g_bufA);
    cudaGetSymbolAddress((void**)&B, g_bufB);
    cudaGetSymbolAddress((void**)&C, g_bufC);
    cudaGetSymbolAddress((void**)&T, g_bufT);
    cudaGetSymbolAddress((void**)&scnt, g_scnt);
    cudaGetSymbolAddress((void**)&srowptr, g_srowptr);
    cudaGetSymbolAddress((void**)&wcnt, g_wcnt);
    cudaGetSymbolAddress((void**)&wrowptr, g_wrowptr);
    cudaGetSymbolAddress((void**)&fill, g_fill);

    const int TB = 256;
    const int MB = (M_ + TB - 1)/TB;
    const int NB = (N_ + TB - 1)/TB;

    cudaStream_t s2 = get_s2();
    cudaEvent_t evF0 = get_ev(0), evJ0 = get_ev(1), evF1 = get_ev(2), evJ1 = get_ev(3);

    // fork 0: first gemm (depends only on inputs) overlaps graph prep
    cudaEventRecord(evF0, 0);
    cudaStreamWaitEvent(s2, evF0, 0);
    k_gemm<<<128,256,0,s2>>>(nodes, w1, T);
    cudaEventRecord(evJ0, s2);

    // graph prep: dst-CSR + src-CSR with folded norms (main stream)
    k_init0<<<NB, TB>>>();
    k_count<<<MB, TB>>>(e0, e1);
    k_scan2<<<2,1024>>>();
    k_fill<<<MB, TB>>>(e0, e1);

    // encoder (needs gemm1 result)
    cudaStreamWaitEvent(0, evJ0, 0);
    k_aggr<<<N_/8,256>>>(T, b1, A, 1);
    k_gemm<<<128,256>>>(A, w2, T);
    k_aggr<<<N_/8,256>>>(T, b2, B, 1);       // B = h

    // pooling
    k_segmax<<<N_/8,256>>>(B, A);
    k_gemm<<<128,256>>>(A, wq, T);
    k_dots<<<N_/8,256>>>(T, B, att, bq);
    k_softcx<<<N_,128>>>(B, C);              // C = cx, writes positional g_alpha
    k_le<<<N_/8,256>>>(C, lw1, lw2, lw3);
    k_fit<<<NB, TB>>>(lb1);
    k_topk<<<1,256>>>();
    k_xp<<<N_,128>>>(C);

    // S CSR (by source)
    k_scount<<<NB, TB>>>();
    k_scan8192<<<1,1024>>>(scnt, srowptr);
    k_zeroN<<<NB, TB>>>(fill);
    k_sfill<<<NB, TB>>>();

    // fork 1: decoder branch (s2) overlaps W-build + AcRow + adjF (main)
    cudaEventRecord(evF1, 0);
    cudaStreamWaitEvent(s2, evF1, 0);
    k_xout<<<N_/8,256,0,s2>>>(A);            // A = x_out
    k_gemm<<<128,256,0,s2>>>(A, w3, T);
    k_aggr<<<N_/8,256,0,s2>>>(T, b3, B, 1);
    k_gemm<<<128,256,0,s2>>>(B, w4, T);
    k_aggr<<<N_/8,256,0,s2>>>(T, b4, A, 1);
    k_gemm<<<128,256,0,s2>>>(A, w5, T);
    k_aggr<<<N_/8,256,0,s2>>>(T, b5, x2out, 0);
    cudaEventRecord(evJ1, s2);

    // main: W = A*S sparse rows, Ac, adj
    k_wcount<<<NB, TB>>>();
    k_scan8192<<<1,1024>>>(wcnt, wrowptr);
    k_wfill<<<N_/8, 256>>>();
    k_AcRow<<<K_, 256>>>();
    cudaFuncSetAttribute(k_adjF, cudaFuncAttributeMaxDynamicSharedMemorySize, PSH_TOTAL);
    k_adjF<<<N_/8, 1024, PSH_TOTAL>>>(adj);

    // join decoder branch
    cudaStreamWaitEvent(0, evJ1, 0);
}

// round 10
// speedup vs baseline: 1.2043x; 1.1596x over previous
#include <cuda_runtime.h>
#include <cuda_fp16.h>
#include <math.h>
#include <stdint.h>

#define N_ 8192
#define E_ 131072
#define M_ (E_ + N_)          // 139264 edges incl self loops
#define H_ 128
#define K_ 4096
#define WCAP_ 3000000

#define AR 16                 // rows per adjF block
#define SCACHE 1024
#define PSH_TOTAL (131072 + SCACHE*8)   // 128KB fp16 P (16 rows x 4096 k) + 8KB S cache

// ---------------- device scratch ----------------
static __device__ float g_bufA[(size_t)N_*H_];
static __device__ float g_bufB[(size_t)N_*H_];
static __device__ float g_bufC[(size_t)N_*H_];
static __device__ float g_bufT[(size_t)N_*H_];
static __device__ int   g_cnt[N_];
static __device__ int   g_ocnt[N_];
static __device__ int   g_fill[N_];
static __device__ int   g_ofill[N_];
static __device__ int   g_rowptr[N_+1];     // CSR by dst
static __device__ int   g_orowptr[N_+1];    // CSR by src
static __device__ int2  g_adj[M_];          // per dst-CSR pos: (src, norm bits)
static __device__ int   g_oadj[M_];         // per src-CSR pos: dst
static __device__ float g_alpha[M_];        // per dst-CSR pos
static __device__ float g_aq[N_];
static __device__ float g_ah[N_];
static __device__ float g_cl1[N_], g_cl2[N_], g_cl3[N_];
static __device__ float g_fit[N_];
static __device__ int   g_sel[N_];
static __device__ int   g_col[N_];
static __device__ int   g_ncol[K_];
static __device__ float g_xp[(size_t)K_*H_];
static __device__ int   g_scnt[N_];
static __device__ int   g_srowptr[N_+1];
static __device__ int2  g_sp[M_];            // packed (col k, alpha bits), CSR by src
static __device__ int   g_wcnt[N_];
static __device__ int   g_wrowptr[N_+1];
static __device__ int2  g_W[WCAP_];          // W = A*S rows
static __device__ float g_Ac[(size_t)K_*K_];

// ---------------- helpers ----------------
__device__ __forceinline__ int esrc_f(const int* __restrict__ e0, int e){ return (e < E_) ? e0[e] : (e - E_); }
__device__ __forceinline__ int edst_f(const int* __restrict__ e1, int e){ return (e < E_) ? e1[e] : (e - E_); }

// ---------------- small utility kernels ----------------
__global__ void k_init0(){
    int i = blockIdx.x*blockDim.x + threadIdx.x;
    if (i < N_){ g_cnt[i]=0; g_ocnt[i]=0; g_fill[i]=0; g_ofill[i]=0; g_scnt[i]=0; }
}
__global__ void k_zeroN(int* __restrict__ p){
    int i = blockIdx.x*blockDim.x + threadIdx.x;
    if (i < N_) p[i]=0;
}
__global__ void k_count(const int* __restrict__ e0, const int* __restrict__ e1){
    int e = blockIdx.x*blockDim.x + threadIdx.x;
    if (e < M_){
        atomicAdd(&g_cnt[edst_f(e1,e)], 1);
        atomicAdd(&g_ocnt[esrc_f(e0,e)], 1);
    }
}
// exclusive scan of exactly 8192 ints with 1024 threads (shfl-based)
__device__ __forceinline__ void scan8192_body(const int* __restrict__ in, int* __restrict__ out){
    __shared__ int wsum[32];
    int tid=threadIdx.x, lane=tid&31, wid=tid>>5;
    int4 a=((const int4*)in)[tid*2], b=((const int4*)in)[tid*2+1];
    int l[8]={a.x,a.y,a.z,a.w,b.x,b.y,b.z,b.w};
    int s=0;
    #pragma unroll
    for(int q=0;q<8;q++) s+=l[q];
    int inc=s;
    #pragma unroll
    for(int o=1;o<32;o<<=1){ int t=__shfl_up_sync(0xffffffffu,inc,o); if(lane>=o) inc+=t; }
    if(lane==31) wsum[wid]=inc;
    __syncthreads();
    if (wid==0){
        int v = wsum[lane];
        #pragma unroll
        for(int o=1;o<32;o<<=1){ int t=__shfl_up_sync(0xffffffffu,v,o); if(lane>=o) v+=t; }
        wsum[lane]=v;
    }
    __syncthreads();
    int r = inc - s + (wid? wsum[wid-1]:0);
    int4 o1,o2;
    o1.x=r; r+=l[0]; o1.y=r; r+=l[1]; o1.z=r; r+=l[2]; o1.w=r; r+=l[3];
    o2.x=r; r+=l[4]; o2.y=r; r+=l[5]; o2.z=r; r+=l[6]; o2.w=r; r+=l[7];
    ((int4*)out)[tid*2]=o1; ((int4*)out)[tid*2+1]=o2;
    if (tid==1023) out[8192]=r;
}
__global__ void k_scan8192(const int* __restrict__ in, int* __restrict__ out){
    scan8192_body(in, out);
}
__global__ void k_scan2(){
    if (blockIdx.x == 0) scan8192_body(g_cnt, g_rowptr);
    else                 scan8192_body(g_ocnt, g_orowptr);
}
// build positional adjacency with folded norm (dis computed inline)
__global__ void k_fill(const int* __restrict__ e0, const int* __restrict__ e1){
    int e = blockIdx.x*blockDim.x + threadIdx.x;
    if (e < M_){
        int s = esrc_f(e0,e);
        int d = edst_f(e1,e);
        float nm = rsqrtf((float)g_cnt[s]) * rsqrtf((float)g_cnt[d]);
        int pos = g_rowptr[d] + atomicAdd(&g_fill[d],1);
        g_adj[pos] = make_int2(s, __float_as_int(nm));
        int opos = g_orowptr[s] + atomicAdd(&g_ofill[s],1);
        g_oadj[opos] = d;
    }
}

// ---------------- 8192x128 @ 128x128 GEMM ----------------
__global__ void k_gemm(const float* __restrict__ x, const float* __restrict__ w, float* __restrict__ y){
    __shared__ __align__(16) float xs[128*64];   // [kk][r]
    int r0 = blockIdx.x*64;
    int tid = threadIdx.x;
    for (int idx=tid; idx<64*128; idx+=256){
        int r = idx >> 7;
        int kk = idx & 127;
        xs[kk*64 + r] = x[(size_t)(r0+r)*128 + kk];
    }
    __syncthreads();
    int cg = tid & 31;
    int rg = tid >> 5;
    float acc[8][4];
    #pragma unroll
    for(int r=0;r<8;r++){ acc[r][0]=0.f;acc[r][1]=0.f;acc[r][2]=0.f;acc[r][3]=0.f; }
    #pragma unroll 4
    for(int kk=0;kk<128;kk++){
        float4 wv = *(const float4*)(w + kk*128 + cg*4);
        float4 x0 = *(const float4*)(xs + kk*64 + rg*8);
        float4 x1 = *(const float4*)(xs + kk*64 + rg*8 + 4);
        float xv[8] = {x0.x,x0.y,x0.z,x0.w,x1.x,x1.y,x1.z,x1.w};
        #pragma unroll
        for(int r=0;r<8;r++){
            acc[r][0] += xv[r]*wv.x; acc[r][1] += xv[r]*wv.y;
            acc[r][2] += xv[r]*wv.z; acc[r][3] += xv[r]*wv.w;
        }
    }
    #pragma unroll
    for(int r=0;r<8;r++){
        float4 o = make_float4(acc[r][0],acc[r][1],acc[r][2],acc[r][3]);
        *(float4*)(y + (size_t)(r0+rg*8+r)*128 + cg*4) = o;
    }
}

// ---------------- GCN aggregation: warp per dst, float4 lanes ----------------
__global__ void k_aggr(const float* __restrict__ y, const float* __restrict__ b,
                       float* __restrict__ out, int dotanh){
    int d = blockIdx.x*8 + (threadIdx.x>>5);
    int lane = threadIdx.x & 31;
    const float4* y4 = (const float4*)y;
    float4 acc = ((const float4*)b)[lane];
    int beg = g_rowptr[d], end = g_rowptr[d+1];
    int p = beg;
    for (; p+1 < end; p += 2){
        int2 a0 = g_adj[p], a1 = g_adj[p+1];
        float n0 = __int_as_float(a0.y), n1 = __int_as_float(a1.y);
        float4 v0 = y4[(size_t)a0.x*32 + lane];
        float4 v1 = y4[(size_t)a1.x*32 + lane];
        acc.x += n0*v0.x + n1*v1.x;
        acc.y += n0*v0.y + n1*v1.y;
        acc.z += n0*v0.z + n1*v1.z;
        acc.w += n0*v0.w + n1*v1.w;
    }
    if (p < end){
        int2 a0 = g_adj[p];
        float n0 = __int_as_float(a0.y);
        float4 v0 = y4[(size_t)a0.x*32 + lane];
        acc.x += n0*v0.x; acc.y += n0*v0.y; acc.z += n0*v0.z; acc.w += n0*v0.w;
    }
    if (dotanh){
        acc.x = tanhf(acc.x); acc.y = tanhf(acc.y);
        acc.z = tanhf(acc.z); acc.w = tanhf(acc.w);
    }
    ((float4*)out)[(size_t)d*32 + lane] = acc;
}

__global__ void k_segmax(const float* __restrict__ h, float* __restrict__ out){
    int d = blockIdx.x*8 + (threadIdx.x>>5);
    int lane = threadIdx.x & 31;
    const float4* h4 = (const float4*)h;
    float4 acc = make_float4(-INFINITY,-INFINITY,-INFINITY,-INFINITY);
    int beg = g_rowptr[d], end = g_rowptr[d+1];
    for (int p=beg; p<end; p++){
        float4 v = h4[(size_t)g_adj[p].x*32 + lane];
        acc.x = fmaxf(acc.x,v.x); acc.y = fmaxf(acc.y,v.y);
        acc.z = fmaxf(acc.z,v.z); acc.w = fmaxf(acc.w,v.w);
    }
    ((float4*)out)[(size_t)d*32 + lane] = acc;
}

__global__ void k_dots(const float* __restrict__ xq, const float* __restrict__ h,
                       const float* __restrict__ att, const float* __restrict__ bq){
    int node = blockIdx.x*8 + (threadIdx.x>>5);
    int lane = threadIdx.x & 31;
    const float4* xq4 = (const float4*)xq;
    const float4* h4  = (const float4*)h;
    const float4* at4 = (const float4*)att;
    const float4* bq4 = (const float4*)bq;
    float4 a1 = at4[lane], a2 = at4[32+lane];
    float4 xv = xq4[(size_t)node*32+lane], bv = bq4[lane], hv = h4[(size_t)node*32+lane];
    float s1 = a1.x*(xv.x+bv.x) + a1.y*(xv.y+bv.y) + a1.z*(xv.z+bv.z) + a1.w*(xv.w+bv.w);
    float s2 = a2.x*hv.x + a2.y*hv.y + a2.z*hv.z + a2.w*hv.w;
    #pragma unroll
    for (int o=16;o;o>>=1){ s1 += __shfl_down_sync(0xffffffffu,s1,o); s2 += __shfl_down_sync(0xffffffffu,s2,o); }
    if (!lane){ g_aq[node]=s1; g_ah[node]=s2; }
}

// per-dst softmax over in-edges (positional alpha) + cluster rep cx
__global__ void k_softcx(const float* __restrict__ h, float* __restrict__ cx){
    __shared__ float red[128];
    __shared__ float cache[1024];
    __shared__ int   scache[1024];
    int d = blockIdx.x, t = threadIdx.x;
    int beg = g_rowptr[d], end = g_rowptr[d+1];
    float aqd = g_aq[d];
    float mx = -INFINITY;
    for (int s=beg+t; s<end; s+=128){
        int src = g_adj[s].x;
        float sc = aqd + g_ah[src];
        sc = sc > 0.f ? sc : 0.2f*sc;
        if (s-beg < 1024){ cache[s-beg] = sc; scache[s-beg] = src; }
        mx = fmaxf(mx, sc);
    }
    red[t]=mx; __syncthreads();
    for (int o=64;o;o>>=1){ if(t<o) red[t]=fmaxf(red[t],red[t+o]); __syncthreads(); }
    mx = red[0]; __syncthreads();
    float sm = 0.f;
    for (int s=beg+t; s<end; s+=128){
        float sc;
        if (s-beg < 1024) sc = cache[s-beg];
        else { float v = aqd + g_ah[g_adj[s].x]; sc = v>0.f? v : 0.2f*v; }
        float ee = __expf(sc - mx);
        if (s-beg < 1024) cache[s-beg] = ee;
        sm += ee;
    }
    red[t]=sm; __syncthreads();
    for (int o=64;o;o>>=1){ if(t<o) red[t]+=red[t+o]; __syncthreads(); }
    float inv = 1.f/red[0];
    for (int s=beg+t; s<end; s+=128){
        float ee;
        if (s-beg < 1024) ee = cache[s-beg];
        else { float v = aqd + g_ah[g_adj[s].x]; v = v>0.f? v:0.2f*v; ee = __expf(v-mx); }
        float a = ee*inv;
        g_alpha[s] = a;
        if (s-beg < 1024) cache[s-beg] = a;
    }
    __syncthreads();
    float acc = 0.f;
    for (int s=beg; s<end; s++){
        float a; int src;
        if (s-beg < 1024){ a = cache[s-beg]; src = scache[s-beg]; }
        else { a = g_alpha[s]; src = g_adj[s].x; }
        acc += a * h[(size_t)src*128 + t];
    }
    cx[(size_t)d*128 + t] = acc;
}

__global__ void k_le(const float* __restrict__ cx, const float* __restrict__ lw1,
                     const float* __restrict__ lw2, const float* __restrict__ lw3){
    int node = blockIdx.x*8 + (threadIdx.x>>5);
    int lane = threadIdx.x & 31;
    const float4* c4 = (const float4*)cx;
    const float4* w14 = (const float4*)lw1;
    const float4* w24 = (const float4*)lw2;
    const float4* w34 = (const float4*)lw3;
    float4 v = c4[(size_t)node*32+lane];
    float4 w1v = w14[lane], w2v = w24[lane], w3v = w34[lane];
    float s1 = v.x*w1v.x + v.y*w1v.y + v.z*w1v.z + v.w*w1v.w;
    float s2 = v.x*w2v.x + v.y*w2v.y + v.z*w2v.z + v.w*w2v.w;
    float s3 = v.x*w3v.x + v.y*w3v.y + v.z*w3v.z + v.w*w3v.w;
    #pragma unroll
    for (int o=16;o;o>>=1){
        s1 += __shfl_down_sync(0xffffffffu,s1,o);
        s2 += __shfl_down_sync(0xffffffffu,s2,o);
        s3 += __shfl_down_sync(0xffffffffu,s3,o);
    }
    if (!lane){ g_cl1[node]=s1; g_cl2[node]=s2; g_cl3[node]=s3; }
}
__global__ void k_fit(const float* __restrict__ lb1){
    int d = blockIdx.x*blockDim.x + threadIdx.x;
    if (d >= N_) return;
    int beg=g_rowptr[d], end=g_rowptr[d+1];
    float s = 0.f;
    for (int q=beg;q<end;q++) s += g_cl3[g_adj[q].x];
    float aggr = (float)(end-beg)*g_cl2[d] - s;
    float z = g_cl1[d] + lb1[0] + aggr;
    g_fit[d] = 1.f/(1.f + __expf(-z));
}

// ---------------- top-K via 4x8-bit histogram radix select ----------------
__global__ void k_topk(){
    __shared__ int hist[256];
    __shared__ int wred[8];
    __shared__ unsigned s_pref;
    __shared__ int s_need;
    int tid=threadIdx.x, lane=tid&31, wid=tid>>5;
    if (tid==0){ s_pref=0u; s_need=K_; }
    unsigned keys[32];
    #pragma unroll
    for (int q=0;q<32;q++){
        unsigned u=__float_as_uint(g_fit[tid*32+q]);
        keys[q] = (u & 0x80000000u) ? ~u : (u | 0x80000000u);
    }
    __syncthreads();
    for (int round=0; round<4; round++){
        int shift = 24 - 8*round;
        hist[tid]=0;
        __syncthreads();
        unsigned pref = s_pref;
        #pragma unroll
        for (int q=0;q<32;q++){
            unsigned k = keys[q];
            bool match = (round==0) || ((k >> (shift+8)) == (pref >> (shift+8)));
            if (match) atomicAdd(&hist[(k>>shift)&0xFFu], 1);
        }
        __syncthreads();
        int mine = hist[255-tid];
        int v = mine;
        #pragma unroll
        for (int o=1;o<32;o<<=1){ int t2=__shfl_up_sync(0xffffffffu,v,o); if(lane>=o) v+=t2; }
        if (lane==31) wred[wid]=v;
        __syncthreads();
        int woff=0;
        #pragma unroll
        for (int w=0;w<8;w++) if (w<wid) woff+=wred[w];
        v += woff;
        int need0 = s_need;
        int vex = v - mine;
        if (v >= need0 && vex < need0){
            s_pref = s_pref | ((unsigned)(255-tid) << shift);
            s_need = need0 - vex;
        }
        __syncthreads();
    }
    unsigned thr = s_pref;
    int need = s_need;
    int tcnt=0;
    #pragma unroll
    for (int q=0;q<32;q++) tcnt += (keys[q]==thr);
    int v=tcnt;
    #pragma unroll
    for (int o=1;o<32;o<<=1){ int t2=__shfl_up_sync(0xffffffffu,v,o); if(lane>=o) v+=t2; }
    if (lane==31) wred[wid]=v;
    __syncthreads();
    int woff=0;
    #pragma unroll
    for (int w=0;w<8;w++) if (w<wid) woff+=wred[w];
    int rank = v - tcnt + woff;
    int scnt=0;
    int selq[32];
    #pragma unroll
    for (int q=0;q<32;q++){
        unsigned k=keys[q];
        bool eq = (k==thr);
        int s = (k>thr) || (eq && rank < need);
        if (eq) rank++;
        selq[q]=s;
        g_sel[tid*32+q]=s;
        scnt+=s;
    }
    __syncthreads();
    v=scnt;
    #pragma unroll
    for (int o=1;o<32;o<<=1){ int t2=__shfl_up_sync(0xffffffffu,v,o); if(lane>=o) v+=t2; }
    if (lane==31) wred[wid]=v;
    __syncthreads();
    woff=0;
    #pragma unroll
    for (int w=0;w<8;w++) if (w<wid) woff+=wred[w];
    int base = v - scnt + woff;
    #pragma unroll
    for (int q=0;q<32;q++){
        int i = tid*32+q;
        if (selq[q]){ g_col[i]=base; g_ncol[base]=i; base++; }
        else g_col[i]=-1;
    }
}

__global__ void k_xp(const float* __restrict__ cx){
    int i = blockIdx.x, t = threadIdx.x;
    if (!g_sel[i]) return;
    g_xp[(size_t)g_col[i]*128 + t] = cx[(size_t)i*128 + t] * g_fit[i];
}

// ---------------- S CSR (by source): count + fill from dst rows ----------------
__global__ void k_scount(){
    int d = blockIdx.x*blockDim.x + threadIdx.x;
    if (d >= N_ || !g_sel[d]) return;
    int beg=g_rowptr[d], end=g_rowptr[d+1];
    for (int p=beg;p<end;p++) atomicAdd(&g_scnt[g_adj[p].x], 1);
}
__global__ void k_sfill(){
    int d = blockIdx.x*blockDim.x + threadIdx.x;
    if (d >= N_ || !g_sel[d]) return;
    int colk = g_col[d];
    int beg=g_rowptr[d], end=g_rowptr[d+1];
    for (int p=beg;p<end;p++){
        int s = g_adj[p].x;
        int pos = g_srowptr[s] + atomicAdd(&g_fill[s],1);
        g_sp[pos] = make_int2(colk, __float_as_int(g_alpha[p]));
    }
}

// ---------------- W = A*S (sparse rows): count, fill ----------------
__global__ void k_wcount(){
    int s = blockIdx.x*blockDim.x + threadIdx.x;
    if (s >= N_) return;
    int ob=g_orowptr[s], oe=g_orowptr[s+1];
    int total=0;
    for (int f=ob;f<oe;f++){
        int j = g_oadj[f];
        total += g_srowptr[j+1]-g_srowptr[j];
    }
    g_wcnt[s]=total;
}
// warp per source: copy S_j lists into W row
__global__ void k_wfill(){
    int s = blockIdx.x*8 + (threadIdx.x>>5);
    int lane = threadIdx.x & 31;
    int wpos = g_wrowptr[s];
    int ob=g_orowptr[s], oe=g_orowptr[s+1];
    for (int f=ob;f<oe;f++){
        int j = g_oadj[f];
        int sb=g_srowptr[j], len=g_srowptr[j+1]-sb;
        for (int q=lane;q<len;q+=32) g_W[wpos+q]=g_sp[sb+q];
        wpos += len;
    }
}

// ---------------- Ac row gather with smem accumulator (flat W rows) ----------------
__global__ void k_AcRow(){
    __shared__ __align__(16) float acc[K_];
    int k = blockIdx.x, tid = threadIdx.x;
    int lane = tid & 31, w = tid >> 5, nw = blockDim.x >> 5;
    {
        float4 z = make_float4(0,0,0,0);
        float4* a4 = (float4*)acc;
        #pragma unroll
        for (int m=0;m<2;m++) a4[tid + m*512] = z;
    }
    __syncthreads();
    int d = g_ncol[k];
    int ib = g_rowptr[d], ie = g_rowptr[d+1];
    for (int p=ib+w; p<ie; p+=nw){
        int s = g_adj[p].x;
        float ae = g_alpha[p];
        int wb = g_wrowptr[s], we = g_wrowptr[s+1];
        int q = wb + lane;
        for (; q+32 < we; q += 64){
            int2 e0 = g_W[q];
            int2 e1 = g_W[q+32];
            atomicAdd(&acc[e0.x], ae*__int_as_float(e0.y));
            atomicAdd(&acc[e1.x], ae*__int_as_float(e1.y));
        }
        if (q < we){
            int2 e0 = g_W[q];
            atomicAdd(&acc[e0.x], ae*__int_as_float(e0.y));
        }
    }
    __syncthreads();
    float4* orow = (float4*)&g_Ac[(size_t)k*K_];
    const float4* a4 = (const float4*)acc;
    #pragma unroll
    for (int m=0;m<2;m++) orow[tid + m*512] = a4[tid + m*512];
}

// ---------------- fused: build 16 P-rows (fp32 acc -> fp16 smem), adj = P S^T ----------------
// 512 threads, 136KB smem. P layout: lo bytes [0,64K): uint4 per k = 4 half2 rowpairs 0-3
// (rows 0-7); hi bytes [64K,128K): rowpairs 4-7 (rows 8-15). 16B chunk index = k mod 8.
__global__ void __launch_bounds__(512, 1) k_adjF(float* __restrict__ adj){
    extern __shared__ __align__(16) char PshB[];
    int2* sc = (int2*)(PshB + 131072);
    int i0 = blockIdx.x*AR, tid = threadIdx.x;

    int qb0 = g_srowptr[i0];
    int qend = g_srowptr[i0+AR];
    int total = qend - qb0;
    int ncache = total < SCACHE ? total : SCACHE;
    for (int q=tid; q<ncache; q+=512) sc[q] = g_sp[qb0+q];
    __syncthreads();

    const float* Ac = g_Ac;
    #pragma unroll 1
    for (int rp=0;rp<8;rp++){
        float accA[8], accB[8];
        #pragma unroll
        for (int m=0;m<8;m++){ accA[m]=0.f; accB[m]=0.f; }
        #pragma unroll 1
        for (int half_i=0; half_i<2; half_i++){
            int i = i0 + 2*rp + half_i;
            float* acc = half_i ? accB : accA;
            int qb=g_srowptr[i], qe=g_srowptr[i+1];
            if (qe - qb0 <= ncache){
                int base = qb - qb0, len = qe - qb;
                #pragma unroll 2
                for (int q=0;q<len;q++){
                    int2 kp = sc[base+q];
                    float a = __int_as_float(kp.y);
                    const float* row = Ac + (size_t)kp.x*K_ + tid;
                    #pragma unroll
                    for (int m=0;m<8;m++) acc[m] += a*row[m*512];
                }
            } else {
                for (int q=qb;q<qe;q++){
                    int2 kp = g_sp[q];
                    float a = __int_as_float(kp.y);
                    const float* row = Ac + (size_t)kp.x*K_ + tid;
                    #pragma unroll
                    for (int m=0;m<8;m++) acc[m] += a*row[m*512];
                }
            }
        }
        char* region = PshB + ((rp<4)? 0 : 65536);
        int woff = (rp & 3)*4;
        #pragma unroll
        for (int m=0;m<8;m++){
            int k = tid + 512*m;
            __half2 h = __floats2half2_rn(accA[m], accB[m]);
            *(__half2*)(region + (size_t)k*16 + woff) = h;
        }
    }
    __syncthreads();
    for (int j=tid; j<N_; j+=512){
        float b[16];
        #pragma unroll
        for (int r=0;r<16;r++) b[r]=0.f;
        int qb = g_srowptr[j], qe = g_srowptr[j+1];
        for (int q=qb;q<qe;q++){
            int2 kp = g_sp[q];
            float a = __int_as_float(kp.y);
            uint4 lo = *(const uint4*)(PshB + (size_t)kp.x*16);
            uint4 hi = *(const uint4*)(PshB + 65536 + (size_t)kp.x*16);
            float2 f;
            f = __half22float2(*(__half2*)&lo.x); b[0] += a*f.x; b[1] += a*f.y;
            f = __half22float2(*(__half2*)&lo.y); b[2] += a*f.x; b[3] += a*f.y;
            f = __half22float2(*(__half2*)&lo.z); b[4] += a*f.x; b[5] += a*f.y;
            f = __half22float2(*(__half2*)&lo.w); b[6] += a*f.x; b[7] += a*f.y;
            f = __half22float2(*(__half2*)&hi.x); b[8] += a*f.x; b[9] += a*f.y;
            f = __half22float2(*(__half2*)&hi.y); b[10]+= a*f.x; b[11]+= a*f.y;
            f = __half22float2(*(__half2*)&hi.z); b[12]+= a*f.x; b[13]+= a*f.y;
            f = __half22float2(*(__half2*)&hi.w); b[14]+= a*f.x; b[15]+= a*f.y;
        }
        #pragma unroll
        for (int r=0;r<16;r++) adj[(size_t)(i0+r)*N_ + j] = b[r];
    }
}

// x_out[i,:] = sum over S row i: alpha*xp[k,:]  (warp per row, float4)
__global__ void k_xout(float* __restrict__ out){
    int i = blockIdx.x*8 + (threadIdx.x>>5);
    int lane = threadIdx.x & 31;
    const float4* xp4 = (const float4*)g_xp;
    float4 acc = make_float4(0,0,0,0);
    int beg=g_srowptr[i], end=g_srowptr[i+1];
    for (int q=beg;q<end;q++){
        int2 kp = g_sp[q];
        float a = __int_as_float(kp.y);
        float4 v = xp4[(size_t)kp.x*32 + lane];
        acc.x += a*v.x; acc.y += a*v.y; acc.z += a*v.z; acc.w += a*v.w;
    }
    ((float4*)out)[(size_t)i*32 + lane] = acc;
}

// ---------------- host ----------------
static cudaStream_t get_s2(){
    static cudaStream_t s = 0;
    if (!s) cudaStreamCreate(&s);
    return s;
}
static cudaEvent_t get_ev(int which){
    static cudaEvent_t ev[4] = {0,0,0,0};
    if (!ev[which]) cudaEventCreateWithFlags(&ev[which], cudaEventDisableTiming);
    return ev[which];
}

extern "C" void kernel_launch(void* const* d_in, const int* in_sizes, int n_in,
                              void* d_out, int out_size){
    const float* nodes = (const float*)d_in[0];
    const int*   edges = (const int*)d_in[1];
    const int* e0 = edges;
    const int* e1 = edges + E_;
    const float* w1 = (const float*)d_in[3];  const float* b1 = (const float*)d_in[4];
    const float* w2 = (const float*)d_in[5];  const float* b2 = (const float*)d_in[6];
    const float* w3 = (const float*)d_in[7];  const float* b3 = (const float*)d_in[8];
    const float* w4 = (const float*)d_in[9];  const float* b4 = (const float*)d_in[10];
    const float* w5 = (const float*)d_in[11]; const float* b5 = (const float*)d_in[12];
    const float* wq = (const float*)d_in[13]; const float* bq = (const float*)d_in[14];
    const float* att = (const float*)d_in[15];
    const float* lw1 = (const float*)d_in[16]; const float* lb1 = (const float*)d_in[17];
    const float* lw2 = (const float*)d_in[18]; const float* lw3 = (const float*)d_in[19];

    float* out = (float*)d_out;
    float* x2out = out;
    float* adj  = out + (size_t)N_*H_;

    float *A,*B,*C,*T; int *scnt,*srowptr,*wcnt,*wrowptr,*fill;
    cudaGetSymbolAddress((void**)&A, g_bufA);
    cudaGetSymbolAddress((void**)&B, g_bufB);
    cudaGetSymbolAddress((void**)&C, g_bufC);
    cudaGetSymbolAddress((void**)&T, g_bufT);
    cudaGetSymbolAddress((void**)&scnt, g_scnt);
    cudaGetSymbolAddress((void**)&srowptr, g_srowptr);
    cudaGetSymbolAddress((void**)&wcnt, g_wcnt);
    cudaGetSymbolAddress((void**)&wrowptr, g_wrowptr);
    cudaGetSymbolAddress((void**)&fill, g_fill);

    const int TB = 256;
    const int MB = (M_ + TB - 1)/TB;
    const int NB = (N_ + TB - 1)/TB;

    cudaStream_t s2 = get_s2();
    cudaEvent_t evF0 = get_ev(0), evJ0 = get_ev(1), evF1 = get_ev(2), evJ1 = get_ev(3);

    // fork 0: first gemm (depends only on inputs) overlaps graph prep
    cudaEventRecord(evF0, 0);
    cudaStreamWaitEvent(s2, evF0, 0);
    k_gemm<<<128,256,0,s2>>>(nodes, w1, T);
    cudaEventRecord(evJ0, s2);

    // graph prep: dst-CSR + src-CSR with folded norms (main stream)
    k_init0<<<NB, TB>>>();
    k_count<<<MB, TB>>>(e0, e1);
    k_scan2<<<2,1024>>>();
    k_fill<<<MB, TB>>>(e0, e1);

    // encoder (needs gemm1 result)
    cudaStreamWaitEvent(0, evJ0, 0);
    k_aggr<<<N_/8,256>>>(T, b1, A, 1);
    k_gemm<<<128,256>>>(A, w2, T);
    k_aggr<<<N_/8,256>>>(T, b2, B, 1);       // B = h

    // pooling
    k_segmax<<<N_/8,256>>>(B, A);
    k_gemm<<<128,256>>>(A, wq, T);
    k_dots<<<N_/8,256>>>(T, B, att, bq);
    k_softcx<<<N_,128>>>(B, C);              // C = cx, writes positional g_alpha
    k_le<<<N_/8,256>>>(C, lw1, lw2, lw3);
    k_fit<<<NB, TB>>>(lb1);
    k_topk<<<1,256>>>();
    k_xp<<<N_,128>>>(C);

    // S CSR (by source)
    k_scount<<<NB, TB>>>();
    k_scan8192<<<1,1024>>>(scnt, srowptr);
    k_zeroN<<<NB, TB>>>(fill);
    k_sfill<<<NB, TB>>>();

    // fork 1: decoder branch (s2) overlaps W-build + AcRow + adjF (main)
    cudaEventRecord(evF1, 0);
    cudaStreamWaitEvent(s2, evF1, 0);
    k_xout<<<N_/8,256,0,s2>>>(A);            // A = x_out
    k_gemm<<<128,256,0,s2>>>(A, w3, T);
    k_aggr<<<N_/8,256,0,s2>>>(T, b3, B, 1);
    k_gemm<<<128,256,0,s2>>>(B, w4, T);
    k_aggr<<<N_/8,256,0,s2>>>(T, b4, A, 1);
    k_gemm<<<128,256,0,s2>>>(A, w5, T);
    k_aggr<<<N_/8,256,0,s2>>>(T, b5, x2out, 0);
    cudaEventRecord(evJ1, s2);

    // main: W = A*S sparse rows, Ac, adj
    k_wcount<<<NB, TB>>>();
    k_scan8192<<<1,1024>>>(wcnt, wrowptr);
    k_wfill<<<N_/8, 256>>>();
    k_AcRow<<<K_, 512>>>();
    cudaFuncSetAttribute(k_adjF, cudaFuncAttributeMaxDynamicSharedMemorySize, PSH_TOTAL);
    k_adjF<<<N_/AR, 512, PSH_TOTAL>>>(adj);

    // join decoder branch
    cudaStreamWaitEvent(0, evJ1, 0);
}

// round 11
// speedup vs baseline: 1.2277x; 1.0194x over previous
#include <cuda_runtime.h>
#include <cuda_fp16.h>
#include <math.h>
#include <stdint.h>

#define N_ 8192
#define E_ 131072
#define M_ (E_ + N_)          // 139264 edges incl self loops
#define H_ 128
#define K_ 4096
#define WCAP_ 3000000

#define AR 16                 // rows per adjF block
#define SCACHE 1024
#define PSH_TOTAL (131072 + SCACHE*8)   // 128KB fp16 P (16 rows x 4096 k) + 8KB S cache

// ---------------- device scratch ----------------
static __device__ float g_bufA[(size_t)N_*H_];
static __device__ float g_bufB[(size_t)N_*H_];
static __device__ float g_bufC[(size_t)N_*H_];
static __device__ float g_bufT[(size_t)N_*H_];
static __device__ int   g_cnt[N_];
static __device__ int   g_ocnt[N_];
static __device__ int   g_fill[N_];
static __device__ int   g_ofill[N_];
static __device__ int   g_rowptr[N_+1];     // CSR by dst
static __device__ int   g_orowptr[N_+1];    // CSR by src
static __device__ int2  g_adj[M_];          // per dst-CSR pos: (src, norm bits)
static __device__ int   g_oadj[M_];         // per src-CSR pos: dst
static __device__ float g_alpha[M_];        // per dst-CSR pos
static __device__ float g_aq[N_];
static __device__ float g_ah[N_];
static __device__ float g_cl1[N_], g_cl2[N_], g_cl3[N_];
static __device__ float g_fit[N_];
static __device__ int   g_sel[N_];
static __device__ int   g_col[N_];
static __device__ int   g_ncol[K_];
static __device__ float g_xp[(size_t)K_*H_];
static __device__ int   g_scnt[N_];
static __device__ int   g_srowptr[N_+1];
static __device__ int2  g_sp[M_];            // packed (col k, alpha bits), CSR by src
static __device__ int   g_wcnt[N_];
static __device__ int   g_wrowptr[N_+1];
static __device__ int2  g_W[WCAP_];          // W = A*S rows
static __device__ __half g_Ach[(size_t)K_*K_];   // Ac in fp16 (32MB, L2-resident)

// ---------------- helpers ----------------
__device__ __forceinline__ int esrc_f(const int* __restrict__ e0, int e){ return (e < E_) ? e0[e] : (e - E_); }
__device__ __forceinline__ int edst_f(const int* __restrict__ e1, int e){ return (e < E_) ? e1[e] : (e - E_); }

// ---------------- small utility kernels ----------------
__global__ void k_init0(){
    int i = blockIdx.x*blockDim.x + threadIdx.x;
    if (i < N_){ g_cnt[i]=0; g_ocnt[i]=0; g_fill[i]=0; g_ofill[i]=0; g_scnt[i]=0; }
}
__global__ void k_zeroN(int* __restrict__ p){
    int i = blockIdx.x*blockDim.x + threadIdx.x;
    if (i < N_) p[i]=0;
}
__global__ void k_count(const int* __restrict__ e0, const int* __restrict__ e1){
    int e = blockIdx.x*blockDim.x + threadIdx.x;
    if (e < M_){
        atomicAdd(&g_cnt[edst_f(e1,e)], 1);
        atomicAdd(&g_ocnt[esrc_f(e0,e)], 1);
    }
}
// exclusive scan of exactly 8192 ints with 1024 threads (shfl-based)
__device__ __forceinline__ void scan8192_body(const int* __restrict__ in, int* __restrict__ out){
    __shared__ int wsum[32];
    int tid=threadIdx.x, lane=tid&31, wid=tid>>5;
    int4 a=((const int4*)in)[tid*2], b=((const int4*)in)[tid*2+1];
    int l[8]={a.x,a.y,a.z,a.w,b.x,b.y,b.z,b.w};
    int s=0;
    #pragma unroll
    for(int q=0;q<8;q++) s+=l[q];
    int inc=s;
    #pragma unroll
    for(int o=1;o<32;o<<=1){ int t=__shfl_up_sync(0xffffffffu,inc,o); if(lane>=o) inc+=t; }
    if(lane==31) wsum[wid]=inc;
    __syncthreads();
    if (wid==0){
        int v = wsum[lane];
        #pragma unroll
        for(int o=1;o<32;o<<=1){ int t=__shfl_up_sync(0xffffffffu,v,o); if(lane>=o) v+=t; }
        wsum[lane]=v;
    }
    __syncthreads();
    int r = inc - s + (wid? wsum[wid-1]:0);
    int4 o1,o2;
    o1.x=r; r+=l[0]; o1.y=r; r+=l[1]; o1.z=r; r+=l[2]; o1.w=r; r+=l[3];
    o2.x=r; r+=l[4]; o2.y=r; r+=l[5]; o2.z=r; r+=l[6]; o2.w=r; r+=l[7];
    ((int4*)out)[tid*2]=o1; ((int4*)out)[tid*2+1]=o2;
    if (tid==1023) out[8192]=r;
}
__global__ void k_scan8192(const int* __restrict__ in, int* __restrict__ out){
    scan8192_body(in, out);
}
__global__ void k_scan2(){
    if (blockIdx.x == 0) scan8192_body(g_cnt, g_rowptr);
    else                 scan8192_body(g_ocnt, g_orowptr);
}
// build positional adjacency with folded norm (dis computed inline)
__global__ void k_fill(const int* __restrict__ e0, const int* __restrict__ e1){
    int e = blockIdx.x*blockDim.x + threadIdx.x;
    if (e < M_){
        int s = esrc_f(e0,e);
        int d = edst_f(e1,e);
        float nm = rsqrtf((float)g_cnt[s]) * rsqrtf((float)g_cnt[d]);
        int pos = g_rowptr[d] + atomicAdd(&g_fill[d],1);
        g_adj[pos] = make_int2(s, __float_as_int(nm));
        int opos = g_orowptr[s] + atomicAdd(&g_ofill[s],1);
        g_oadj[opos] = d;
    }
}

// ---------------- 8192x128 @ 128x128 GEMM ----------------
__global__ void k_gemm(const float* __restrict__ x, const float* __restrict__ w, float* __restrict__ y){
    __shared__ __align__(16) float xs[128*64];   // [kk][r]
    int r0 = blockIdx.x*64;
    int tid = threadIdx.x;
    for (int idx=tid; idx<64*128; idx+=256){
        int r = idx >> 7;
        int kk = idx & 127;
        xs[kk*64 + r] = x[(size_t)(r0+r)*128 + kk];
    }
    __syncthreads();
    int cg = tid & 31;
    int rg = tid >> 5;
    float acc[8][4];
    #pragma unroll
    for(int r=0;r<8;r++){ acc[r][0]=0.f;acc[r][1]=0.f;acc[r][2]=0.f;acc[r][3]=0.f; }
    #pragma unroll 4
    for(int kk=0;kk<128;kk++){
        float4 wv = *(const float4*)(w + kk*128 + cg*4);
        float4 x0 = *(const float4*)(xs + kk*64 + rg*8);
        float4 x1 = *(const float4*)(xs + kk*64 + rg*8 + 4);
        float xv[8] = {x0.x,x0.y,x0.z,x0.w,x1.x,x1.y,x1.z,x1.w};
        #pragma unroll
        for(int r=0;r<8;r++){
            acc[r][0] += xv[r]*wv.x; acc[r][1] += xv[r]*wv.y;
            acc[r][2] += xv[r]*wv.z; acc[r][3] += xv[r]*wv.w;
        }
    }
    #pragma unroll
    for(int r=0;r<8;r++){
        float4 o = make_float4(acc[r][0],acc[r][1],acc[r][2],acc[r][3]);
        *(float4*)(y + (size_t)(r0+rg*8+r)*128 + cg*4) = o;
    }
}

// ---------------- GCN aggregation: warp per dst, float4 lanes ----------------
__global__ void k_aggr(const float* __restrict__ y, const float* __restrict__ b,
                       float* __restrict__ out, int dotanh){
    int d = blockIdx.x*8 + (threadIdx.x>>5);
    int lane = threadIdx.x & 31;
    const float4* y4 = (const float4*)y;
    float4 acc = ((const float4*)b)[lane];
    int beg = g_rowptr[d], end = g_rowptr[d+1];
    int p = beg;
    for (; p+1 < end; p += 2){
        int2 a0 = g_adj[p], a1 = g_adj[p+1];
        float n0 = __int_as_float(a0.y), n1 = __int_as_float(a1.y);
        float4 v0 = y4[(size_t)a0.x*32 + lane];
        float4 v1 = y4[(size_t)a1.x*32 + lane];
        acc.x += n0*v0.x + n1*v1.x;
        acc.y += n0*v0.y + n1*v1.y;
        acc.z += n0*v0.z + n1*v1.z;
        acc.w += n0*v0.w + n1*v1.w;
    }
    if (p < end){
        int2 a0 = g_adj[p];
        float n0 = __int_as_float(a0.y);
        float4 v0 = y4[(size_t)a0.x*32 + lane];
        acc.x += n0*v0.x; acc.y += n0*v0.y; acc.z += n0*v0.z; acc.w += n0*v0.w;
    }
    if (dotanh){
        acc.x = tanhf(acc.x); acc.y = tanhf(acc.y);
        acc.z = tanhf(acc.z); acc.w = tanhf(acc.w);
    }
    ((float4*)out)[(size_t)d*32 + lane] = acc;
}

__global__ void k_segmax(const float* __restrict__ h, float* __restrict__ out){
    int d = blockIdx.x*8 + (threadIdx.x>>5);
    int lane = threadIdx.x & 31;
    const float4* h4 = (const float4*)h;
    float4 acc = make_float4(-INFINITY,-INFINITY,-INFINITY,-INFINITY);
    int beg = g_rowptr[d], end = g_rowptr[d+1];
    for (int p=beg; p<end; p++){
        float4 v = h4[(size_t)g_adj[p].x*32 + lane];
        acc.x = fmaxf(acc.x,v.x); acc.y = fmaxf(acc.y,v.y);
        acc.z = fmaxf(acc.z,v.z); acc.w = fmaxf(acc.w,v.w);
    }
    ((float4*)out)[(size_t)d*32 + lane] = acc;
}

__global__ void k_dots(const float* __restrict__ xq, const float* __restrict__ h,
                       const float* __restrict__ att, const float* __restrict__ bq){
    int node = blockIdx.x*8 + (threadIdx.x>>5);
    int lane = threadIdx.x & 31;
    const float4* xq4 = (const float4*)xq;
    const float4* h4  = (const float4*)h;
    const float4* at4 = (const float4*)att;
    const float4* bq4 = (const float4*)bq;
    float4 a1 = at4[lane], a2 = at4[32+lane];
    float4 xv = xq4[(size_t)node*32+lane], bv = bq4[lane], hv = h4[(size_t)node*32+lane];
    float s1 = a1.x*(xv.x+bv.x) + a1.y*(xv.y+bv.y) + a1.z*(xv.z+bv.z) + a1.w*(xv.w+bv.w);
    float s2 = a2.x*hv.x + a2.y*hv.y + a2.z*hv.z + a2.w*hv.w;
    #pragma unroll
    for (int o=16;o;o>>=1){ s1 += __shfl_down_sync(0xffffffffu,s1,o); s2 += __shfl_down_sync(0xffffffffu,s2,o); }
    if (!lane){ g_aq[node]=s1; g_ah[node]=s2; }
}

// per-dst softmax over in-edges + cluster rep cx + fused LEConv dots (k_le)
__global__ void k_softcx(const float* __restrict__ h, float* __restrict__ cx,
                         const float* __restrict__ lw1, const float* __restrict__ lw2,
                         const float* __restrict__ lw3){
    __shared__ float red[128];
    __shared__ float cache[1024];
    __shared__ int   scache[1024];
    int d = blockIdx.x, t = threadIdx.x;
    int beg = g_rowptr[d], end = g_rowptr[d+1];
    float aqd = g_aq[d];
    float mx = -INFINITY;
    for (int s=beg+t; s<end; s+=128){
        int src = g_adj[s].x;
        float sc = aqd + g_ah[src];
        sc = sc > 0.f ? sc : 0.2f*sc;
        if (s-beg < 1024){ cache[s-beg] = sc; scache[s-beg] = src; }
        mx = fmaxf(mx, sc);
    }
    red[t]=mx; __syncthreads();
    for (int o=64;o;o>>=1){ if(t<o) red[t]=fmaxf(red[t],red[t+o]); __syncthreads(); }
    mx = red[0]; __syncthreads();
    float sm = 0.f;
    for (int s=beg+t; s<end; s+=128){
        float sc;
        if (s-beg < 1024) sc = cache[s-beg];
        else { float v = aqd + g_ah[g_adj[s].x]; sc = v>0.f? v : 0.2f*v; }
        float ee = __expf(sc - mx);
        if (s-beg < 1024) cache[s-beg] = ee;
        sm += ee;
    }
    red[t]=sm; __syncthreads();
    for (int o=64;o;o>>=1){ if(t<o) red[t]+=red[t+o]; __syncthreads(); }
    float inv = 1.f/red[0];
    for (int s=beg+t; s<end; s+=128){
        float ee;
        if (s-beg < 1024) ee = cache[s-beg];
        else { float v = aqd + g_ah[g_adj[s].x]; v = v>0.f? v:0.2f*v; ee = __expf(v-mx); }
        float a = ee*inv;
        g_alpha[s] = a;
        if (s-beg < 1024) cache[s-beg] = a;
    }
    __syncthreads();
    float acc = 0.f;
    for (int s=beg; s<end; s++){
        float a; int src;
        if (s-beg < 1024){ a = cache[s-beg]; src = scache[s-beg]; }
        else { a = g_alpha[s]; src = g_adj[s].x; }
        acc += a * h[(size_t)src*128 + t];
    }
    cx[(size_t)d*128 + t] = acc;
    // fused LEConv dots: cl1/2/3[d] = cx[d,:].lw{1,2,3}
    __syncthreads();
    red[t] = acc*lw1[t]; __syncthreads();
    for (int o=64;o;o>>=1){ if(t<o) red[t]+=red[t+o]; __syncthreads(); }
    if (!t) g_cl1[d]=red[0];
    __syncthreads();
    red[t] = acc*lw2[t]; __syncthreads();
    for (int o=64;o;o>>=1){ if(t<o) red[t]+=red[t+o]; __syncthreads(); }
    if (!t) g_cl2[d]=red[0];
    __syncthreads();
    red[t] = acc*lw3[t]; __syncthreads();
    for (int o=64;o;o>>=1){ if(t<o) red[t]+=red[t+o]; __syncthreads(); }
    if (!t) g_cl3[d]=red[0];
}

__global__ void k_fit(const float* __restrict__ lb1){
    int d = blockIdx.x*blockDim.x + threadIdx.x;
    if (d >= N_) return;
    int beg=g_rowptr[d], end=g_rowptr[d+1];
    float s = 0.f;
    for (int q=beg;q<end;q++) s += g_cl3[g_adj[q].x];
    float aggr = (float)(end-beg)*g_cl2[d] - s;
    float z = g_cl1[d] + lb1[0] + aggr;
    g_fit[d] = 1.f/(1.f + __expf(-z));
}

// ---------------- top-K via 4x8-bit histogram radix select ----------------
__global__ void k_topk(){
    __shared__ int hist[256];
    __shared__ int wred[8];
    __shared__ unsigned s_pref;
    __shared__ int s_need;
    int tid=threadIdx.x, lane=tid&31, wid=tid>>5;
    if (tid==0){ s_pref=0u; s_need=K_; }
    unsigned keys[32];
    #pragma unroll
    for (int q=0;q<32;q++){
        unsigned u=__float_as_uint(g_fit[tid*32+q]);
        keys[q] = (u & 0x80000000u) ? ~u : (u | 0x80000000u);
    }
    __syncthreads();
    for (int round=0; round<4; round++){
        int shift = 24 - 8*round;
        hist[tid]=0;
        __syncthreads();
        unsigned pref = s_pref;
        #pragma unroll
        for (int q=0;q<32;q++){
            unsigned k = keys[q];
            bool match = (round==0) || ((k >> (shift+8)) == (pref >> (shift+8)));
            if (match) atomicAdd(&hist[(k>>shift)&0xFFu], 1);
        }
        __syncthreads();
        int mine = hist[255-tid];
        int v = mine;
        #pragma unroll
        for (int o=1;o<32;o<<=1){ int t2=__shfl_up_sync(0xffffffffu,v,o); if(lane>=o) v+=t2; }
        if (lane==31) wred[wid]=v;
        __syncthreads();
        int woff=0;
        #pragma unroll
        for (int w=0;w<8;w++) if (w<wid) woff+=wred[w];
        v += woff;
        int need0 = s_need;
        int vex = v - mine;
        if (v >= need0 && vex < need0){
            s_pref = s_pref | ((unsigned)(255-tid) << shift);
            s_need = need0 - vex;
        }
        __syncthreads();
    }
    unsigned thr = s_pref;
    int need = s_need;
    int tcnt=0;
    #pragma unroll
    for (int q=0;q<32;q++) tcnt += (keys[q]==thr);
    int v=tcnt;
    #pragma unroll
    for (int o=1;o<32;o<<=1){ int t2=__shfl_up_sync(0xffffffffu,v,o); if(lane>=o) v+=t2; }
    if (lane==31) wred[wid]=v;
    __syncthreads();
    int woff=0;
    #pragma unroll
    for (int w=0;w<8;w++) if (w<wid) woff+=wred[w];
    int rank = v - tcnt + woff;
    int scnt=0;
    int selq[32];
    #pragma unroll
    for (int q=0;q<32;q++){
        unsigned k=keys[q];
        bool eq = (k==thr);
        int s = (k>thr) || (eq && rank < need);
        if (eq) rank++;
        selq[q]=s;
        g_sel[tid*32+q]=s;
        scnt+=s;
    }
    __syncthreads();
    v=scnt;
    #pragma unroll
    for (int o=1;o<32;o<<=1){ int t2=__shfl_up_sync(0xffffffffu,v,o); if(lane>=o) v+=t2; }
    if (lane==31) wred[wid]=v;
    __syncthreads();
    woff=0;
    #pragma unroll
    for (int w=0;w<8;w++) if (w<wid) woff+=wred[w];
    int base = v - scnt + woff;
    #pragma unroll
    for (int q=0;q<32;q++){
        int i = tid*32+q;
        if (selq[q]){ g_col[i]=base; g_ncol[base]=i; base++; }
        else g_col[i]=-1;
    }
}

__global__ void k_xp(const float* __restrict__ cx){
    int i = blockIdx.x, t = threadIdx.x;
    if (!g_sel[i]) return;
    g_xp[(size_t)g_col[i]*128 + t] = cx[(size_t)i*128 + t] * g_fit[i];
}

// ---------------- S CSR (by source): count + fill from dst rows ----------------
__global__ void k_scount(){
    int d = blockIdx.x*blockDim.x + threadIdx.x;
    if (d >= N_ || !g_sel[d]) return;
    int beg=g_rowptr[d], end=g_rowptr[d+1];
    for (int p=beg;p<end;p++) atomicAdd(&g_scnt[g_adj[p].x], 1);
}
__global__ void k_sfill(){
    int d = blockIdx.x*blockDim.x + threadIdx.x;
    if (d >= N_ || !g_sel[d]) return;
    int colk = g_col[d];
    int beg=g_rowptr[d], end=g_rowptr[d+1];
    for (int p=beg;p<end;p++){
        int s = g_adj[p].x;
        int pos = g_srowptr[s] + atomicAdd(&g_fill[s],1);
        g_sp[pos] = make_int2(colk, __float_as_int(g_alpha[p]));
    }
}

// ---------------- W = A*S (sparse rows): count, fill ----------------
__global__ void k_wcount(){
    int s = blockIdx.x*blockDim.x + threadIdx.x;
    if (s >= N_) return;
    int ob=g_orowptr[s], oe=g_orowptr[s+1];
    int total=0;
    for (int f=ob;f<oe;f++){
        int j = g_oadj[f];
        total += g_srowptr[j+1]-g_srowptr[j];
    }
    g_wcnt[s]=total;
}
// warp per source: copy S_j lists into W row
__global__ void k_wfill(){
    int s = blockIdx.x*8 + (threadIdx.x>>5);
    int lane = threadIdx.x & 31;
    int wpos = g_wrowptr[s];
    int ob=g_orowptr[s], oe=g_orowptr[s+1];
    for (int f=ob;f<oe;f++){
        int j = g_oadj[f];
        int sb=g_srowptr[j], len=g_srowptr[j+1]-sb;
        for (int q=lane;q<len;q+=32) g_W[wpos+q]=g_sp[sb+q];
        wpos += len;
    }
}

// ---------------- Ac row gather with smem fp32 accumulator -> fp16 store ----------------
__global__ void k_AcRow(){
    __shared__ __align__(16) float acc[K_];
    int k = blockIdx.x, tid = threadIdx.x;
    int lane = tid & 31, w = tid >> 5, nw = blockDim.x >> 5;
    {
        float4 z = make_float4(0,0,0,0);
        float4* a4 = (float4*)acc;
        #pragma unroll
        for (int m=0;m<2;m++) a4[tid + m*512] = z;
    }
    __syncthreads();
    int d = g_ncol[k];
    int ib = g_rowptr[d], ie = g_rowptr[d+1];
    for (int p=ib+w; p<ie; p+=nw){
        int s = g_adj[p].x;
        float ae = g_alpha[p];
        int wb = g_wrowptr[s], we = g_wrowptr[s+1];
        int q = wb + lane;
        for (; q+32 < we; q += 64){
            int2 e0 = g_W[q];
            int2 e1 = g_W[q+32];
            atomicAdd(&acc[e0.x], ae*__int_as_float(e0.y));
            atomicAdd(&acc[e1.x], ae*__int_as_float(e1.y));
        }
        if (q < we){
            int2 e0 = g_W[q];
            atomicAdd(&acc[e0.x], ae*__int_as_float(e0.y));
        }
    }
    __syncthreads();
    __half2* orow = (__half2*)(g_Ach + (size_t)k*K_);
    #pragma unroll
    for (int m=0;m<4;m++){
        int i2 = tid + m*512;
        orow[i2] = __floats2half2_rn(acc[2*i2], acc[2*i2+1]);
    }
}

// ---------------- fused: build 16 P-rows (fp32 acc -> fp16 smem), adj = P S^T ----------------
// 512 threads, 136KB smem. Ac read as half2 (coalesced). P layout: lo bytes [0,64K):
// uint4 per k = 4 half2 rowpairs 0-3 (rows 0-7); hi [64K,128K): rowpairs 4-7 (rows 8-15).
__global__ void __launch_bounds__(512, 1) k_adjF(float* __restrict__ adj){
    extern __shared__ __align__(16) char PshB[];
    int2* sc = (int2*)(PshB + 131072);
    int i0 = blockIdx.x*AR, tid = threadIdx.x;

    int qb0 = g_srowptr[i0];
    int qend = g_srowptr[i0+AR];
    int total = qend - qb0;
    int ncache = total < SCACHE ? total : SCACHE;
    for (int q=tid; q<ncache; q+=512) sc[q] = g_sp[qb0+q];
    __syncthreads();

    #pragma unroll 1
    for (int rp=0;rp<8;rp++){
        // per thread: 8 columns = {2*(tid+512m), 2*(tid+512m)+1}, m=0..3
        float accA[8], accB[8];
        #pragma unroll
        for (int m=0;m<8;m++){ accA[m]=0.f; accB[m]=0.f; }
        #pragma unroll 1
        for (int half_i=0; half_i<2; half_i++){
            int i = i0 + 2*rp + half_i;
            float* acc = half_i ? accB : accA;
            int qb=g_srowptr[i], qe=g_srowptr[i+1];
            if (qe - qb0 <= ncache){
                int base = qb - qb0, len = qe - qb;
                #pragma unroll 2
                for (int q=0;q<len;q++){
                    int2 kp = sc[base+q];
                    float a = __int_as_float(kp.y);
                    const __half2* row = (const __half2*)(g_Ach + (size_t)kp.x*K_);
                    #pragma unroll
                    for (int m=0;m<4;m++){
                        float2 f = __half22float2(row[tid + 512*m]);
                        acc[2*m]   += a*f.x;
                        acc[2*m+1] += a*f.y;
                    }
                }
            } else {
                for (int q=qb;q<qe;q++){
                    int2 kp = g_sp[q];
                    float a = __int_as_float(kp.y);
                    const __half2* row = (const __half2*)(g_Ach + (size_t)kp.x*K_);
                    #pragma unroll
                    for (int m=0;m<4;m++){
                        float2 f = __half22float2(row[tid + 512*m]);
                        acc[2*m]   += a*f.x;
                        acc[2*m+1] += a*f.y;
                    }
                }
            }
        }
        char* region = PshB + ((rp<4)? 0 : 65536);
        int woff = (rp & 3)*4;
        #pragma unroll
        for (int m=0;m<4;m++){
            int k0 = 2*(tid + 512*m);
            *(__half2*)(region + (size_t)k0*16 + woff)     = __floats2half2_rn(accA[2*m],   accB[2*m]);
            *(__half2*)(region + (size_t)(k0+1)*16 + woff) = __floats2half2_rn(accA[2*m+1], accB[2*m+1]);
        }
    }
    __syncthreads();
    for (int j=tid; j<N_; j+=512){
        float b[16];
        #pragma unroll
        for (int r=0;r<16;r++) b[r]=0.f;
        int qb = g_srowptr[j], qe = g_srowptr[j+1];
        for (int q=qb;q<qe;q++){
            int2 kp = g_sp[q];
            float a = __int_as_float(kp.y);
            uint4 lo = *(const uint4*)(PshB + (size_t)kp.x*16);
            uint4 hi = *(const uint4*)(PshB + 65536 + (size_t)kp.x*16);
            float2 f;
            f = __half22float2(*(__half2*)&lo.x); b[0] += a*f.x; b[1] += a*f.y;
            f = __half22float2(*(__half2*)&lo.y); b[2] += a*f.x; b[3] += a*f.y;
            f = __half22float2(*(__half2*)&lo.z); b[4] += a*f.x; b[5] += a*f.y;
            f = __half22float2(*(__half2*)&lo.w); b[6] += a*f.x; b[7] += a*f.y;
            f = __half22float2(*(__half2*)&hi.x); b[8] += a*f.x; b[9] += a*f.y;
            f = __half22float2(*(__half2*)&hi.y); b[10]+= a*f.x; b[11]+= a*f.y;
            f = __half22float2(*(__half2*)&hi.z); b[12]+= a*f.x; b[13]+= a*f.y;
            f = __half22float2(*(__half2*)&hi.w); b[14]+= a*f.x; b[15]+= a*f.y;
        }
        #pragma unroll
        for (int r=0;r<16;r++) adj[(size_t)(i0+r)*N_ + j] = b[r];
    }
}

// x_out[i,:] = sum over S row i: alpha*xp[k,:]  (warp per row, float4)
__global__ void k_xout(float* __restrict__ out){
    int i = blockIdx.x*8 + (threadIdx.x>>5);
    int lane = threadIdx.x & 31;
    const float4* xp4 = (const float4*)g_xp;
    float4 acc = make_float4(0,0,0,0);
    int beg=g_srowptr[i], end=g_srowptr[i+1];
    for (int q=beg;q<end;q++){
        int2 kp = g_sp[q];
        float a = __int_as_float(kp.y);
        float4 v = xp4[(size_t)kp.x*32 + lane];
        acc.x += a*v.x; acc.y += a*v.y; acc.z += a*v.z; acc.w += a*v.w;
    }
    ((float4*)out)[(size_t)i*32 + lane] = acc;
}

// ---------------- host ----------------
static cudaStream_t get_s2(){
    static cudaStream_t s = 0;
    if (!s) cudaStreamCreate(&s);
    return s;
}
static cudaEvent_t get_ev(int which){
    static cudaEvent_t ev[4] = {0,0,0,0};
    if (!ev[which]) cudaEventCreateWithFlags(&ev[which], cudaEventDisableTiming);
    return ev[which];
}

extern "C" void kernel_launch(void* const* d_in, const int* in_sizes, int n_in,
                              void* d_out, int out_size){
    const float* nodes = (const float*)d_in[0];
    const int*   edges = (const int*)d_in[1];
    const int* e0 = edges;
    const int* e1 = edges + E_;
    const float* w1 = (const float*)d_in[3];  const float* b1 = (const float*)d_in[4];
    const float* w2 = (const float*)d_in[5];  const float* b2 = (const float*)d_in[6];
    const float* w3 = (const float*)d_in[7];  const float* b3 = (const float*)d_in[8];
    const float* w4 = (const float*)d_in[9];  const float* b4 = (const float*)d_in[10];
    const float* w5 = (const float*)d_in[11]; const float* b5 = (const float*)d_in[12];
    const float* wq = (const float*)d_in[13]; const float* bq = (const float*)d_in[14];
    const float* att = (const float*)d_in[15];
    const float* lw1 = (const float*)d_in[16]; const float* lb1 = (const float*)d_in[17];
    const float* lw2 = (const float*)d_in[18]; const float* lw3 = (const float*)d_in[19];

    float* out = (float*)d_out;
    float* x2out = out;
    float* adj  = out + (size_t)N_*H_;

    float *A,*B,*C,*T; int *scnt,*srowptr,*wcnt,*wrowptr,*fill;
    cudaGetSymbolAddress((void**)&A, g_bufA);
    cudaGetSymbolAddress((void**)&B, g_bufB);
    cudaGetSymbolAddress((void**)&C, g_bufC);
    cudaGetSymbolAddress((void**)&T, g_bufT);
    cudaGetSymbolAddress((void**)&scnt, g_scnt);
    cudaGetSymbolAddress((void**)&srowptr, g_srowptr);
    cudaGetSymbolAddress((void**)&wcnt, g_wcnt);
    cudaGetSymbolAddress((void**)&wrowptr, g_wrowptr);
    cudaGetSymbolAddress((void**)&fill, g_fill);

    const int TB = 256;
    const int MB = (M_ + TB - 1)/TB;
    const int NB = (N_ + TB - 1)/TB;

    cudaStream_t s2 = get_s2();
    cudaEvent_t evF0 = get_ev(0), evJ0 = get_ev(1), evF1 = get_ev(2), evJ1 = get_ev(3);

    // fork 0: first gemm (depends only on inputs) overlaps graph prep
    cudaEventRecord(evF0, 0);
    cudaStreamWaitEvent(s2, evF0, 0);
    k_gemm<<<128,256,0,s2>>>(nodes, w1, T);
    cudaEventRecord(evJ0, s2);

    // graph prep: dst-CSR + src-CSR with folded norms (main stream)
    k_init0<<<NB, TB>>>();
    k_count<<<MB, TB>>>(e0, e1);
    k_scan2<<<2,1024>>>();
    k_fill<<<MB, TB>>>(e0, e1);

    // encoder (needs gemm1 result)
    cudaStreamWaitEvent(0, evJ0, 0);
    k_aggr<<<N_/8,256>>>(T, b1, A, 1);
    k_gemm<<<128,256>>>(A, w2, T);
    k_aggr<<<N_/8,256>>>(T, b2, B, 1);       // B = h

    // pooling
    k_segmax<<<N_/8,256>>>(B, A);
    k_gemm<<<128,256>>>(A, wq, T);
    k_dots<<<N_/8,256>>>(T, B, att, bq);
    k_softcx<<<N_,128>>>(B, C, lw1, lw2, lw3);  // cx + alpha + fused LEConv dots
    k_fit<<<NB, TB>>>(lb1);
    k_topk<<<1,256>>>();
    k_xp<<<N_,128>>>(C);

    // S CSR (by source)
    k_scount<<<NB, TB>>>();
    k_scan8192<<<1,1024>>>(scnt, srowptr);
    k_zeroN<<<NB, TB>>>(fill);
    k_sfill<<<NB, TB>>>();

    // fork 1: decoder branch (s2) overlaps W-build + AcRow + adjF (main)
    cudaEventRecord(evF1, 0);
    cudaStreamWaitEvent(s2, evF1, 0);
    k_xout<<<N_/8,256,0,s2>>>(A);            // A = x_out
    k_gemm<<<128,256,0,s2>>>(A, w3, T);
    k_aggr<<<N_/8,256,0,s2>>>(T, b3, B, 1);
    k_gemm<<<128,256,0,s2>>>(B, w4, T);
    k_aggr<<<N_/8,256,0,s2>>>(T, b4, A, 1);
    k_gemm<<<128,256,0,s2>>>(A, w5, T);
    k_aggr<<<N_/8,256,0,s2>>>(T, b5, x2out, 0);
    cudaEventRecord(evJ1, s2);

    // main: W = A*S sparse rows, Ac (fp16), adj
    k_wcount<<<NB, TB>>>();
    k_scan8192<<<1,1024>>>(wcnt, wrowptr);
    k_wfill<<<N_/8, 256>>>();
    k_AcRow<<<K_, 512>>>();
    cudaFuncSetAttribute(k_adjF, cudaFuncAttributeMaxDynamicSharedMemorySize, PSH_TOTAL);
    k_adjF<<<N_/AR, 512, PSH_TOTAL>>>(adj);

    // join decoder branch
    cudaStreamWaitEvent(0, evJ1, 0);
}

// round 12
// speedup vs baseline: 1.2902x; 1.0509x over previous
#include <cuda_runtime.h>
#include <cuda_fp16.h>
#include <math.h>
#include <stdint.h>

#define N_ 8192
#define E_ 131072
#define M_ (E_ + N_)          // 139264 edges incl self loops
#define H_ 128
#define K_ 4096
#define WCAP_ 3000000

#define AR 16                 // rows per adjF block
#define SCACHE 1024
#define PSH_TOTAL (131072 + SCACHE*8)   // 128KB fp16 P (16 rows x 4096 k) + 8KB S cache

// ---------------- device scratch ----------------
static __device__ float g_bufA[(size_t)N_*H_];
static __device__ float g_bufB[(size_t)N_*H_];
static __device__ float g_bufC[(size_t)N_*H_];
static __device__ float g_bufT[(size_t)N_*H_];
static __device__ int   g_cnt[N_];
static __device__ int   g_ocnt[N_];
static __device__ int   g_fill[N_];
static __device__ int   g_ofill[N_];
static __device__ int   g_rowptr[N_+1];     // CSR by dst
static __device__ int   g_orowptr[N_+1];    // CSR by src
static __device__ int2  g_adj[M_];          // per dst-CSR pos: (src, norm bits)
static __device__ int   g_oadj[M_];         // per src-CSR pos: dst
static __device__ float g_alpha[M_];        // per dst-CSR pos
static __device__ float g_aq[N_];
static __device__ float g_ah[N_];
static __device__ float g_cl1[N_], g_cl2[N_], g_cl3[N_];
static __device__ float g_fit[N_];
static __device__ int   g_sel[N_];
static __device__ int   g_col[N_];
static __device__ int   g_ncol[K_];
static __device__ float g_xp[(size_t)K_*H_];
static __device__ int   g_scnt[N_];
static __device__ int   g_srowptr[N_+1];
static __device__ int2  g_sp[M_];            // packed (col k, alpha bits), CSR by src
static __device__ int   g_wcnt[N_];
static __device__ int   g_wrowptr[N_+1];
static __device__ int2  g_W[WCAP_];          // W = A*S rows
static __device__ __half g_Ach[(size_t)K_*K_];   // Ac in fp16 (32MB, L2-resident)

// ---------------- helpers ----------------
__device__ __forceinline__ int esrc_f(const int* __restrict__ e0, int e){ return (e < E_) ? e0[e] : (e - E_); }
__device__ __forceinline__ int edst_f(const int* __restrict__ e1, int e){ return (e < E_) ? e1[e] : (e - E_); }

// ---------------- small utility kernels ----------------
__global__ void k_init0(){
    int i = blockIdx.x*blockDim.x + threadIdx.x;
    if (i < N_){ g_cnt[i]=0; g_ocnt[i]=0; g_fill[i]=0; g_ofill[i]=0; g_scnt[i]=0; }
}
__global__ void k_count(const int* __restrict__ e0, const int* __restrict__ e1){
    int e = blockIdx.x*blockDim.x + threadIdx.x;
    if (e < M_){
        atomicAdd(&g_cnt[edst_f(e1,e)], 1);
        atomicAdd(&g_ocnt[esrc_f(e0,e)], 1);
    }
}
// exclusive scan of exactly 8192 ints with 1024 threads (shfl-based)
__device__ __forceinline__ void scan8192_body(const int* __restrict__ in, int* __restrict__ out){
    __shared__ int wsum[32];
    int tid=threadIdx.x, lane=tid&31, wid=tid>>5;
    int4 a=((const int4*)in)[tid*2], b=((const int4*)in)[tid*2+1];
    int l[8]={a.x,a.y,a.z,a.w,b.x,b.y,b.z,b.w};
    int s=0;
    #pragma unroll
    for(int q=0;q<8;q++) s+=l[q];
    int inc=s;
    #pragma unroll
    for(int o=1;o<32;o<<=1){ int t=__shfl_up_sync(0xffffffffu,inc,o); if(lane>=o) inc+=t; }
    if(lane==31) wsum[wid]=inc;
    __syncthreads();
    if (wid==0){
        int v = wsum[lane];
        #pragma unroll
        for(int o=1;o<32;o<<=1){ int t=__shfl_up_sync(0xffffffffu,v,o); if(lane>=o) v+=t; }
        wsum[lane]=v;
    }
    __syncthreads();
    int r = inc - s + (wid? wsum[wid-1]:0);
    int4 o1,o2;
    o1.x=r; r+=l[0]; o1.y=r; r+=l[1]; o1.z=r; r+=l[2]; o1.w=r; r+=l[3];
    o2.x=r; r+=l[4]; o2.y=r; r+=l[5]; o2.z=r; r+=l[6]; o2.w=r; r+=l[7];
    ((int4*)out)[tid*2]=o1; ((int4*)out)[tid*2+1]=o2;
    if (tid==1023) out[8192]=r;
}
__global__ void k_scan8192(const int* __restrict__ in, int* __restrict__ out){
    scan8192_body(in, out);
}
__global__ void k_scan2(){
    if (blockIdx.x == 0) scan8192_body(g_cnt, g_rowptr);
    else                 scan8192_body(g_ocnt, g_orowptr);
}
// build positional adjacency with folded norm (dis computed inline)
__global__ void k_fill(const int* __restrict__ e0, const int* __restrict__ e1){
    int e = blockIdx.x*blockDim.x + threadIdx.x;
    if (e < M_){
        int s = esrc_f(e0,e);
        int d = edst_f(e1,e);
        float nm = rsqrtf((float)g_cnt[s]) * rsqrtf((float)g_cnt[d]);
        int pos = g_rowptr[d] + atomicAdd(&g_fill[d],1);
        g_adj[pos] = make_int2(s, __float_as_int(nm));
        int opos = g_orowptr[s] + atomicAdd(&g_ofill[s],1);
        g_oadj[opos] = d;
    }
}

// ---------------- 8192x128 @ 128x128 GEMM ----------------
__global__ void k_gemm(const float* __restrict__ x, const float* __restrict__ w, float* __restrict__ y){
    __shared__ __align__(16) float xs[128*64];   // [kk][r]
    int r0 = blockIdx.x*64;
    int tid = threadIdx.x;
    for (int idx=tid; idx<64*128; idx+=256){
        int r = idx >> 7;
        int kk = idx & 127;
        xs[kk*64 + r] = x[(size_t)(r0+r)*128 + kk];
    }
    __syncthreads();
    int cg = tid & 31;
    int rg = tid >> 5;
    float acc[8][4];
    #pragma unroll
    for(int r=0;r<8;r++){ acc[r][0]=0.f;acc[r][1]=0.f;acc[r][2]=0.f;acc[r][3]=0.f; }
    #pragma unroll 4
    for(int kk=0;kk<128;kk++){
        float4 wv = *(const float4*)(w + kk*128 + cg*4);
        float4 x0 = *(const float4*)(xs + kk*64 + rg*8);
        float4 x1 = *(const float4*)(xs + kk*64 + rg*8 + 4);
        float xv[8] = {x0.x,x0.y,x0.z,x0.w,x1.x,x1.y,x1.z,x1.w};
        #pragma unroll
        for(int r=0;r<8;r++){
            acc[r][0] += xv[r]*wv.x; acc[r][1] += xv[r]*wv.y;
            acc[r][2] += xv[r]*wv.z; acc[r][3] += xv[r]*wv.w;
        }
    }
    #pragma unroll
    for(int r=0;r<8;r++){
        float4 o = make_float4(acc[r][0],acc[r][1],acc[r][2],acc[r][3]);
        *(float4*)(y + (size_t)(r0+rg*8+r)*128 + cg*4) = o;
    }
}

// ---------------- GCN aggregation: warp per dst, float4 lanes ----------------
__global__ void k_aggr(const float* __restrict__ y, const float* __restrict__ b,
                       float* __restrict__ out, int dotanh){
    int d = blockIdx.x*8 + (threadIdx.x>>5);
    int lane = threadIdx.x & 31;
    const float4* y4 = (const float4*)y;
    float4 acc = ((const float4*)b)[lane];
    int beg = g_rowptr[d], end = g_rowptr[d+1];
    int p = beg;
    for (; p+1 < end; p += 2){
        int2 a0 = g_adj[p], a1 = g_adj[p+1];
        float n0 = __int_as_float(a0.y), n1 = __int_as_float(a1.y);
        float4 v0 = y4[(size_t)a0.x*32 + lane];
        float4 v1 = y4[(size_t)a1.x*32 + lane];
        acc.x += n0*v0.x + n1*v1.x;
        acc.y += n0*v0.y + n1*v1.y;
        acc.z += n0*v0.z + n1*v1.z;
        acc.w += n0*v0.w + n1*v1.w;
    }
    if (p < end){
        int2 a0 = g_adj[p];
        float n0 = __int_as_float(a0.y);
        float4 v0 = y4[(size_t)a0.x*32 + lane];
        acc.x += n0*v0.x; acc.y += n0*v0.y; acc.z += n0*v0.z; acc.w += n0*v0.w;
    }
    if (dotanh){
        acc.x = tanhf(acc.x); acc.y = tanhf(acc.y);
        acc.z = tanhf(acc.z); acc.w = tanhf(acc.w);
    }
    ((float4*)out)[(size_t)d*32 + lane] = acc;
}

__global__ void k_segmax(const float* __restrict__ h, float* __restrict__ out){
    int d = blockIdx.x*8 + (threadIdx.x>>5);
    int lane = threadIdx.x & 31;
    const float4* h4 = (const float4*)h;
    float4 acc = make_float4(-INFINITY,-INFINITY,-INFINITY,-INFINITY);
    int beg = g_rowptr[d], end = g_rowptr[d+1];
    for (int p=beg; p<end; p++){
        float4 v = h4[(size_t)g_adj[p].x*32 + lane];
        acc.x = fmaxf(acc.x,v.x); acc.y = fmaxf(acc.y,v.y);
        acc.z = fmaxf(acc.z,v.z); acc.w = fmaxf(acc.w,v.w);
    }
    ((float4*)out)[(size_t)d*32 + lane] = acc;
}

__global__ void k_dots(const float* __restrict__ xq, const float* __restrict__ h,
                       const float* __restrict__ att, const float* __restrict__ bq){
    int node = blockIdx.x*8 + (threadIdx.x>>5);
    int lane = threadIdx.x & 31;
    const float4* xq4 = (const float4*)xq;
    const float4* h4  = (const float4*)h;
    const float4* at4 = (const float4*)att;
    const float4* bq4 = (const float4*)bq;
    float4 a1 = at4[lane], a2 = at4[32+lane];
    float4 xv = xq4[(size_t)node*32+lane], bv = bq4[lane], hv = h4[(size_t)node*32+lane];
    float s1 = a1.x*(xv.x+bv.x) + a1.y*(xv.y+bv.y) + a1.z*(xv.z+bv.z) + a1.w*(xv.w+bv.w);
    float s2 = a2.x*hv.x + a2.y*hv.y + a2.z*hv.z + a2.w*hv.w;
    #pragma unroll
    for (int o=16;o;o>>=1){ s1 += __shfl_down_sync(0xffffffffu,s1,o); s2 += __shfl_down_sync(0xffffffffu,s2,o); }
    if (!lane){ g_aq[node]=s1; g_ah[node]=s2; }
}

// per-dst softmax over in-edges + cluster rep cx + fused LEConv dots
__global__ void k_softcx(const float* __restrict__ h, float* __restrict__ cx,
                         const float* __restrict__ lw1, const float* __restrict__ lw2,
                         const float* __restrict__ lw3){
    __shared__ float red[128];
    __shared__ float cache[1024];
    __shared__ int   scache[1024];
    int d = blockIdx.x, t = threadIdx.x;
    int beg = g_rowptr[d], end = g_rowptr[d+1];
    float aqd = g_aq[d];
    float mx = -INFINITY;
    for (int s=beg+t; s<end; s+=128){
        int src = g_adj[s].x;
        float sc = aqd + g_ah[src];
        sc = sc > 0.f ? sc : 0.2f*sc;
        if (s-beg < 1024){ cache[s-beg] = sc; scache[s-beg] = src; }
        mx = fmaxf(mx, sc);
    }
    red[t]=mx; __syncthreads();
    for (int o=64;o;o>>=1){ if(t<o) red[t]=fmaxf(red[t],red[t+o]); __syncthreads(); }
    mx = red[0]; __syncthreads();
    float sm = 0.f;
    for (int s=beg+t; s<end; s+=128){
        float sc;
        if (s-beg < 1024) sc = cache[s-beg];
        else { float v = aqd + g_ah[g_adj[s].x]; sc = v>0.f? v : 0.2f*v; }
        float ee = __expf(sc - mx);
        if (s-beg < 1024) cache[s-beg] = ee;
        sm += ee;
    }
    red[t]=sm; __syncthreads();
    for (int o=64;o;o>>=1){ if(t<o) red[t]+=red[t+o]; __syncthreads(); }
    float inv = 1.f/red[0];
    for (int s=beg+t; s<end; s+=128){
        float ee;
        if (s-beg < 1024) ee = cache[s-beg];
        else { float v = aqd + g_ah[g_adj[s].x]; v = v>0.f? v:0.2f*v; ee = __expf(v-mx); }
        float a = ee*inv;
        g_alpha[s] = a;
        if (s-beg < 1024) cache[s-beg] = a;
    }
    __syncthreads();
    float acc = 0.f;
    for (int s=beg; s<end; s++){
        float a; int src;
        if (s-beg < 1024){ a = cache[s-beg]; src = scache[s-beg]; }
        else { a = g_alpha[s]; src = g_adj[s].x; }
        acc += a * h[(size_t)src*128 + t];
    }
    cx[(size_t)d*128 + t] = acc;
    __syncthreads();
    red[t] = acc*lw1[t]; __syncthreads();
    for (int o=64;o;o>>=1){ if(t<o) red[t]+=red[t+o]; __syncthreads(); }
    if (!t) g_cl1[d]=red[0];
    __syncthreads();
    red[t] = acc*lw2[t]; __syncthreads();
    for (int o=64;o;o>>=1){ if(t<o) red[t]+=red[t+o]; __syncthreads(); }
    if (!t) g_cl2[d]=red[0];
    __syncthreads();
    red[t] = acc*lw3[t]; __syncthreads();
    for (int o=64;o;o>>=1){ if(t<o) red[t]+=red[t+o]; __syncthreads(); }
    if (!t) g_cl3[d]=red[0];
}

__global__ void k_fit(const float* __restrict__ lb1){
    int d = blockIdx.x*blockDim.x + threadIdx.x;
    if (d >= N_) return;
    int beg=g_rowptr[d], end=g_rowptr[d+1];
    float s = 0.f;
    for (int q=beg;q<end;q++) s += g_cl3[g_adj[q].x];
    float aggr = (float)(end-beg)*g_cl2[d] - s;
    float z = g_cl1[d] + lb1[0] + aggr;
    g_fit[d] = 1.f/(1.f + __expf(-z));
}

// ---------------- top-K via 4x8-bit histogram radix select ----------------
__global__ void k_topk(){
    __shared__ int hist[256];
    __shared__ int wred[8];
    __shared__ unsigned s_pref;
    __shared__ int s_need;
    int tid=threadIdx.x, lane=tid&31, wid=tid>>5;
    if (tid==0){ s_pref=0u; s_need=K_; }
    unsigned keys[32];
    #pragma unroll
    for (int q=0;q<32;q++){
        unsigned u=__float_as_uint(g_fit[tid*32+q]);
        keys[q] = (u & 0x80000000u) ? ~u : (u | 0x80000000u);
    }
    __syncthreads();
    for (int round=0; round<4; round++){
        int shift = 24 - 8*round;
        hist[tid]=0;
        __syncthreads();
        unsigned pref = s_pref;
        #pragma unroll
        for (int q=0;q<32;q++){
            unsigned k = keys[q];
            bool match = (round==0) || ((k >> (shift+8)) == (pref >> (shift+8)));
            if (match) atomicAdd(&hist[(k>>shift)&0xFFu], 1);
        }
        __syncthreads();
        int mine = hist[255-tid];
        int v = mine;
        #pragma unroll
        for (int o=1;o<32;o<<=1){ int t2=__shfl_up_sync(0xffffffffu,v,o); if(lane>=o) v+=t2; }
        if (lane==31) wred[wid]=v;
        __syncthreads();
        int woff=0;
        #pragma unroll
        for (int w=0;w<8;w++) if (w<wid) woff+=wred[w];
        v += woff;
        int need0 = s_need;
        int vex = v - mine;
        if (v >= need0 && vex < need0){
            s_pref = s_pref | ((unsigned)(255-tid) << shift);
            s_need = need0 - vex;
        }
        __syncthreads();
    }
    unsigned thr = s_pref;
    int need = s_need;
    int tcnt=0;
    #pragma unroll
    for (int q=0;q<32;q++) tcnt += (keys[q]==thr);
    int v=tcnt;
    #pragma unroll
    for (int o=1;o<32;o<<=1){ int t2=__shfl_up_sync(0xffffffffu,v,o); if(lane>=o) v+=t2; }
    if (lane==31) wred[wid]=v;
    __syncthreads();
    int woff=0;
    #pragma unroll
    for (int w=0;w<8;w++) if (w<wid) woff+=wred[w];
    int rank = v - tcnt + woff;
    int scnt=0;
    int selq[32];
    #pragma unroll
    for (int q=0;q<32;q++){
        unsigned k=keys[q];
        bool eq = (k==thr);
        int s = (k>thr) || (eq && rank < need);
        if (eq) rank++;
        selq[q]=s;
        g_sel[tid*32+q]=s;
        scnt+=s;
    }
    __syncthreads();
    v=scnt;
    #pragma unroll
    for (int o=1;o<32;o<<=1){ int t2=__shfl_up_sync(0xffffffffu,v,o); if(lane>=o) v+=t2; }
    if (lane==31) wred[wid]=v;
    __syncthreads();
    woff=0;
    #pragma unroll
    for (int w=0;w<8;w++) if (w<wid) woff+=wred[w];
    int base = v - scnt + woff;
    #pragma unroll
    for (int q=0;q<32;q++){
        int i = tid*32+q;
        if (selq[q]){ g_col[i]=base; g_ncol[base]=i; base++; }
        else g_col[i]=-1;
    }
}

// ---------------- S CSR count (+ g_fill reset folded in) ----------------
__global__ void k_scount(){
    int d = blockIdx.x*blockDim.x + threadIdx.x;
    if (d >= N_) return;
    g_fill[d]=0;
    if (!g_sel[d]) return;
    int beg=g_rowptr[d], end=g_rowptr[d+1];
    for (int p=beg;p<end;p++) atomicAdd(&g_scnt[g_adj[p].x], 1);
}
// merged xp write + sfill scatter: block per dst, 128 threads
__global__ void k_xpsfill(const float* __restrict__ cx){
    int d = blockIdx.x, t = threadIdx.x;
    if (!g_sel[d]) return;
    int colk = g_col[d];
    g_xp[(size_t)colk*128 + t] = cx[(size_t)d*128 + t] * g_fit[d];
    int beg=g_rowptr[d], end=g_rowptr[d+1];
    for (int p=beg+t; p<end; p+=128){
        int s = g_adj[p].x;
        int pos = g_srowptr[s] + atomicAdd(&g_fill[s],1);
        g_sp[pos] = make_int2(colk, __float_as_int(g_alpha[p]));
    }
}

// ---------------- W = A*S (sparse rows): count, fill ----------------
__global__ void k_wcount(){
    int s = blockIdx.x*blockDim.x + threadIdx.x;
    if (s >= N_) return;
    int ob=g_orowptr[s], oe=g_orowptr[s+1];
    int total=0;
    for (int f=ob;f<oe;f++){
        int j = g_oadj[f];
        total += g_srowptr[j+1]-g_srowptr[j];
    }
    g_wcnt[s]=total;
}
// warp per source: copy S_j lists into W row
__global__ void k_wfill(){
    int s = blockIdx.x*8 + (threadIdx.x>>5);
    int lane = threadIdx.x & 31;
    int wpos = g_wrowptr[s];
    int ob=g_orowptr[s], oe=g_orowptr[s+1];
    for (int f=ob;f<oe;f++){
        int j = g_oadj[f];
        int sb=g_srowptr[j], len=g_srowptr[j+1]-sb;
        for (int q=lane;q<len;q+=32) g_W[wpos+q]=g_sp[sb+q];
        wpos += len;
    }
}

// ---------------- Ac row gather with smem fp32 accumulator -> fp16 store ----------------
__global__ void k_AcRow(){
    __shared__ __align__(16) float acc[K_];
    int k = blockIdx.x, tid = threadIdx.x;
    int lane = tid & 31, w = tid >> 5, nw = blockDim.x >> 5;
    {
        float4 z = make_float4(0,0,0,0);
        float4* a4 = (float4*)acc;
        #pragma unroll
        for (int m=0;m<2;m++) a4[tid + m*512] = z;
    }
    __syncthreads();
    int d = g_ncol[k];
    int ib = g_rowptr[d], ie = g_rowptr[d+1];
    for (int p=ib+w; p<ie; p+=nw){
        int s = g_adj[p].x;
        float ae = g_alpha[p];
        int wb = g_wrowptr[s], we = g_wrowptr[s+1];
        int q = wb + lane;
        for (; q+32 < we; q += 64){
            int2 e0 = g_W[q];
            int2 e1 = g_W[q+32];
            atomicAdd(&acc[e0.x], ae*__int_as_float(e0.y));
            atomicAdd(&acc[e1.x], ae*__int_as_float(e1.y));
        }
        if (q < we){
            int2 e0 = g_W[q];
            atomicAdd(&acc[e0.x], ae*__int_as_float(e0.y));
        }
    }
    __syncthreads();
    __half2* orow = (__half2*)(g_Ach + (size_t)k*K_);
    #pragma unroll
    for (int m=0;m<4;m++){
        int i2 = tid + m*512;
        orow[i2] = __floats2half2_rn(acc[2*i2], acc[2*i2+1]);
    }
}

// ---------------- fused: build 16 P-rows (fp32 acc -> fp16 smem), adj = P S^T ----------------
// 1024 threads, 136KB smem. Ac read as half2 (coalesced). P layout: lo bytes [0,64K):
// uint4 per k = 4 half2 rowpairs 0-3 (rows 0-7); hi [64K,128K): rowpairs 4-7 (rows 8-15).
__global__ void __launch_bounds__(1024, 1) k_adjF(float* __restrict__ adj){
    extern __shared__ __align__(16) char PshB[];
    int2* sc = (int2*)(PshB + 131072);
    int i0 = blockIdx.x*AR, tid = threadIdx.x;

    int qb0 = g_srowptr[i0];
    int qend = g_srowptr[i0+AR];
    int total = qend - qb0;
    int ncache = total < SCACHE ? total : SCACHE;
    for (int q=tid; q<ncache; q+=1024) sc[q] = g_sp[qb0+q];
    __syncthreads();

    #pragma unroll 1
    for (int rp=0;rp<8;rp++){
        // per thread: 4 columns = {2*(tid+1024m), 2*(tid+1024m)+1}, m=0..1
        float accA[4], accB[4];
        #pragma unroll
        for (int m=0;m<4;m++){ accA[m]=0.f; accB[m]=0.f; }
        #pragma unroll 1
        for (int half_i=0; half_i<2; half_i++){
            int i = i0 + 2*rp + half_i;
            float* acc = half_i ? accB : accA;
            int qb=g_srowptr[i], qe=g_srowptr[i+1];
            if (qe - qb0 <= ncache){
                int base = qb - qb0, len = qe - qb;
                #pragma unroll 2
                for (int q=0;q<len;q++){
                    int2 kp = sc[base+q];
                    float a = __int_as_float(kp.y);
                    const __half2* row = (const __half2*)(g_Ach + (size_t)kp.x*K_);
                    #pragma unroll
                    for (int m=0;m<2;m++){
                        float2 f = __half22float2(row[tid + 1024*m]);
                        acc[2*m]   += a*f.x;
                        acc[2*m+1] += a*f.y;
                    }
                }
            } else {
                for (int q=qb;q<qe;q++){
                    int2 kp = g_sp[q];
                    float a = __int_as_float(kp.y);
                    const __half2* row = (const __half2*)(g_Ach + (size_t)kp.x*K_);
                    #pragma unroll
                    for (int m=0;m<2;m++){
                        float2 f = __half22float2(row[tid + 1024*m]);
                        acc[2*m]   += a*f.x;
                        acc[2*m+1] += a*f.y;
                    }
                }
            }
        }
        char* region = PshB + ((rp<4)? 0 : 65536);
        int woff = (rp & 3)*4;
        #pragma unroll
        for (int m=0;m<2;m++){
            int k0 = 2*(tid + 1024*m);
            *(__half2*)(region + (size_t)k0*16 + woff)     = __floats2half2_rn(accA[2*m],   accB[2*m]);
            *(__half2*)(region + (size_t)(k0+1)*16 + woff) = __floats2half2_rn(accA[2*m+1], accB[2*m+1]);
        }
    }
    __syncthreads();
    for (int j=tid; j<N_; j+=1024){
        float b[16];
        #pragma unroll
        for (int r=0;r<16;r++) b[r]=0.f;
        int qb = g_srowptr[j], qe = g_srowptr[j+1];
        for (int q=qb;q<qe;q++){
            int2 kp = g_sp[q];
            float a = __int_as_float(kp.y);
            uint4 lo = *(const uint4*)(PshB + (size_t)kp.x*16);
            uint4 hi = *(const uint4*)(PshB + 65536 + (size_t)kp.x*16);
            float2 f;
            f = __half22float2(*(__half2*)&lo.x); b[0] += a*f.x; b[1] += a*f.y;
            f = __half22float2(*(__half2*)&lo.y); b[2] += a*f.x; b[3] += a*f.y;
            f = __half22float2(*(__half2*)&lo.z); b[4] += a*f.x; b[5] += a*f.y;
            f = __half22float2(*(__half2*)&lo.w); b[6] += a*f.x; b[7] += a*f.y;
            f = __half22float2(*(__half2*)&hi.x); b[8] += a*f.x; b[9] += a*f.y;
            f = __half22float2(*(__half2*)&hi.y); b[10]+= a*f.x; b[11]+= a*f.y;
            f = __half22float2(*(__half2*)&hi.z); b[12]+= a*f.x; b[13]+= a*f.y;
            f = __half22float2(*(__half2*)&hi.w); b[14]+= a*f.x; b[15]+= a*f.y;
        }
        #pragma unroll
        for (int r=0;r<16;r++) adj[(size_t)(i0+r)*N_ + j] = b[r];
    }
}

// x_out[i,:] = sum over S row i: alpha*xp[k,:]  (warp per row, float4)
__global__ void k_xout(float* __restrict__ out){
    int i = blockIdx.x*8 + (threadIdx.x>>5);
    int lane = threadIdx.x & 31;
    const float4* xp4 = (const float4*)g_xp;
    float4 acc = make_float4(0,0,0,0);
    int beg=g_srowptr[i], end=g_srowptr[i+1];
    for (int q=beg;q<end;q++){
        int2 kp = g_sp[q];
        float a = __int_as_float(kp.y);
        float4 v = xp4[(size_t)kp.x*32 + lane];
        acc.x += a*v.x; acc.y += a*v.y; acc.z += a*v.z; acc.w += a*v.w;
    }
    ((float4*)out)[(size_t)i*32 + lane] = acc;
}

// ---------------- host ----------------
static cudaStream_t get_s2(){
    static cudaStream_t s = 0;
    if (!s) cudaStreamCreate(&s);
    return s;
}
static cudaEvent_t get_ev(int which){
    static cudaEvent_t ev[4] = {0,0,0,0};
    if (!ev[which]) cudaEventCreateWithFlags(&ev[which], cudaEventDisableTiming);
    return ev[which];
}

extern "C" void kernel_launch(void* const* d_in, const int* in_sizes, int n_in,
                              void* d_out, int out_size){
    const float* nodes = (const float*)d_in[0];
    const int*   edges = (const int*)d_in[1];
    const int* e0 = edges;
    const int* e1 = edges + E_;
    const float* w1 = (const float*)d_in[3];  const float* b1 = (const float*)d_in[4];
    const float* w2 = (const float*)d_in[5];  const float* b2 = (const float*)d_in[6];
    const float* w3 = (const float*)d_in[7];  const float* b3 = (const float*)d_in[8];
    const float* w4 = (const float*)d_in[9];  const float* b4 = (const float*)d_in[10];
    const float* w5 = (const float*)d_in[11]; const float* b5 = (const float*)d_in[12];
    const float* wq = (const float*)d_in[13]; const float* bq = (const float*)d_in[14];
    const float* att = (const float*)d_in[15];
    const float* lw1 = (const float*)d_in[16]; const float* lb1 = (const float*)d_in[17];
    const float* lw2 = (const float*)d_in[18]; const float* lw3 = (const float*)d_in[19];

    float* out = (float*)d_out;
    float* x2out = out;
    float* adj  = out + (size_t)N_*H_;

    float *A,*B,*C,*T; int *scnt,*srowptr,*wcnt,*wrowptr;
    cudaGetSymbolAddress((void**)&A, g_bufA);
    cudaGetSymbolAddress((void**)&B, g_bufB);
    cudaGetSymbolAddress((void**)&C, g_bufC);
    cudaGetSymbolAddress((void**)&T, g_bufT);
    cudaGetSymbolAddress((void**)&scnt, g_scnt);
    cudaGetSymbolAddress((void**)&srowptr, g_srowptr);
    cudaGetSymbolAddress((void**)&wcnt, g_wcnt);
    cudaGetSymbolAddress((void**)&wrowptr, g_wrowptr);

    const int TB = 256;
    const int MB = (M_ + TB - 1)/TB;
    const int NB = (N_ + TB - 1)/TB;

    cudaStream_t s2 = get_s2();
    cudaEvent_t evF0 = get_ev(0), evJ0 = get_ev(1), evF1 = get_ev(2), evJ1 = get_ev(3);

    // fork 0: first gemm (depends only on inputs) overlaps graph prep
    cudaEventRecord(evF0, 0);
    cudaStreamWaitEvent(s2, evF0, 0);
    k_gemm<<<128,256,0,s2>>>(nodes, w1, T);
    cudaEventRecord(evJ0, s2);

    // graph prep: dst-CSR + src-CSR with folded norms (main stream)
    k_init0<<<NB, TB>>>();
    k_count<<<MB, TB>>>(e0, e1);
    k_scan2<<<2,1024>>>();
    k_fill<<<MB, TB>>>(e0, e1);

    // encoder (needs gemm1 result)
    cudaStreamWaitEvent(0, evJ0, 0);
    k_aggr<<<N_/8,256>>>(T, b1, A, 1);
    k_gemm<<<128,256>>>(A, w2, T);
    k_aggr<<<N_/8,256>>>(T, b2, B, 1);       // B = h

    // pooling
    k_segmax<<<N_/8,256>>>(B, A);
    k_gemm<<<128,256>>>(A, wq, T);
    k_dots<<<N_/8,256>>>(T, B, att, bq);
    k_softcx<<<N_,128>>>(B, C, lw1, lw2, lw3);  // cx + alpha + fused LEConv dots
    k_fit<<<NB, TB>>>(lb1);
    k_topk<<<1,256>>>();

    // S CSR (by source); scount also resets g_fill
    k_scount<<<NB, TB>>>();
    k_scan8192<<<1,1024>>>(scnt, srowptr);
    k_xpsfill<<<N_,128>>>(C);

    // fork 1: decoder branch (s2) overlaps W-build + AcRow + adjF (main)
    cudaEventRecord(evF1, 0);
    cudaStreamWaitEvent(s2, evF1, 0);
    k_xout<<<N_/8,256,0,s2>>>(A);            // A = x_out
    k_gemm<<<128,256,0,s2>>>(A, w3, T);
    k_aggr<<<N_/8,256,0,s2>>>(T, b3, B, 1);
    k_gemm<<<128,256,0,s2>>>(B, w4, T);
    k_aggr<<<N_/8,256,0,s2>>>(T, b4, A, 1);
    k_gemm<<<128,256,0,s2>>>(A, w5, T);
    k_aggr<<<N_/8,256,0,s2>>>(T, b5, x2out, 0);
    cudaEventRecord(evJ1, s2);

    // main: W = A*S sparse rows, Ac (fp16), adj
    k_wcount<<<NB, TB>>>();
    k_scan8192<<<1,1024>>>(wcnt, wrowptr);
    k_wfill<<<N_/8, 256>>>();
    k_AcRow<<<K_, 512>>>();
    cudaFuncSetAttribute(k_adjF, cudaFuncAttributeMaxDynamicSharedMemorySize, PSH_TOTAL);
    k_adjF<<<N_/AR, 1024, PSH_TOTAL>>>(adj);

    // join decoder branch
    cudaStreamWaitEvent(0, evJ1, 0);
}

// round 13
// speedup vs baseline: 1.3498x; 1.0462x over previous
#include <cuda_runtime.h>
#include <cuda_fp16.h>
#include <math.h>
#include <stdint.h>

#define N_ 8192
#define E_ 131072
#define M_ (E_ + N_)          // 139264 edges incl self loops
#define H_ 128
#define K_ 4096
#define WCAP_ 3000000

#define AR 16                 // rows per adjF block
#define SCACHE 1024
#define PSH_TOTAL (131072 + SCACHE*8)   // 128KB fp16 P (16 rows x 4096 k) + 8KB S cache

// ---------------- device scratch ----------------
static __device__ float g_bufA[(size_t)N_*H_];
static __device__ float g_bufB[(size_t)N_*H_];
static __device__ float g_bufC[(size_t)N_*H_];
static __device__ float g_bufT[(size_t)N_*H_];
static __device__ int   g_cnt[N_];
static __device__ int   g_ocnt[N_];
static __device__ int   g_fill[N_];
static __device__ int   g_ofill[N_];
static __device__ int   g_rowptr[N_+1];     // CSR by dst
static __device__ int   g_orowptr[N_+1];    // CSR by src
static __device__ int2  g_adj[M_];          // per dst-CSR pos: (src, norm bits)
static __device__ int   g_oadj[M_];         // per src-CSR pos: dst
static __device__ float g_alpha[M_];        // per dst-CSR pos
static __device__ float g_aq[N_];
static __device__ float g_ah[N_];
static __device__ float g_cl1[N_], g_cl2[N_], g_cl3[N_];
static __device__ float g_fit[N_];
static __device__ int   g_sel[N_];
static __device__ int   g_col[N_];
static __device__ int   g_ncol[K_];
static __device__ float g_xp[(size_t)K_*H_];
static __device__ int   g_scnt[N_];
static __device__ int   g_srowptr[N_+1];
static __device__ int2  g_sp[M_];            // packed (col k, alpha bits), CSR by src
static __device__ int   g_wcnt[N_];
static __device__ int   g_wrowptr[N_+1];
static __device__ int2  g_W[WCAP_];          // W = A*S rows
static __device__ __half g_Ach[(size_t)K_*K_];   // Ac in fp16 (32MB, L2-resident)

// ---------------- helpers ----------------
__device__ __forceinline__ int esrc_f(const int* __restrict__ e0, int e){ return (e < E_) ? e0[e] : (e - E_); }
__device__ __forceinline__ int edst_f(const int* __restrict__ e1, int e){ return (e < E_) ? e1[e] : (e - E_); }

// ---------------- small utility kernels ----------------
__global__ void k_init0(){
    int i = blockIdx.x*blockDim.x + threadIdx.x;
    if (i < N_){ g_cnt[i]=0; g_ocnt[i]=0; g_fill[i]=0; g_ofill[i]=0; g_scnt[i]=0; }
}
__global__ void k_count(const int* __restrict__ e0, const int* __restrict__ e1){
    int e = blockIdx.x*blockDim.x + threadIdx.x;
    if (e < M_){
        atomicAdd(&g_cnt[edst_f(e1,e)], 1);
        atomicAdd(&g_ocnt[esrc_f(e0,e)], 1);
    }
}
// exclusive scan of exactly 8192 ints with 1024 threads (shfl-based)
__device__ __forceinline__ void scan8192_body(const int* __restrict__ in, int* __restrict__ out){
    __shared__ int wsum[32];
    int tid=threadIdx.x, lane=tid&31, wid=tid>>5;
    int4 a=((const int4*)in)[tid*2], b=((const int4*)in)[tid*2+1];
    int l[8]={a.x,a.y,a.z,a.w,b.x,b.y,b.z,b.w};
    int s=0;
    #pragma unroll
    for(int q=0;q<8;q++) s+=l[q];
    int inc=s;
    #pragma unroll
    for(int o=1;o<32;o<<=1){ int t=__shfl_up_sync(0xffffffffu,inc,o); if(lane>=o) inc+=t; }
    if(lane==31) wsum[wid]=inc;
    __syncthreads();
    if (wid==0){
        int v = wsum[lane];
        #pragma unroll
        for(int o=1;o<32;o<<=1){ int t=__shfl_up_sync(0xffffffffu,v,o); if(lane>=o) v+=t; }
        wsum[lane]=v;
    }
    __syncthreads();
    int r = inc - s + (wid? wsum[wid-1]:0);
    int4 o1,o2;
    o1.x=r; r+=l[0]; o1.y=r; r+=l[1]; o1.z=r; r+=l[2]; o1.w=r; r+=l[3];
    o2.x=r; r+=l[4]; o2.y=r; r+=l[5]; o2.z=r; r+=l[6]; o2.w=r; r+=l[7];
    ((int4*)out)[tid*2]=o1; ((int4*)out)[tid*2+1]=o2;
    if (tid==1023) out[8192]=r;
}
__global__ void k_scan8192(const int* __restrict__ in, int* __restrict__ out){
    scan8192_body(in, out);
}
__global__ void k_scan2(){
    if (blockIdx.x == 0) scan8192_body(g_cnt, g_rowptr);
    else                 scan8192_body(g_ocnt, g_orowptr);
}
// build positional adjacency with folded norm (dis computed inline)
__global__ void k_fill(const int* __restrict__ e0, const int* __restrict__ e1){
    int e = blockIdx.x*blockDim.x + threadIdx.x;
    if (e < M_){
        int s = esrc_f(e0,e);
        int d = edst_f(e1,e);
        float nm = rsqrtf((float)g_cnt[s]) * rsqrtf((float)g_cnt[d]);
        int pos = g_rowptr[d] + atomicAdd(&g_fill[d],1);
        g_adj[pos] = make_int2(s, __float_as_int(nm));
        int opos = g_orowptr[s] + atomicAdd(&g_ofill[s],1);
        g_oadj[opos] = d;
    }
}

// ---------------- 8192x128 @ 128x128 GEMM ----------------
__global__ void k_gemm(const float* __restrict__ x, const float* __restrict__ w, float* __restrict__ y){
    __shared__ __align__(16) float xs[128*64];   // [kk][r]
    int r0 = blockIdx.x*64;
    int tid = threadIdx.x;
    for (int idx=tid; idx<64*128; idx+=256){
        int r = idx >> 7;
        int kk = idx & 127;
        xs[kk*64 + r] = x[(size_t)(r0+r)*128 + kk];
    }
    __syncthreads();
    int cg = tid & 31;
    int rg = tid >> 5;
    float acc[8][4];
    #pragma unroll
    for(int r=0;r<8;r++){ acc[r][0]=0.f;acc[r][1]=0.f;acc[r][2]=0.f;acc[r][3]=0.f; }
    #pragma unroll 4
    for(int kk=0;kk<128;kk++){
        float4 wv = *(const float4*)(w + kk*128 + cg*4);
        float4 x0 = *(const float4*)(xs + kk*64 + rg*8);
        float4 x1 = *(const float4*)(xs + kk*64 + rg*8 + 4);
        float xv[8] = {x0.x,x0.y,x0.z,x0.w,x1.x,x1.y,x1.z,x1.w};
        #pragma unroll
        for(int r=0;r<8;r++){
            acc[r][0] += xv[r]*wv.x; acc[r][1] += xv[r]*wv.y;
            acc[r][2] += xv[r]*wv.z; acc[r][3] += xv[r]*wv.w;
        }
    }
    #pragma unroll
    for(int r=0;r<8;r++){
        float4 o = make_float4(acc[r][0],acc[r][1],acc[r][2],acc[r][3]);
        *(float4*)(y + (size_t)(r0+rg*8+r)*128 + cg*4) = o;
    }
}

// ---------------- GCN aggregation: warp per dst, float4 lanes ----------------
__global__ void k_aggr(const float* __restrict__ y, const float* __restrict__ b,
                       float* __restrict__ out, int dotanh){
    int d = blockIdx.x*8 + (threadIdx.x>>5);
    int lane = threadIdx.x & 31;
    const float4* y4 = (const float4*)y;
    float4 acc = ((const float4*)b)[lane];
    int beg = g_rowptr[d], end = g_rowptr[d+1];
    int p = beg;
    for (; p+1 < end; p += 2){
        int2 a0 = g_adj[p], a1 = g_adj[p+1];
        float n0 = __int_as_float(a0.y), n1 = __int_as_float(a1.y);
        float4 v0 = y4[(size_t)a0.x*32 + lane];
        float4 v1 = y4[(size_t)a1.x*32 + lane];
        acc.x += n0*v0.x + n1*v1.x;
        acc.y += n0*v0.y + n1*v1.y;
        acc.z += n0*v0.z + n1*v1.z;
        acc.w += n0*v0.w + n1*v1.w;
    }
    if (p < end){
        int2 a0 = g_adj[p];
        float n0 = __int_as_float(a0.y);
        float4 v0 = y4[(size_t)a0.x*32 + lane];
        acc.x += n0*v0.x; acc.y += n0*v0.y; acc.z += n0*v0.z; acc.w += n0*v0.w;
    }
    if (dotanh){
        acc.x = tanhf(acc.x); acc.y = tanhf(acc.y);
        acc.z = tanhf(acc.z); acc.w = tanhf(acc.w);
    }
    ((float4*)out)[(size_t)d*32 + lane] = acc;
}

__global__ void k_segmax(const float* __restrict__ h, float* __restrict__ out){
    int d = blockIdx.x*8 + (threadIdx.x>>5);
    int lane = threadIdx.x & 31;
    const float4* h4 = (const float4*)h;
    float4 acc = make_float4(-INFINITY,-INFINITY,-INFINITY,-INFINITY);
    int beg = g_rowptr[d], end = g_rowptr[d+1];
    for (int p=beg; p<end; p++){
        float4 v = h4[(size_t)g_adj[p].x*32 + lane];
        acc.x = fmaxf(acc.x,v.x); acc.y = fmaxf(acc.y,v.y);
        acc.z = fmaxf(acc.z,v.z); acc.w = fmaxf(acc.w,v.w);
    }
    ((float4*)out)[(size_t)d*32 + lane] = acc;
}

__global__ void k_dots(const float* __restrict__ xq, const float* __restrict__ h,
                       const float* __restrict__ att, const float* __restrict__ bq){
    int node = blockIdx.x*8 + (threadIdx.x>>5);
    int lane = threadIdx.x & 31;
    const float4* xq4 = (const float4*)xq;
    const float4* h4  = (const float4*)h;
    const float4* at4 = (const float4*)att;
    const float4* bq4 = (const float4*)bq;
    float4 a1 = at4[lane], a2 = at4[32+lane];
    float4 xv = xq4[(size_t)node*32+lane], bv = bq4[lane], hv = h4[(size_t)node*32+lane];
    float s1 = a1.x*(xv.x+bv.x) + a1.y*(xv.y+bv.y) + a1.z*(xv.z+bv.z) + a1.w*(xv.w+bv.w);
    float s2 = a2.x*hv.x + a2.y*hv.y + a2.z*hv.z + a2.w*hv.w;
    #pragma unroll
    for (int o=16;o;o>>=1){ s1 += __shfl_down_sync(0xffffffffu,s1,o); s2 += __shfl_down_sync(0xffffffffu,s2,o); }
    if (!lane){ g_aq[node]=s1; g_ah[node]=s2; }
}

// ---------------- alpha: per-dst softmax over in-edges (warp per dst) ----------------
__global__ void k_alpha(){
    int d = blockIdx.x*8 + (threadIdx.x>>5);
    int lane = threadIdx.x & 31;
    int beg = g_rowptr[d], end = g_rowptr[d+1];
    float aqd = g_aq[d];
    float mx = -INFINITY;
    for (int p=beg+lane; p<end; p+=32){
        float sc = aqd + g_ah[g_adj[p].x];
        sc = sc > 0.f ? sc : 0.2f*sc;
        mx = fmaxf(mx, sc);
    }
    #pragma unroll
    for (int o=16;o;o>>=1) mx = fmaxf(mx, __shfl_xor_sync(0xffffffffu, mx, o));
    float sm = 0.f;
    for (int p=beg+lane; p<end; p+=32){
        float sc = aqd + g_ah[g_adj[p].x];
        sc = sc > 0.f ? sc : 0.2f*sc;
        sm += __expf(sc - mx);
    }
    #pragma unroll
    for (int o=16;o;o>>=1) sm += __shfl_xor_sync(0xffffffffu, sm, o);
    float inv = 1.f/sm;
    for (int p=beg+lane; p<end; p+=32){
        float sc = aqd + g_ah[g_adj[p].x];
        sc = sc > 0.f ? sc : 0.2f*sc;
        g_alpha[p] = __expf(sc - mx)*inv;
    }
}

// ---------------- cx = sum alpha*h[src] (warp per dst, float4) + fused LE dots ----------------
__global__ void k_cxle(const float* __restrict__ h, float* __restrict__ cx,
                       const float* __restrict__ lw1, const float* __restrict__ lw2,
                       const float* __restrict__ lw3){
    int d = blockIdx.x*8 + (threadIdx.x>>5);
    int lane = threadIdx.x & 31;
    const float4* h4 = (const float4*)h;
    float4 acc = make_float4(0,0,0,0);
    int beg = g_rowptr[d], end = g_rowptr[d+1];
    int p = beg;
    for (; p+1 < end; p += 2){
        float a0 = g_alpha[p], a1 = g_alpha[p+1];
        float4 v0 = h4[(size_t)g_adj[p].x*32 + lane];
        float4 v1 = h4[(size_t)g_adj[p+1].x*32 + lane];
        acc.x += a0*v0.x + a1*v1.x;
        acc.y += a0*v0.y + a1*v1.y;
        acc.z += a0*v0.z + a1*v1.z;
        acc.w += a0*v0.w + a1*v1.w;
    }
    if (p < end){
        float a0 = g_alpha[p];
        float4 v0 = h4[(size_t)g_adj[p].x*32 + lane];
        acc.x += a0*v0.x; acc.y += a0*v0.y; acc.z += a0*v0.z; acc.w += a0*v0.w;
    }
    ((float4*)cx)[(size_t)d*32 + lane] = acc;
    // LE dots
    float4 w1v = ((const float4*)lw1)[lane];
    float4 w2v = ((const float4*)lw2)[lane];
    float4 w3v = ((const float4*)lw3)[lane];
    float s1 = acc.x*w1v.x + acc.y*w1v.y + acc.z*w1v.z + acc.w*w1v.w;
    float s2 = acc.x*w2v.x + acc.y*w2v.y + acc.z*w2v.z + acc.w*w2v.w;
    float s3 = acc.x*w3v.x + acc.y*w3v.y + acc.z*w3v.z + acc.w*w3v.w;
    #pragma unroll
    for (int o=16;o;o>>=1){
        s1 += __shfl_down_sync(0xffffffffu,s1,o);
        s2 += __shfl_down_sync(0xffffffffu,s2,o);
        s3 += __shfl_down_sync(0xffffffffu,s3,o);
    }
    if (!lane){ g_cl1[d]=s1; g_cl2[d]=s2; g_cl3[d]=s3; }
}

__global__ void k_fit(const float* __restrict__ lb1){
    int d = blockIdx.x*blockDim.x + threadIdx.x;
    if (d >= N_) return;
    int beg=g_rowptr[d], end=g_rowptr[d+1];
    float s = 0.f;
    for (int q=beg;q<end;q++) s += g_cl3[g_adj[q].x];
    float aggr = (float)(end-beg)*g_cl2[d] - s;
    float z = g_cl1[d] + lb1[0] + aggr;
    g_fit[d] = 1.f/(1.f + __expf(-z));
}

// ---------------- top-K via 4x8-bit histogram radix select ----------------
__global__ void k_topk(){
    __shared__ int hist[256];
    __shared__ int wred[8];
    __shared__ unsigned s_pref;
    __shared__ int s_need;
    int tid=threadIdx.x, lane=tid&31, wid=tid>>5;
    if (tid==0){ s_pref=0u; s_need=K_; }
    unsigned keys[32];
    #pragma unroll
    for (int q=0;q<32;q++){
        unsigned u=__float_as_uint(g_fit[tid*32+q]);
        keys[q] = (u & 0x80000000u) ? ~u : (u | 0x80000000u);
    }
    __syncthreads();
    for (int round=0; round<4; round++){
        int shift = 24 - 8*round;
        hist[tid]=0;
        __syncthreads();
        unsigned pref = s_pref;
        #pragma unroll
        for (int q=0;q<32;q++){
            unsigned k = keys[q];
            bool match = (round==0) || ((k >> (shift+8)) == (pref >> (shift+8)));
            if (match) atomicAdd(&hist[(k>>shift)&0xFFu], 1);
        }
        __syncthreads();
        int mine = hist[255-tid];
        int v = mine;
        #pragma unroll
        for (int o=1;o<32;o<<=1){ int t2=__shfl_up_sync(0xffffffffu,v,o); if(lane>=o) v+=t2; }
        if (lane==31) wred[wid]=v;
        __syncthreads();
        int woff=0;
        #pragma unroll
        for (int w=0;w<8;w++) if (w<wid) woff+=wred[w];
        v += woff;
        int need0 = s_need;
        int vex = v - mine;
        if (v >= need0 && vex < need0){
            s_pref = s_pref | ((unsigned)(255-tid) << shift);
            s_need = need0 - vex;
        }
        __syncthreads();
    }
    unsigned thr = s_pref;
    int need = s_need;
    int tcnt=0;
    #pragma unroll
    for (int q=0;q<32;q++) tcnt += (keys[q]==thr);
    int v=tcnt;
    #pragma unroll
    for (int o=1;o<32;o<<=1){ int t2=__shfl_up_sync(0xffffffffu,v,o); if(lane>=o) v+=t2; }
    if (lane==31) wred[wid]=v;
    __syncthreads();
    int woff=0;
    #pragma unroll
    for (int w=0;w<8;w++) if (w<wid) woff+=wred[w];
    int rank = v - tcnt + woff;
    int scnt=0;
    int selq[32];
    #pragma unroll
    for (int q=0;q<32;q++){
        unsigned k=keys[q];
        bool eq = (k==thr);
        int s = (k>thr) || (eq && rank < need);
        if (eq) rank++;
        selq[q]=s;
        g_sel[tid*32+q]=s;
        scnt+=s;
    }
    __syncthreads();
    v=scnt;
    #pragma unroll
    for (int o=1;o<32;o<<=1){ int t2=__shfl_up_sync(0xffffffffu,v,o); if(lane>=o) v+=t2; }
    if (lane==31) wred[wid]=v;
    __syncthreads();
    woff=0;
    #pragma unroll
    for (int w=0;w<8;w++) if (w<wid) woff+=wred[w];
    int base = v - scnt + woff;
    #pragma unroll
    for (int q=0;q<32;q++){
        int i = tid*32+q;
        if (selq[q]){ g_col[i]=base; g_ncol[base]=i; base++; }
        else g_col[i]=-1;
    }
}

// ---------------- S CSR count (+ g_fill reset folded in) ----------------
__global__ void k_scount(){
    int d = blockIdx.x*blockDim.x + threadIdx.x;
    if (d >= N_) return;
    g_fill[d]=0;
    if (!g_sel[d]) return;
    int beg=g_rowptr[d], end=g_rowptr[d+1];
    for (int p=beg;p<end;p++) atomicAdd(&g_scnt[g_adj[p].x], 1);
}
// merged xp write + sfill scatter: block per dst, 128 threads
__global__ void k_xpsfill(const float* __restrict__ cx){
    int d = blockIdx.x, t = threadIdx.x;
    if (!g_sel[d]) return;
    int colk = g_col[d];
    g_xp[(size_t)colk*128 + t] = cx[(size_t)d*128 + t] * g_fit[d];
    int beg=g_rowptr[d], end=g_rowptr[d+1];
    for (int p=beg+t; p<end; p+=128){
        int s = g_adj[p].x;
        int pos = g_srowptr[s] + atomicAdd(&g_fill[s],1);
        g_sp[pos] = make_int2(colk, __float_as_int(g_alpha[p]));
    }
}

// ---------------- W = A*S (sparse rows): count, fill ----------------
__global__ void k_wcount(){
    int s = blockIdx.x*blockDim.x + threadIdx.x;
    if (s >= N_) return;
    int ob=g_orowptr[s], oe=g_orowptr[s+1];
    int total=0;
    for (int f=ob;f<oe;f++){
        int j = g_oadj[f];
        total += g_srowptr[j+1]-g_srowptr[j];
    }
    g_wcnt[s]=total;
}
// warp per source: copy S_j lists into W row
__global__ void k_wfill(){
    int s = blockIdx.x*8 + (threadIdx.x>>5);
    int lane = threadIdx.x & 31;
    int wpos = g_wrowptr[s];
    int ob=g_orowptr[s], oe=g_orowptr[s+1];
    for (int f=ob;f<oe;f++){
        int j = g_oadj[f];
        int sb=g_srowptr[j], len=g_srowptr[j+1]-sb;
        for (int q=lane;q<len;q+=32) g_W[wpos+q]=g_sp[sb+q];
        wpos += len;
    }
}

// ---------------- Ac row gather with smem fp32 accumulator -> fp16 store ----------------
__global__ void k_AcRow(){
    __shared__ __align__(16) float acc[K_];
    int k = blockIdx.x, tid = threadIdx.x;
    int lane = tid & 31, w = tid >> 5, nw = blockDim.x >> 5;
    {
        float4 z = make_float4(0,0,0,0);
        float4* a4 = (float4*)acc;
        #pragma unroll
        for (int m=0;m<2;m++) a4[tid + m*512] = z;
    }
    __syncthreads();
    int d = g_ncol[k];
    int ib = g_rowptr[d], ie = g_rowptr[d+1];
    for (int p=ib+w; p<ie; p+=nw){
        int s = g_adj[p].x;
        float ae = g_alpha[p];
        int wb = g_wrowptr[s], we = g_wrowptr[s+1];
        int q = wb + lane;
        for (; q+32 < we; q += 64){
            int2 e0 = g_W[q];
            int2 e1 = g_W[q+32];
            atomicAdd(&acc[e0.x], ae*__int_as_float(e0.y));
            atomicAdd(&acc[e1.x], ae*__int_as_float(e1.y));
        }
        if (q < we){
            int2 e0 = g_W[q];
            atomicAdd(&acc[e0.x], ae*__int_as_float(e0.y));
        }
    }
    __syncthreads();
    __half2* orow = (__half2*)(g_Ach + (size_t)k*K_);
    #pragma unroll
    for (int m=0;m<4;m++){
        int i2 = tid + m*512;
        orow[i2] = __floats2half2_rn(acc[2*i2], acc[2*i2+1]);
    }
}

// ---------------- fused: build 16 P-rows (fp32 acc -> fp16 smem), adj = P S^T ----------------
__global__ void __launch_bounds__(1024, 1) k_adjF(float* __restrict__ adj){
    extern __shared__ __align__(16) char PshB[];
    int2* sc = (int2*)(PshB + 131072);
    int i0 = blockIdx.x*AR, tid = threadIdx.x;

    int qb0 = g_srowptr[i0];
    int qend = g_srowptr[i0+AR];
    int total = qend - qb0;
    int ncache = total < SCACHE ? total : SCACHE;
    for (int q=tid; q<ncache; q+=1024) sc[q] = g_sp[qb0+q];
    __syncthreads();

    #pragma unroll 1
    for (int rp=0;rp<8;rp++){
        float accA[4], accB[4];
        #pragma unroll
        for (int m=0;m<4;m++){ accA[m]=0.f; accB[m]=0.f; }
        #pragma unroll 1
        for (int half_i=0; half_i<2; half_i++){
            int i = i0 + 2*rp + half_i;
            float* acc = half_i ? accB : accA;
            int qb=g_srowptr[i], qe=g_srowptr[i+1];
            if (qe - qb0 <= ncache){
                int base = qb - qb0, len = qe - qb;
                #pragma unroll 2
                for (int q=0;q<len;q++){
                    int2 kp = sc[base+q];
                    float a = __int_as_float(kp.y);
                    const __half2* row = (const __half2*)(g_Ach + (size_t)kp.x*K_);
                    #pragma unroll
                    for (int m=0;m<2;m++){
                        float2 f = __half22float2(row[tid + 1024*m]);
                        acc[2*m]   += a*f.x;
                        acc[2*m+1] += a*f.y;
                    }
                }
            } else {
                for (int q=qb;q<qe;q++){
                    int2 kp = g_sp[q];
                    float a = __int_as_float(kp.y);
                    const __half2* row = (const __half2*)(g_Ach + (size_t)kp.x*K_);
                    #pragma unroll
                    for (int m=0;m<2;m++){
                        float2 f = __half22float2(row[tid + 1024*m]);
                        acc[2*m]   += a*f.x;
                        acc[2*m+1] += a*f.y;
                    }
                }
            }
        }
        char* region = PshB + ((rp<4)? 0 : 65536);
        int woff = (rp & 3)*4;
        #pragma unroll
        for (int m=0;m<2;m++){
            int k0 = 2*(tid + 1024*m);
            *(__half2*)(region + (size_t)k0*16 + woff)     = __floats2half2_rn(accA[2*m],   accB[2*m]);
            *(__half2*)(region + (size_t)(k0+1)*16 + woff) = __floats2half2_rn(accA[2*m+1], accB[2*m+1]);
        }
    }
    __syncthreads();
    for (int j=tid; j<N_; j+=1024){
        float b[16];
        #pragma unroll
        for (int r=0;r<16;r++) b[r]=0.f;
        int qb = g_srowptr[j], qe = g_srowptr[j+1];
        for (int q=qb;q<qe;q++){
            int2 kp = g_sp[q];
            float a = __int_as_float(kp.y);
            uint4 lo = *(const uint4*)(PshB + (size_t)kp.x*16);
            uint4 hi = *(const uint4*)(PshB + 65536 + (size_t)kp.x*16);
            float2 f;
            f = __half22float2(*(__half2*)&lo.x); b[0] += a*f.x; b[1] += a*f.y;
            f = __half22float2(*(__half2*)&lo.y); b[2] += a*f.x; b[3] += a*f.y;
            f = __half22float2(*(__half2*)&lo.z); b[4] += a*f.x; b[5] += a*f.y;
            f = __half22float2(*(__half2*)&lo.w); b[6] += a*f.x; b[7] += a*f.y;
            f = __half22float2(*(__half2*)&hi.x); b[8] += a*f.x; b[9] += a*f.y;
            f = __half22float2(*(__half2*)&hi.y); b[10]+= a*f.x; b[11]+= a*f.y;
            f = __half22float2(*(__half2*)&hi.z); b[12]+= a*f.x; b[13]+= a*f.y;
            f = __half22float2(*(__half2*)&hi.w); b[14]+= a*f.x; b[15]+= a*f.y;
        }
        #pragma unroll
        for (int r=0;r<16;r++) adj[(size_t)(i0+r)*N_ + j] = b[r];
    }
}

// x_out[i,:] = sum over S row i: alpha*xp[k,:]  (warp per row, float4)
__global__ void k_xout(float* __restrict__ out){
    int i = blockIdx.x*8 + (threadIdx.x>>5);
    int lane = threadIdx.x & 31;
    const float4* xp4 = (const float4*)g_xp;
    float4 acc = make_float4(0,0,0,0);
    int beg=g_srowptr[i], end=g_srowptr[i+1];
    for (int q=beg;q<end;q++){
        int2 kp = g_sp[q];
        float a = __int_as_float(kp.y);
        float4 v = xp4[(size_t)kp.x*32 + lane];
        acc.x += a*v.x; acc.y += a*v.y; acc.z += a*v.z; acc.w += a*v.w;
    }
    ((float4*)out)[(size_t)i*32 + lane] = acc;
}

// ---------------- host ----------------
static cudaStream_t get_s2(){
    static cudaStream_t s = 0;
    if (!s) cudaStreamCreate(&s);
    return s;
}
static cudaEvent_t get_ev(int which){
    static cudaEvent_t ev[4] = {0,0,0,0};
    if (!ev[which]) cudaEventCreateWithFlags(&ev[which], cudaEventDisableTiming);
    return ev[which];
}

extern "C" void kernel_launch(void* const* d_in, const int* in_sizes, int n_in,
                              void* d_out, int out_size){
    const float* nodes = (const float*)d_in[0];
    const int*   edges = (const int*)d_in[1];
    const int* e0 = edges;
    const int* e1 = edges + E_;
    const float* w1 = (const float*)d_in[3];  const float* b1 = (const float*)d_in[4];
    const float* w2 = (const float*)d_in[5];  const float* b2 = (const float*)d_in[6];
    const float* w3 = (const float*)d_in[7];  const float* b3 = (const float*)d_in[8];
    const float* w4 = (const float*)d_in[9];  const float* b4 = (const float*)d_in[10];
    const float* w5 = (const float*)d_in[11]; const float* b5 = (const float*)d_in[12];
    const float* wq = (const float*)d_in[13]; const float* bq = (const float*)d_in[14];
    const float* att = (const float*)d_in[15];
    const float* lw1 = (const float*)d_in[16]; const float* lb1 = (const float*)d_in[17];
    const float* lw2 = (const float*)d_in[18]; const float* lw3 = (const float*)d_in[19];

    float* out = (float*)d_out;
    float* x2out = out;
    float* adj  = out + (size_t)N_*H_;

    float *A,*B,*C,*T; int *scnt,*srowptr,*wcnt,*wrowptr;
    cudaGetSymbolAddress((void**)&A, g_bufA);
    cudaGetSymbolAddress((void**)&B, g_bufB);
    cudaGetSymbolAddress((void**)&C, g_bufC);
    cudaGetSymbolAddress((void**)&T, g_bufT);
    cudaGetSymbolAddress((void**)&scnt, g_scnt);
    cudaGetSymbolAddress((void**)&srowptr, g_srowptr);
    cudaGetSymbolAddress((void**)&wcnt, g_wcnt);
    cudaGetSymbolAddress((void**)&wrowptr, g_wrowptr);

    const int TB = 256;
    const int MB = (M_ + TB - 1)/TB;
    const int NB = (N_ + TB - 1)/TB;

    cudaStream_t s2 = get_s2();
    cudaEvent_t evF0 = get_ev(0), evJ0 = get_ev(1), evF1 = get_ev(2), evJ1 = get_ev(3);

    // fork 0: first gemm (depends only on inputs) overlaps graph prep
    cudaEventRecord(evF0, 0);
    cudaStreamWaitEvent(s2, evF0, 0);
    k_gemm<<<128,256,0,s2>>>(nodes, w1, T);
    cudaEventRecord(evJ0, s2);

    // graph prep: dst-CSR + src-CSR with folded norms (main stream)
    k_init0<<<NB, TB>>>();
    k_count<<<MB, TB>>>(e0, e1);
    k_scan2<<<2,1024>>>();
    k_fill<<<MB, TB>>>(e0, e1);

    // encoder (needs gemm1 result)
    cudaStreamWaitEvent(0, evJ0, 0);
    k_aggr<<<N_/8,256>>>(T, b1, A, 1);
    k_gemm<<<128,256>>>(A, w2, T);
    k_aggr<<<N_/8,256>>>(T, b2, B, 1);       // B = h

    // pooling
    k_segmax<<<N_/8,256>>>(B, A);
    k_gemm<<<128,256>>>(A, wq, T);
    k_dots<<<N_/8,256>>>(T, B, att, bq);
    k_alpha<<<N_/8,256>>>();                 // positional softmax alpha
    k_cxle<<<N_/8,256>>>(B, C, lw1, lw2, lw3); // cx + fused LE dots
    k_fit<<<NB, TB>>>(lb1);
    k_topk<<<1,256>>>();

    // S CSR (by source); scount also resets g_fill
    k_scount<<<NB, TB>>>();
    k_scan8192<<<1,1024>>>(scnt, srowptr);
    k_xpsfill<<<N_,128>>>(C);

    // fork 1: decoder branch (s2) overlaps W-build + AcRow + adjF (main)
    cudaEventRecord(evF1, 0);
    cudaStreamWaitEvent(s2, evF1, 0);
    k_xout<<<N_/8,256,0,s2>>>(A);            // A = x_out
    k_gemm<<<128,256,0,s2>>>(A, w3, T);
    k_aggr<<<N_/8,256,0,s2>>>(T, b3, B, 1);
    k_gemm<<<128,256,0,s2>>>(B, w4, T);
    k_aggr<<<N_/8,256,0,s2>>>(T, b4, A, 1);
    k_gemm<<<128,256,0,s2>>>(A, w5, T);
    k_aggr<<<N_/8,256,0,s2>>>(T, b5, x2out, 0);
    cudaEventRecord(evJ1, s2);

    // main: W = A*S sparse rows, Ac (fp16), adj
    k_wcount<<<NB, TB>>>();
    k_scan8192<<<1,1024>>>(wcnt, wrowptr);
    k_wfill<<<N_/8, 256>>>();
    k_AcRow<<<K_, 512>>>();
    cudaFuncSetAttribute(k_adjF, cudaFuncAttributeMaxDynamicSharedMemorySize, PSH_TOTAL);
    k_adjF<<<N_/AR, 1024, PSH_TOTAL>>>(adj);

    // join decoder branch
    cudaStreamWaitEvent(0, evJ1, 0);
}

// round 14
// speedup vs baseline: 1.3837x; 1.0251x over previous
#include <cuda_runtime.h>
#include <cuda_fp16.h>
#include <math.h>
#include <stdint.h>

#define N_ 8192
#define E_ 131072
#define M_ (E_ + N_)          // 139264 edges incl self loops
#define H_ 128
#define K_ 4096
#define WCAP_ 3000000

#define AR 16                 // rows per adjF block
#define SCACHE 1024
#define PSH_TOTAL (131072 + SCACHE*8)

// ---------------- device scratch ----------------
static __device__ float g_bufA[(size_t)N_*H_];
static __device__ float g_bufB[(size_t)N_*H_];
static __device__ float g_bufC[(size_t)N_*H_];
static __device__ float g_bufT[(size_t)N_*H_];
static __device__ int   g_cnt[N_];
static __device__ int   g_ocnt[N_];
static __device__ int   g_fill[N_];
static __device__ int   g_ofill[N_];
static __device__ int   g_rowptr[N_+1];     // CSR by dst
static __device__ int   g_orowptr[N_+1];    // CSR by src
static __device__ int2  g_adj[M_];          // per dst-CSR pos: (src, norm bits)
static __device__ int   g_oadj[M_];         // per src-CSR pos: dst
static __device__ float g_alpha[M_];        // per dst-CSR pos
static __device__ float g_aq[N_];
static __device__ float g_ah[N_];
static __device__ float g_vq[H_];           // wq @ att1
static __device__ float g_cq;               // bq . att1
static __device__ float g_cl1[N_], g_cl2[N_], g_cl3[N_];
static __device__ float g_fit[N_];
static __device__ int   g_sel[N_];
static __device__ int   g_col[N_];
static __device__ int   g_ncol[K_];
static __device__ float g_xp[(size_t)K_*H_];
static __device__ int   g_scnt[N_];
static __device__ int   g_srowptr[N_+1];
static __device__ int2  g_sp[M_];            // packed (col k, alpha bits), CSR by src
static __device__ int   g_wcnt[N_];
static __device__ int   g_wrowptr[N_+1];
static __device__ int2  g_W[WCAP_];          // W = A*S rows
static __device__ __half g_Ach[(size_t)K_*K_];   // Ac in fp16

// ---------------- helpers ----------------
__device__ __forceinline__ int esrc_f(const int* __restrict__ e0, int e){ return (e < E_) ? e0[e] : (e - E_); }
__device__ __forceinline__ int edst_f(const int* __restrict__ e1, int e){ return (e < E_) ? e1[e] : (e - E_); }

// ---------------- small utility kernels ----------------
__global__ void k_init0(){
    int i = blockIdx.x*blockDim.x + threadIdx.x;
    if (i < N_){ g_cnt[i]=0; g_ocnt[i]=0; g_fill[i]=0; g_ofill[i]=0; g_scnt[i]=0; }
}
__global__ void k_count(const int* __restrict__ e0, const int* __restrict__ e1){
    int e = blockIdx.x*blockDim.x + threadIdx.x;
    if (e < M_){
        atomicAdd(&g_cnt[edst_f(e1,e)], 1);
        atomicAdd(&g_ocnt[esrc_f(e0,e)], 1);
    }
}
// v = wq @ att1, c = bq . att1
__global__ void k_prevec(const float* __restrict__ wq, const float* __restrict__ att,
                         const float* __restrict__ bq){
    int k = threadIdx.x;
    float s = 0.f;
    for (int j=0;j<H_;j++) s += wq[k*H_+j]*att[j];
    g_vq[k] = s;
    if (k==0){
        float c = 0.f;
        for (int j=0;j<H_;j++) c += bq[j]*att[j];
        g_cq = c;
    }
}
// exclusive scan of exactly 8192 ints with 1024 threads (shfl-based)
__device__ __forceinline__ void scan8192_body(const int* __restrict__ in, int* __restrict__ out){
    __shared__ int wsum[32];
    int tid=threadIdx.x, lane=tid&31, wid=tid>>5;
    int4 a=((const int4*)in)[tid*2], b=((const int4*)in)[tid*2+1];
    int l[8]={a.x,a.y,a.z,a.w,b.x,b.y,b.z,b.w};
    int s=0;
    #pragma unroll
    for(int q=0;q<8;q++) s+=l[q];
    int inc=s;
    #pragma unroll
    for(int o=1;o<32;o<<=1){ int t=__shfl_up_sync(0xffffffffu,inc,o); if(lane>=o) inc+=t; }
    if(lane==31) wsum[wid]=inc;
    __syncthreads();
    if (wid==0){
        int v = wsum[lane];
        #pragma unroll
        for(int o=1;o<32;o<<=1){ int t=__shfl_up_sync(0xffffffffu,v,o); if(lane>=o) v+=t; }
        wsum[lane]=v;
    }
    __syncthreads();
    int r = inc - s + (wid? wsum[wid-1]:0);
    int4 o1,o2;
    o1.x=r; r+=l[0]; o1.y=r; r+=l[1]; o1.z=r; r+=l[2]; o1.w=r; r+=l[3];
    o2.x=r; r+=l[4]; o2.y=r; r+=l[5]; o2.z=r; r+=l[6]; o2.w=r; r+=l[7];
    ((int4*)out)[tid*2]=o1; ((int4*)out)[tid*2+1]=o2;
    if (tid==1023) out[8192]=r;
}
__global__ void k_scan8192(const int* __restrict__ in, int* __restrict__ out){
    scan8192_body(in, out);
}
__global__ void k_scan2(){
    if (blockIdx.x == 0) scan8192_body(g_cnt, g_rowptr);
    else                 scan8192_body(g_ocnt, g_orowptr);
}
// build positional adjacency with folded norm
__global__ void k_fill(const int* __restrict__ e0, const int* __restrict__ e1){
    int e = blockIdx.x*blockDim.x + threadIdx.x;
    if (e < M_){
        int s = esrc_f(e0,e);
        int d = edst_f(e1,e);
        float nm = rsqrtf((float)g_cnt[s]) * rsqrtf((float)g_cnt[d]);
        int pos = g_rowptr[d] + atomicAdd(&g_fill[d],1);
        g_adj[pos] = make_int2(s, __float_as_int(nm));
        int opos = g_orowptr[s] + atomicAdd(&g_ofill[s],1);
        g_oadj[opos] = d;
    }
}

// ---------------- 8192x128 @ 128x128 GEMM ----------------
__global__ void k_gemm(const float* __restrict__ x, const float* __restrict__ w, float* __restrict__ y){
    __shared__ __align__(16) float xs[128*64];   // [kk][r]
    int r0 = blockIdx.x*64;
    int tid = threadIdx.x;
    for (int idx=tid; idx<64*128; idx+=256){
        int r = idx >> 7;
        int kk = idx & 127;
        xs[kk*64 + r] = x[(size_t)(r0+r)*128 + kk];
    }
    __syncthreads();
    int cg = tid & 31;
    int rg = tid >> 5;
    float acc[8][4];
    #pragma unroll
    for(int r=0;r<8;r++){ acc[r][0]=0.f;acc[r][1]=0.f;acc[r][2]=0.f;acc[r][3]=0.f; }
    #pragma unroll 4
    for(int kk=0;kk<128;kk++){
        float4 wv = *(const float4*)(w + kk*128 + cg*4);
        float4 x0 = *(const float4*)(xs + kk*64 + rg*8);
        float4 x1 = *(const float4*)(xs + kk*64 + rg*8 + 4);
        float xv[8] = {x0.x,x0.y,x0.z,x0.w,x1.x,x1.y,x1.z,x1.w};
        #pragma unroll
        for(int r=0;r<8;r++){
            acc[r][0] += xv[r]*wv.x; acc[r][1] += xv[r]*wv.y;
            acc[r][2] += xv[r]*wv.z; acc[r][3] += xv[r]*wv.w;
        }
    }
    #pragma unroll
    for(int r=0;r<8;r++){
        float4 o = make_float4(acc[r][0],acc[r][1],acc[r][2],acc[r][3]);
        *(float4*)(y + (size_t)(r0+rg*8+r)*128 + cg*4) = o;
    }
}

// ---------------- GCN aggregation: warp per dst, float4 lanes ----------------
__global__ void k_aggr(const float* __restrict__ y, const float* __restrict__ b,
                       float* __restrict__ out, int dotanh){
    int d = blockIdx.x*8 + (threadIdx.x>>5);
    int lane = threadIdx.x & 31;
    const float4* y4 = (const float4*)y;
    float4 acc = ((const float4*)b)[lane];
    int beg = g_rowptr[d], end = g_rowptr[d+1];
    int p = beg;
    for (; p+1 < end; p += 2){
        int2 a0 = g_adj[p], a1 = g_adj[p+1];
        float n0 = __int_as_float(a0.y), n1 = __int_as_float(a1.y);
        float4 v0 = y4[(size_t)a0.x*32 + lane];
        float4 v1 = y4[(size_t)a1.x*32 + lane];
        acc.x += n0*v0.x + n1*v1.x;
        acc.y += n0*v0.y + n1*v1.y;
        acc.z += n0*v0.z + n1*v1.z;
        acc.w += n0*v0.w + n1*v1.w;
    }
    if (p < end){
        int2 a0 = g_adj[p];
        float n0 = __int_as_float(a0.y);
        float4 v0 = y4[(size_t)a0.x*32 + lane];
        acc.x += n0*v0.x; acc.y += n0*v0.y; acc.z += n0*v0.z; acc.w += n0*v0.w;
    }
    if (dotanh){
        acc.x = tanhf(acc.x); acc.y = tanhf(acc.y);
        acc.z = tanhf(acc.z); acc.w = tanhf(acc.w);
    }
    ((float4*)out)[(size_t)d*32 + lane] = acc;
}

// ---------------- fused segmax + aq/ah dots (warp per dst) ----------------
__global__ void k_segdots(const float* __restrict__ h, const float* __restrict__ att){
    int d = blockIdx.x*8 + (threadIdx.x>>5);
    int lane = threadIdx.x & 31;
    const float4* h4 = (const float4*)h;
    float4 mx = make_float4(-INFINITY,-INFINITY,-INFINITY,-INFINITY);
    int beg = g_rowptr[d], end = g_rowptr[d+1];
    for (int p=beg; p<end; p++){
        float4 v = h4[(size_t)g_adj[p].x*32 + lane];
        mx.x = fmaxf(mx.x,v.x); mx.y = fmaxf(mx.y,v.y);
        mx.z = fmaxf(mx.z,v.z); mx.w = fmaxf(mx.w,v.w);
    }
    float4 vv = ((const float4*)g_vq)[lane];
    float4 a2 = ((const float4*)att)[32+lane];
    float4 hd = h4[(size_t)d*32 + lane];
    float s1 = mx.x*vv.x + mx.y*vv.y + mx.z*vv.z + mx.w*vv.w;
    float s2 = hd.x*a2.x + hd.y*a2.y + hd.z*a2.z + hd.w*a2.w;
    #pragma unroll
    for (int o=16;o;o>>=1){
        s1 += __shfl_down_sync(0xffffffffu,s1,o);
        s2 += __shfl_down_sync(0xffffffffu,s2,o);
    }
    if (!lane){ g_aq[d]=s1+g_cq; g_ah[d]=s2; }
}

// ---------------- alpha: per-dst softmax over in-edges (warp per dst) ----------------
__global__ void k_alpha(){
    int d = blockIdx.x*8 + (threadIdx.x>>5);
    int lane = threadIdx.x & 31;
    int beg = g_rowptr[d], end = g_rowptr[d+1];
    float aqd = g_aq[d];
    float mx = -INFINITY;
    for (int p=beg+lane; p<end; p+=32){
        float sc = aqd + g_ah[g_adj[p].x];
        sc = sc > 0.f ? sc : 0.2f*sc;
        mx = fmaxf(mx, sc);
    }
    #pragma unroll
    for (int o=16;o;o>>=1) mx = fmaxf(mx, __shfl_xor_sync(0xffffffffu, mx, o));
    float sm = 0.f;
    for (int p=beg+lane; p<end; p+=32){
        float sc = aqd + g_ah[g_adj[p].x];
        sc = sc > 0.f ? sc : 0.2f*sc;
        sm += __expf(sc - mx);
    }
    #pragma unroll
    for (int o=16;o;o>>=1) sm += __shfl_xor_sync(0xffffffffu, sm, o);
    float inv = 1.f/sm;
    for (int p=beg+lane; p<end; p+=32){
        float sc = aqd + g_ah[g_adj[p].x];
        sc = sc > 0.f ? sc : 0.2f*sc;
        g_alpha[p] = __expf(sc - mx)*inv;
    }
}

// ---------------- cx = sum alpha*h[src] (warp per dst, float4) + fused LE dots ----------------
__global__ void k_cxle(const float* __restrict__ h, float* __restrict__ cx,
                       const float* __restrict__ lw1, const float* __restrict__ lw2,
                       const float* __restrict__ lw3){
    int d = blockIdx.x*8 + (threadIdx.x>>5);
    int lane = threadIdx.x & 31;
    const float4* h4 = (const float4*)h;
    float4 acc = make_float4(0,0,0,0);
    int beg = g_rowptr[d], end = g_rowptr[d+1];
    int p = beg;
    for (; p+1 < end; p += 2){
        float a0 = g_alpha[p], a1 = g_alpha[p+1];
        float4 v0 = h4[(size_t)g_adj[p].x*32 + lane];
        float4 v1 = h4[(size_t)g_adj[p+1].x*32 + lane];
        acc.x += a0*v0.x + a1*v1.x;
        acc.y += a0*v0.y + a1*v1.y;
        acc.z += a0*v0.z + a1*v1.z;
        acc.w += a0*v0.w + a1*v1.w;
    }
    if (p < end){
        float a0 = g_alpha[p];
        float4 v0 = h4[(size_t)g_adj[p].x*32 + lane];
        acc.x += a0*v0.x; acc.y += a0*v0.y; acc.z += a0*v0.z; acc.w += a0*v0.w;
    }
    ((float4*)cx)[(size_t)d*32 + lane] = acc;
    float4 w1v = ((const float4*)lw1)[lane];
    float4 w2v = ((const float4*)lw2)[lane];
    float4 w3v = ((const float4*)lw3)[lane];
    float s1 = acc.x*w1v.x + acc.y*w1v.y + acc.z*w1v.z + acc.w*w1v.w;
    float s2 = acc.x*w2v.x + acc.y*w2v.y + acc.z*w2v.z + acc.w*w2v.w;
    float s3 = acc.x*w3v.x + acc.y*w3v.y + acc.z*w3v.z + acc.w*w3v.w;
    #pragma unroll
    for (int o=16;o;o>>=1){
        s1 += __shfl_down_sync(0xffffffffu,s1,o);
        s2 += __shfl_down_sync(0xffffffffu,s2,o);
        s3 += __shfl_down_sync(0xffffffffu,s3,o);
    }
    if (!lane){ g_cl1[d]=s1; g_cl2[d]=s2; g_cl3[d]=s3; }
}

__global__ void k_fit(const float* __restrict__ lb1){
    int d = blockIdx.x*blockDim.x + threadIdx.x;
    if (d >= N_) return;
    int beg=g_rowptr[d], end=g_rowptr[d+1];
    float s = 0.f;
    for (int q=beg;q<end;q++) s += g_cl3[g_adj[q].x];
    float aggr = (float)(end-beg)*g_cl2[d] - s;
    float z = g_cl1[d] + lb1[0] + aggr;
    g_fit[d] = 1.f/(1.f + __expf(-z));
}

// ---------------- top-K via 4x8-bit histogram radix select ----------------
__global__ void k_topk(){
    __shared__ int hist[256];
    __shared__ int wred[8];
    __shared__ unsigned s_pref;
    __shared__ int s_need;
    int tid=threadIdx.x, lane=tid&31, wid=tid>>5;
    if (tid==0){ s_pref=0u; s_need=K_; }
    unsigned keys[32];
    #pragma unroll
    for (int q=0;q<32;q++){
        unsigned u=__float_as_uint(g_fit[tid*32+q]);
        keys[q] = (u & 0x80000000u) ? ~u : (u | 0x80000000u);
    }
    __syncthreads();
    for (int round=0; round<4; round++){
        int shift = 24 - 8*round;
        hist[tid]=0;
        __syncthreads();
        unsigned pref = s_pref;
        #pragma unroll
        for (int q=0;q<32;q++){
            unsigned k = keys[q];
            bool match = (round==0) || ((k >> (shift+8)) == (pref >> (shift+8)));
            if (match) atomicAdd(&hist[(k>>shift)&0xFFu], 1);
        }
        __syncthreads();
        int mine = hist[255-tid];
        int v = mine;
        #pragma unroll
        for (int o=1;o<32;o<<=1){ int t2=__shfl_up_sync(0xffffffffu,v,o); if(lane>=o) v+=t2; }
        if (lane==31) wred[wid]=v;
        __syncthreads();
        int woff=0;
        #pragma unroll
        for (int w=0;w<8;w++) if (w<wid) woff+=wred[w];
        v += woff;
        int need0 = s_need;
        int vex = v - mine;
        if (v >= need0 && vex < need0){
            s_pref = s_pref | ((unsigned)(255-tid) << shift);
            s_need = need0 - vex;
        }
        __syncthreads();
    }
    unsigned thr = s_pref;
    int need = s_need;
    int tcnt=0;
    #pragma unroll
    for (int q=0;q<32;q++) tcnt += (keys[q]==thr);
    int v=tcnt;
    #pragma unroll
    for (int o=1;o<32;o<<=1){ int t2=__shfl_up_sync(0xffffffffu,v,o); if(lane>=o) v+=t2; }
    if (lane==31) wred[wid]=v;
    __syncthreads();
    int woff=0;
    #pragma unroll
    for (int w=0;w<8;w++) if (w<wid) woff+=wred[w];
    int rank = v - tcnt + woff;
    int scnt=0;
    int selq[32];
    #pragma unroll
    for (int q=0;q<32;q++){
        unsigned k=keys[q];
        bool eq = (k==thr);
        int s = (k>thr) || (eq && rank < need);
        if (eq) rank++;
        selq[q]=s;
        g_sel[tid*32+q]=s;
        scnt+=s;
    }
    __syncthreads();
    v=scnt;
    #pragma unroll
    for (int o=1;o<32;o<<=1){ int t2=__shfl_up_sync(0xffffffffu,v,o); if(lane>=o) v+=t2; }
    if (lane==31) wred[wid]=v;
    __syncthreads();
    woff=0;
    #pragma unroll
    for (int w=0;w<8;w++) if (w<wid) woff+=wred[w];
    int base = v - scnt + woff;
    #pragma unroll
    for (int q=0;q<32;q++){
        int i = tid*32+q;
        if (selq[q]){ g_col[i]=base; g_ncol[base]=i; base++; }
        else g_col[i]=-1;
    }
}

// ---------------- S CSR count (+ g_fill reset folded in) ----------------
__global__ void k_scount(){
    int d = blockIdx.x*blockDim.x + threadIdx.x;
    if (d >= N_) return;
    g_fill[d]=0;
    if (!g_sel[d]) return;
    int beg=g_rowptr[d], end=g_rowptr[d+1];
    for (int p=beg;p<end;p++) atomicAdd(&g_scnt[g_adj[p].x], 1);
}
// merged xp write + sfill scatter: block per dst, 128 threads
__global__ void k_xpsfill(const float* __restrict__ cx){
    int d = blockIdx.x, t = threadIdx.x;
    if (!g_sel[d]) return;
    int colk = g_col[d];
    g_xp[(size_t)colk*128 + t] = cx[(size_t)d*128 + t] * g_fit[d];
    int beg=g_rowptr[d], end=g_rowptr[d+1];
    for (int p=beg+t; p<end; p+=128){
        int s = g_adj[p].x;
        int pos = g_srowptr[s] + atomicAdd(&g_fill[s],1);
        g_sp[pos] = make_int2(colk, __float_as_int(g_alpha[p]));
    }
}

// ---------------- W = A*S (sparse rows): count, fill ----------------
__global__ void k_wcount(){
    int s = blockIdx.x*blockDim.x + threadIdx.x;
    if (s >= N_) return;
    int ob=g_orowptr[s], oe=g_orowptr[s+1];
    int total=0;
    for (int f=ob;f<oe;f++){
        int j = g_oadj[f];
        total += g_srowptr[j+1]-g_srowptr[j];
    }
    g_wcnt[s]=total;
}
__global__ void k_wfill(){
    int s = blockIdx.x*8 + (threadIdx.x>>5);
    int lane = threadIdx.x & 31;
    int wpos = g_wrowptr[s];
    int ob=g_orowptr[s], oe=g_orowptr[s+1];
    for (int f=ob;f<oe;f++){
        int j = g_oadj[f];
        int sb=g_srowptr[j], len=g_srowptr[j+1]-sb;
        for (int q=lane;q<len;q+=32) g_W[wpos+q]=g_sp[sb+q];
        wpos += len;
    }
}

// ---------------- Ac row gather with smem fp32 accumulator -> fp16 store ----------------
__global__ void k_AcRow(){
    __shared__ __align__(16) float acc[K_];
    int k = blockIdx.x, tid = threadIdx.x;
    int lane = tid & 31, w = tid >> 5, nw = blockDim.x >> 5;
    {
        float4 z = make_float4(0,0,0,0);
        float4* a4 = (float4*)acc;
        #pragma unroll
        for (int m=0;m<2;m++) a4[tid + m*512] = z;
    }
    __syncthreads();
    int d = g_ncol[k];
    int ib = g_rowptr[d], ie = g_rowptr[d+1];
    for (int p=ib+w; p<ie; p+=nw){
        int s = g_adj[p].x;
        float ae = g_alpha[p];
        int wb = g_wrowptr[s], we = g_wrowptr[s+1];
        int q = wb + lane;
        for (; q+32 < we; q += 64){
            int2 e0 = g_W[q];
            int2 e1 = g_W[q+32];
            atomicAdd(&acc[e0.x], ae*__int_as_float(e0.y));
            atomicAdd(&acc[e1.x], ae*__int_as_float(e1.y));
        }
        if (q < we){
            int2 e0 = g_W[q];
            atomicAdd(&acc[e0.x], ae*__int_as_float(e0.y));
        }
    }
    __syncthreads();
    __half2* orow = (__half2*)(g_Ach + (size_t)k*K_);
    #pragma unroll
    for (int m=0;m<4;m++){
        int i2 = tid + m*512;
        orow[i2] = __floats2half2_rn(acc[2*i2], acc[2*i2+1]);
    }
}

// ---------------- fused: build 16 P-rows (fp32 acc -> fp16 smem), adj = P S^T ----------------
__global__ void __launch_bounds__(1024, 1) k_adjF(float* __restrict__ adj){
    extern __shared__ __align__(16) char PshB[];
    int2* sc = (int2*)(PshB + 131072);
    int i0 = blockIdx.x*AR, tid = threadIdx.x;

    int qb0 = g_srowptr[i0];
    int qend = g_srowptr[i0+AR];
    int total = qend - qb0;
    int ncache = total < SCACHE ? total : SCACHE;
    for (int q=tid; q<ncache; q+=1024) sc[q] = g_sp[qb0+q];
    __syncthreads();

    #pragma unroll 1
    for (int rp=0;rp<8;rp++){
        float accA[4], accB[4];
        #pragma unroll
        for (int m=0;m<4;m++){ accA[m]=0.f; accB[m]=0.f; }
        #pragma unroll 1
        for (int half_i=0; half_i<2; half_i++){
            int i = i0 + 2*rp + half_i;
            float* acc = half_i ? accB : accA;
            int qb=g_srowptr[i], qe=g_srowptr[i+1];
            if (qe - qb0 <= ncache){
                int base = qb - qb0, len = qe - qb;
                #pragma unroll 2
                for (int q=0;q<len;q++){
                    int2 kp = sc[base+q];
                    float a = __int_as_float(kp.y);
                    const __half2* row = (const __half2*)(g_Ach + (size_t)kp.x*K_);
                    #pragma unroll
                    for (int m=0;m<2;m++){
                        float2 f = __half22float2(row[tid + 1024*m]);
                        acc[2*m]   += a*f.x;
                        acc[2*m+1] += a*f.y;
                    }
                }
            } else {
                for (int q=qb;q<qe;q++){
                    int2 kp = g_sp[q];
                    float a = __int_as_float(kp.y);
                    const __half2* row = (const __half2*)(g_Ach + (size_t)kp.x*K_);
                    #pragma unroll
                    for (int m=0;m<2;m++){
                        float2 f = __half22float2(row[tid + 1024*m]);
                        acc[2*m]   += a*f.x;
                        acc[2*m+1] += a*f.y;
                    }
                }
            }
        }
        char* region = PshB + ((rp<4)? 0 : 65536);
        int woff = (rp & 3)*4;
        #pragma unroll
        for (int m=0;m<2;m++){
            int k0 = 2*(tid + 1024*m);
            *(__half2*)(region + (size_t)k0*16 + woff)     = __floats2half2_rn(accA[2*m],   accB[2*m]);
            *(__half2*)(region + (size_t)(k0+1)*16 + woff) = __floats2half2_rn(accA[2*m+1], accB[2*m+1]);
        }
    }
    __syncthreads();
    for (int j=tid; j<N_; j+=1024){
        float b[16];
        #pragma unroll
        for (int r=0;r<16;r++) b[r]=0.f;
        int qb = g_srowptr[j], qe = g_srowptr[j+1];
        for (int q=qb;q<qe;q++){
            int2 kp = g_sp[q];
            float a = __int_as_float(kp.y);
            uint4 lo = *(const uint4*)(PshB + (size_t)kp.x*16);
            uint4 hi = *(const uint4*)(PshB + 65536 + (size_t)kp.x*16);
            float2 f;
            f = __half22float2(*(__half2*)&lo.x); b[0] += a*f.x; b[1] += a*f.y;
            f = __half22float2(*(__half2*)&lo.y); b[2] += a*f.x; b[3] += a*f.y;
            f = __half22float2(*(__half2*)&lo.z); b[4] += a*f.x; b[5] += a*f.y;
            f = __half22float2(*(__half2*)&lo.w); b[6] += a*f.x; b[7] += a*f.y;
            f = __half22float2(*(__half2*)&hi.x); b[8] += a*f.x; b[9] += a*f.y;
            f = __half22float2(*(__half2*)&hi.y); b[10]+= a*f.x; b[11]+= a*f.y;
            f = __half22float2(*(__half2*)&hi.z); b[12]+= a*f.x; b[13]+= a*f.y;
            f = __half22float2(*(__half2*)&hi.w); b[14]+= a*f.x; b[15]+= a*f.y;
        }
        #pragma unroll
        for (int r=0;r<16;r++) adj[(size_t)(i0+r)*N_ + j] = b[r];
    }
}

// x_out[i,:] = sum over S row i: alpha*xp[k,:]  (warp per row, float4)
__global__ void k_xout(float* __restrict__ out){
    int i = blockIdx.x*8 + (threadIdx.x>>5);
    int lane = threadIdx.x & 31;
    const float4* xp4 = (const float4*)g_xp;
    float4 acc = make_float4(0,0,0,0);
    int beg=g_srowptr[i], end=g_srowptr[i+1];
    for (int q=beg;q<end;q++){
        int2 kp = g_sp[q];
        float a = __int_as_float(kp.y);
        float4 v = xp4[(size_t)kp.x*32 + lane];
        acc.x += a*v.x; acc.y += a*v.y; acc.z += a*v.z; acc.w += a*v.w;
    }
    ((float4*)out)[(size_t)i*32 + lane] = acc;
}

// ---------------- host ----------------
static cudaStream_t get_s2(){
    static cudaStream_t s = 0;
    if (!s) cudaStreamCreate(&s);
    return s;
}
static cudaEvent_t get_ev(int which){
    static cudaEvent_t ev[4] = {0,0,0,0};
    if (!ev[which]) cudaEventCreateWithFlags(&ev[which], cudaEventDisableTiming);
    return ev[which];
}

extern "C" void kernel_launch(void* const* d_in, const int* in_sizes, int n_in,
                              void* d_out, int out_size){
    const float* nodes = (const float*)d_in[0];
    const int*   edges = (const int*)d_in[1];
    const int* e0 = edges;
    const int* e1 = edges + E_;
    const float* w1 = (const float*)d_in[3];  const float* b1 = (const float*)d_in[4];
    const float* w2 = (const float*)d_in[5];  const float* b2 = (const float*)d_in[6];
    const float* w3 = (const float*)d_in[7];  const float* b3 = (const float*)d_in[8];
    const float* w4 = (const float*)d_in[9];  const float* b4 = (const float*)d_in[10];
    const float* w5 = (const float*)d_in[11]; const float* b5 = (const float*)d_in[12];
    const float* wq = (const float*)d_in[13]; const float* bq = (const float*)d_in[14];
    const float* att = (const float*)d_in[15];
    const float* lw1 = (const float*)d_in[16]; const float* lb1 = (const float*)d_in[17];
    const float* lw2 = (const float*)d_in[18]; const float* lw3 = (const float*)d_in[19];

    float* out = (float*)d_out;
    float* x2out = out;
    float* adj  = out + (size_t)N_*H_;

    float *A,*B,*C,*T; int *scnt,*srowptr,*wcnt,*wrowptr;
    cudaGetSymbolAddress((void**)&A, g_bufA);
    cudaGetSymbolAddress((void**)&B, g_bufB);
    cudaGetSymbolAddress((void**)&C, g_bufC);
    cudaGetSymbolAddress((void**)&T, g_bufT);
    cudaGetSymbolAddress((void**)&scnt, g_scnt);
    cudaGetSymbolAddress((void**)&srowptr, g_srowptr);
    cudaGetSymbolAddress((void**)&wcnt, g_wcnt);
    cudaGetSymbolAddress((void**)&wrowptr, g_wrowptr);

    const int TB = 256;
    const int MB = (M_ + TB - 1)/TB;
    const int NB = (N_ + TB - 1)/TB;

    cudaStream_t s2 = get_s2();
    cudaEvent_t evF0 = get_ev(0), evJ0 = get_ev(1), evF1 = get_ev(2), evJ1 = get_ev(3);

    // fork 0: prevec + first gemm (depend only on inputs) overlap graph prep
    cudaEventRecord(evF0, 0);
    cudaStreamWaitEvent(s2, evF0, 0);
    k_prevec<<<1,128,0,s2>>>(wq, att, bq);
    k_gemm<<<128,256,0,s2>>>(nodes, w1, T);
    cudaEventRecord(evJ0, s2);

    // graph prep: dst-CSR + src-CSR with folded norms (main stream)
    k_init0<<<NB, TB>>>();
    k_count<<<MB, TB>>>(e0, e1);
    k_scan2<<<2,1024>>>();
    k_fill<<<MB, TB>>>(e0, e1);

    // encoder (needs gemm1 result)
    cudaStreamWaitEvent(0, evJ0, 0);
    k_aggr<<<N_/8,256>>>(T, b1, A, 1);
    k_gemm<<<128,256>>>(A, w2, T);
    k_aggr<<<N_/8,256>>>(T, b2, B, 1);       // B = h

    // pooling (gemm(wq)+dots algebraically folded into segdots)
    k_segdots<<<N_/8,256>>>(B, att);
    k_alpha<<<N_/8,256>>>();
    k_cxle<<<N_/8,256>>>(B, C, lw1, lw2, lw3);
    k_fit<<<NB, TB>>>(lb1);
    k_topk<<<1,256>>>();

    // S CSR (by source); scount also resets g_fill
    k_scount<<<NB, TB>>>();
    k_scan8192<<<1,1024>>>(scnt, srowptr);
    k_xpsfill<<<N_,128>>>(C);

    // fork 1: decoder branch (s2) overlaps W-build + AcRow + adjF (main)
    cudaEventRecord(evF1, 0);
    cudaStreamWaitEvent(s2, evF1, 0);
    k_xout<<<N_/8,256,0,s2>>>(A);            // A = x_out
    k_gemm<<<128,256,0,s2>>>(A, w3, T);
    k_aggr<<<N_/8,256,0,s2>>>(T, b3, B, 1);
    k_gemm<<<128,256,0,s2>>>(B, w4, T);
    k_aggr<<<N_/8,256,0,s2>>>(T, b4, A, 1);
    k_gemm<<<128,256,0,s2>>>(A, w5, T);
    k_aggr<<<N_/8,256,0,s2>>>(T, b5, x2out, 0);
    cudaEventRecord(evJ1, s2);

    // main: W = A*S sparse rows, Ac (fp16), adj
    k_wcount<<<NB, TB>>>();
    k_scan8192<<<1,1024>>>(wcnt, wrowptr);
    k_wfill<<<N_/8, 256>>>();
    k_AcRow<<<K_, 512>>>();
    cudaFuncSetAttribute(k_adjF, cudaFuncAttributeMaxDynamicSharedMemorySize, PSH_TOTAL);
    k_adjF<<<N_/AR, 1024, PSH_TOTAL>>>(adj);

    // join decoder branch
    cudaStreamWaitEvent(0, evJ1, 0);
}

// round 15
// speedup vs baseline: 1.4328x; 1.0355x over previous
#include <cuda_runtime.h>
#include <cuda_fp16.h>
#include <math.h>
#include <stdint.h>

#define N_ 8192
#define E_ 131072
#define M_ (E_ + N_)
#define H_ 128
#define K_ 4096
#define WCAP_ 3000000

#define AR 16
#define SCACHE 1024
#define PSH_TOTAL (131072 + SCACHE*8)

// ---------------- device scratch ----------------
static __device__ float g_bufA[(size_t)N_*H_];
static __device__ float g_bufB[(size_t)N_*H_];
static __device__ float g_bufC[(size_t)N_*H_];
static __device__ float g_bufT[(size_t)N_*H_];
static __device__ int   g_cnt[N_];
static __device__ int   g_ocnt[N_];
static __device__ int   g_fill[N_];
static __device__ int   g_ofill[N_];
static __device__ int   g_rowptr[N_+1];
static __device__ int   g_orowptr[N_+1];
static __device__ int2  g_adj[M_];
static __device__ int   g_oadj[M_];
static __device__ float g_alpha[M_];
static __device__ float g_aq[N_];
static __device__ float g_ah[N_];
static __device__ float g_vq[H_];
static __device__ float g_cq;
static __device__ float g_cl1[N_], g_cl2[N_], g_cl3[N_];
static __device__ float g_fit[N_];
static __device__ int   g_sel[N_];
static __device__ int   g_col[N_];
static __device__ int   g_ncol[K_];
static __device__ float g_xp[(size_t)K_*H_];
static __device__ int   g_scnt[N_];
static __device__ int   g_srowptr[N_+1];
static __device__ int2  g_sp[M_];            // exact (col k, fp32 alpha bits)
static __device__ unsigned g_spp[M_];        // packed: k | half(alpha)<<16
static __device__ int   g_wcnt[N_];
static __device__ int   g_wrowptr[N_+1];
static __device__ unsigned g_W[WCAP_];       // packed W = A*S rows
static __device__ __half g_Ach[(size_t)K_*K_];

__device__ __forceinline__ int esrc_f(const int* __restrict__ e0, int e){ return (e < E_) ? e0[e] : (e - E_); }
__device__ __forceinline__ int edst_f(const int* __restrict__ e1, int e){ return (e < E_) ? e1[e] : (e - E_); }
__device__ __forceinline__ float unp_a(unsigned v){ return __half2float(__ushort_as_half((unsigned short)(v>>16))); }

// ---------------- small utility kernels ----------------
__global__ void k_init0(){
    int i = blockIdx.x*blockDim.x + threadIdx.x;
    if (i < N_){ g_cnt[i]=0; g_ocnt[i]=0; g_fill[i]=0; g_ofill[i]=0; g_scnt[i]=0; }
}
__global__ void k_count(const int* __restrict__ e0, const int* __restrict__ e1){
    int e = blockIdx.x*blockDim.x + threadIdx.x;
    if (e < M_){
        atomicAdd(&g_cnt[edst_f(e1,e)], 1);
        atomicAdd(&g_ocnt[esrc_f(e0,e)], 1);
    }
}
__global__ void k_prevec(const float* __restrict__ wq, const float* __restrict__ att,
                         const float* __restrict__ bq){
    int k = threadIdx.x;
    float s = 0.f;
    for (int j=0;j<H_;j++) s += wq[k*H_+j]*att[j];
    g_vq[k] = s;
    if (k==0){
        float c = 0.f;
        for (int j=0;j<H_;j++) c += bq[j]*att[j];
        g_cq = c;
    }
}
__device__ __forceinline__ void scan8192_body(const int* __restrict__ in, int* __restrict__ out){
    __shared__ int wsum[32];
    int tid=threadIdx.x, lane=tid&31, wid=tid>>5;
    int4 a=((const int4*)in)[tid*2], b=((const int4*)in)[tid*2+1];
    int l[8]={a.x,a.y,a.z,a.w,b.x,b.y,b.z,b.w};
    int s=0;
    #pragma unroll
    for(int q=0;q<8;q++) s+=l[q];
    int inc=s;
    #pragma unroll
    for(int o=1;o<32;o<<=1){ int t=__shfl_up_sync(0xffffffffu,inc,o); if(lane>=o) inc+=t; }
    if(lane==31) wsum[wid]=inc;
    __syncthreads();
    if (wid==0){
        int v = wsum[lane];
        #pragma unroll
        for(int o=1;o<32;o<<=1){ int t=__shfl_up_sync(0xffffffffu,v,o); if(lane>=o) v+=t; }
        wsum[lane]=v;
    }
    __syncthreads();
    int r = inc - s + (wid? wsum[wid-1]:0);
    int4 o1,o2;
    o1.x=r; r+=l[0]; o1.y=r; r+=l[1]; o1.z=r; r+=l[2]; o1.w=r; r+=l[3];
    o2.x=r; r+=l[4]; o2.y=r; r+=l[5]; o2.z=r; r+=l[6]; o2.w=r; r+=l[7];
    ((int4*)out)[tid*2]=o1; ((int4*)out)[tid*2+1]=o2;
    if (tid==1023) out[8192]=r;
}
__global__ void k_scan8192(const int* __restrict__ in, int* __restrict__ out){
    scan8192_body(in, out);
}
__global__ void k_scan2(){
    if (blockIdx.x == 0) scan8192_body(g_cnt, g_rowptr);
    else                 scan8192_body(g_ocnt, g_orowptr);
}
__global__ void k_fill(const int* __restrict__ e0, const int* __restrict__ e1){
    int e = blockIdx.x*blockDim.x + threadIdx.x;
    if (e < M_){
        int s = esrc_f(e0,e);
        int d = edst_f(e1,e);
        float nm = rsqrtf((float)g_cnt[s]) * rsqrtf((float)g_cnt[d]);
        int pos = g_rowptr[d] + atomicAdd(&g_fill[d],1);
        g_adj[pos] = make_int2(s, __float_as_int(nm));
        int opos = g_orowptr[s] + atomicAdd(&g_ofill[s],1);
        g_oadj[opos] = d;
    }
}

// ---------------- 8192x128 @ 128x128 GEMM ----------------
__global__ void k_gemm(const float* __restrict__ x, const float* __restrict__ w, float* __restrict__ y){
    __shared__ __align__(16) float xs[128*64];
    int r0 = blockIdx.x*64;
    int tid = threadIdx.x;
    for (int idx=tid; idx<64*128; idx+=256){
        int r = idx >> 7;
        int kk = idx & 127;
        xs[kk*64 + r] = x[(size_t)(r0+r)*128 + kk];
    }
    __syncthreads();
    int cg = tid & 31;
    int rg = tid >> 5;
    float acc[8][4];
    #pragma unroll
    for(int r=0;r<8;r++){ acc[r][0]=0.f;acc[r][1]=0.f;acc[r][2]=0.f;acc[r][3]=0.f; }
    #pragma unroll 4
    for(int kk=0;kk<128;kk++){
        float4 wv = *(const float4*)(w + kk*128 + cg*4);
        float4 x0 = *(const float4*)(xs + kk*64 + rg*8);
        float4 x1 = *(const float4*)(xs + kk*64 + rg*8 + 4);
        float xv[8] = {x0.x,x0.y,x0.z,x0.w,x1.x,x1.y,x1.z,x1.w};
        #pragma unroll
        for(int r=0;r<8;r++){
            acc[r][0] += xv[r]*wv.x; acc[r][1] += xv[r]*wv.y;
            acc[r][2] += xv[r]*wv.z; acc[r][3] += xv[r]*wv.w;
        }
    }
    #pragma unroll
    for(int r=0;r<8;r++){
        float4 o = make_float4(acc[r][0],acc[r][1],acc[r][2],acc[r][3]);
        *(float4*)(y + (size_t)(r0+rg*8+r)*128 + cg*4) = o;
    }
}

// ---------------- GCN aggregation ----------------
__global__ void k_aggr(const float* __restrict__ y, const float* __restrict__ b,
                       float* __restrict__ out, int dotanh){
    int d = blockIdx.x*8 + (threadIdx.x>>5);
    int lane = threadIdx.x & 31;
    const float4* y4 = (const float4*)y;
    float4 acc = ((const float4*)b)[lane];
    int beg = g_rowptr[d], end = g_rowptr[d+1];
    int p = beg;
    for (; p+1 < end; p += 2){
        int2 a0 = g_adj[p], a1 = g_adj[p+1];
        float n0 = __int_as_float(a0.y), n1 = __int_as_float(a1.y);
        float4 v0 = y4[(size_t)a0.x*32 + lane];
        float4 v1 = y4[(size_t)a1.x*32 + lane];
        acc.x += n0*v0.x + n1*v1.x;
        acc.y += n0*v0.y + n1*v1.y;
        acc.z += n0*v0.z + n1*v1.z;
        acc.w += n0*v0.w + n1*v1.w;
    }
    if (p < end){
        int2 a0 = g_adj[p];
        float n0 = __int_as_float(a0.y);
        float4 v0 = y4[(size_t)a0.x*32 + lane];
        acc.x += n0*v0.x; acc.y += n0*v0.y; acc.z += n0*v0.z; acc.w += n0*v0.w;
    }
    if (dotanh){
        acc.x = tanhf(acc.x); acc.y = tanhf(acc.y);
        acc.z = tanhf(acc.z); acc.w = tanhf(acc.w);
    }
    ((float4*)out)[(size_t)d*32 + lane] = acc;
}

// ---------------- fused segmax + aq/ah dots ----------------
__global__ void k_segdots(const float* __restrict__ h, const float* __restrict__ att){
    int d = blockIdx.x*8 + (threadIdx.x>>5);
    int lane = threadIdx.x & 31;
    const float4* h4 = (const float4*)h;
    float4 mx = make_float4(-INFINITY,-INFINITY,-INFINITY,-INFINITY);
    int beg = g_rowptr[d], end = g_rowptr[d+1];
    for (int p=beg; p<end; p++){
        float4 v = h4[(size_t)g_adj[p].x*32 + lane];
        mx.x = fmaxf(mx.x,v.x); mx.y = fmaxf(mx.y,v.y);
        mx.z = fmaxf(mx.z,v.z); mx.w = fmaxf(mx.w,v.w);
    }
    float4 vv = ((const float4*)g_vq)[lane];
    float4 a2 = ((const float4*)att)[32+lane];
    float4 hd = h4[(size_t)d*32 + lane];
    float s1 = mx.x*vv.x + mx.y*vv.y + mx.z*vv.z + mx.w*vv.w;
    float s2 = hd.x*a2.x + hd.y*a2.y + hd.z*a2.z + hd.w*a2.w;
    #pragma unroll
    for (int o=16;o;o>>=1){
        s1 += __shfl_down_sync(0xffffffffu,s1,o);
        s2 += __shfl_down_sync(0xffffffffu,s2,o);
    }
    if (!lane){ g_aq[d]=s1+g_cq; g_ah[d]=s2; }
}

// ---------------- alpha softmax ----------------
__global__ void k_alpha(){
    int d = blockIdx.x*8 + (threadIdx.x>>5);
    int lane = threadIdx.x & 31;
    int beg = g_rowptr[d], end = g_rowptr[d+1];
    float aqd = g_aq[d];
    float mx = -INFINITY;
    for (int p=beg+lane; p<end; p+=32){
        float sc = aqd + g_ah[g_adj[p].x];
        sc = sc > 0.f ? sc : 0.2f*sc;
        mx = fmaxf(mx, sc);
    }
    #pragma unroll
    for (int o=16;o;o>>=1) mx = fmaxf(mx, __shfl_xor_sync(0xffffffffu, mx, o));
    float sm = 0.f;
    for (int p=beg+lane; p<end; p+=32){
        float sc = aqd + g_ah[g_adj[p].x];
        sc = sc > 0.f ? sc : 0.2f*sc;
        sm += __expf(sc - mx);
    }
    #pragma unroll
    for (int o=16;o;o>>=1) sm += __shfl_xor_sync(0xffffffffu, sm, o);
    float inv = 1.f/sm;
    for (int p=beg+lane; p<end; p+=32){
        float sc = aqd + g_ah[g_adj[p].x];
        sc = sc > 0.f ? sc : 0.2f*sc;
        g_alpha[p] = __expf(sc - mx)*inv;
    }
}

// ---------------- cx + fused LE dots ----------------
__global__ void k_cxle(const float* __restrict__ h, float* __restrict__ cx,
                       const float* __restrict__ lw1, const float* __restrict__ lw2,
                       const float* __restrict__ lw3){
    int d = blockIdx.x*8 + (threadIdx.x>>5);
    int lane = threadIdx.x & 31;
    const float4* h4 = (const float4*)h;
    float4 acc = make_float4(0,0,0,0);
    int beg = g_rowptr[d], end = g_rowptr[d+1];
    int p = beg;
    for (; p+1 < end; p += 2){
        float a0 = g_alpha[p], a1 = g_alpha[p+1];
        float4 v0 = h4[(size_t)g_adj[p].x*32 + lane];
        float4 v1 = h4[(size_t)g_adj[p+1].x*32 + lane];
        acc.x += a0*v0.x + a1*v1.x;
        acc.y += a0*v0.y + a1*v1.y;
        acc.z += a0*v0.z + a1*v1.z;
        acc.w += a0*v0.w + a1*v1.w;
    }
    if (p < end){
        float a0 = g_alpha[p];
        float4 v0 = h4[(size_t)g_adj[p].x*32 + lane];
        acc.x += a0*v0.x; acc.y += a0*v0.y; acc.z += a0*v0.z; acc.w += a0*v0.w;
    }
    ((float4*)cx)[(size_t)d*32 + lane] = acc;
    float4 w1v = ((const float4*)lw1)[lane];
    float4 w2v = ((const float4*)lw2)[lane];
    float4 w3v = ((const float4*)lw3)[lane];
    float s1 = acc.x*w1v.x + acc.y*w1v.y + acc.z*w1v.z + acc.w*w1v.w;
    float s2 = acc.x*w2v.x + acc.y*w2v.y + acc.z*w2v.z + acc.w*w2v.w;
    float s3 = acc.x*w3v.x + acc.y*w3v.y + acc.z*w3v.z + acc.w*w3v.w;
    #pragma unroll
    for (int o=16;o;o>>=1){
        s1 += __shfl_down_sync(0xffffffffu,s1,o);
        s2 += __shfl_down_sync(0xffffffffu,s2,o);
        s3 += __shfl_down_sync(0xffffffffu,s3,o);
    }
    if (!lane){ g_cl1[d]=s1; g_cl2[d]=s2; g_cl3[d]=s3; }
}

__global__ void k_fit(const float* __restrict__ lb1){
    int d = blockIdx.x*blockDim.x + threadIdx.x;
    if (d >= N_) return;
    int beg=g_rowptr[d], end=g_rowptr[d+1];
    float s = 0.f;
    for (int q=beg;q<end;q++) s += g_cl3[g_adj[q].x];
    float aggr = (float)(end-beg)*g_cl2[d] - s;
    float z = g_cl1[d] + lb1[0] + aggr;
    g_fit[d] = 1.f/(1.f + __expf(-z));
}

// ---------------- top-K via 4x8-bit histogram radix select ----------------
__global__ void k_topk(){
    __shared__ int hist[256];
    __shared__ int wred[8];
    __shared__ unsigned s_pref;
    __shared__ int s_need;
    int tid=threadIdx.x, lane=tid&31, wid=tid>>5;
    if (tid==0){ s_pref=0u; s_need=K_; }
    unsigned keys[32];
    #pragma unroll
    for (int q=0;q<32;q++){
        unsigned u=__float_as_uint(g_fit[tid*32+q]);
        keys[q] = (u & 0x80000000u) ? ~u : (u | 0x80000000u);
    }
    __syncthreads();
    for (int round=0; round<4; round++){
        int shift = 24 - 8*round;
        hist[tid]=0;
        __syncthreads();
        unsigned pref = s_pref;
        #pragma unroll
        for (int q=0;q<32;q++){
            unsigned k = keys[q];
            bool match = (round==0) || ((k >> (shift+8)) == (pref >> (shift+8)));
            if (match) atomicAdd(&hist[(k>>shift)&0xFFu], 1);
        }
        __syncthreads();
        int mine = hist[255-tid];
        int v = mine;
        #pragma unroll
        for (int o=1;o<32;o<<=1){ int t2=__shfl_up_sync(0xffffffffu,v,o); if(lane>=o) v+=t2; }
        if (lane==31) wred[wid]=v;
        __syncthreads();
        int woff=0;
        #pragma unroll
        for (int w=0;w<8;w++) if (w<wid) woff+=wred[w];
        v += woff;
        int need0 = s_need;
        int vex = v - mine;
        if (v >= need0 && vex < need0){
            s_pref = s_pref | ((unsigned)(255-tid) << shift);
            s_need = need0 - vex;
        }
        __syncthreads();
    }
    unsigned thr = s_pref;
    int need = s_need;
    int tcnt=0;
    #pragma unroll
    for (int q=0;q<32;q++) tcnt += (keys[q]==thr);
    int v=tcnt;
    #pragma unroll
    for (int o=1;o<32;o<<=1){ int t2=__shfl_up_sync(0xffffffffu,v,o); if(lane>=o) v+=t2; }
    if (lane==31) wred[wid]=v;
    __syncthreads();
    int woff=0;
    #pragma unroll
    for (int w=0;w<8;w++) if (w<wid) woff+=wred[w];
    int rank = v - tcnt + woff;
    int scnt=0;
    int selq[32];
    #pragma unroll
    for (int q=0;q<32;q++){
        unsigned k=keys[q];
        bool eq = (k==thr);
        int s = (k>thr) || (eq && rank < need);
        if (eq) rank++;
        selq[q]=s;
        g_sel[tid*32+q]=s;
        scnt+=s;
    }
    __syncthreads();
    v=scnt;
    #pragma unroll
    for (int o=1;o<32;o<<=1){ int t2=__shfl_up_sync(0xffffffffu,v,o); if(lane>=o) v+=t2; }
    if (lane==31) wred[wid]=v;
    __syncthreads();
    woff=0;
    #pragma unroll
    for (int w=0;w<8;w++) if (w<wid) woff+=wred[w];
    int base = v - scnt + woff;
    #pragma unroll
    for (int q=0;q<32;q++){
        int i = tid*32+q;
        if (selq[q]){ g_col[i]=base; g_ncol[base]=i; base++; }
        else g_col[i]=-1;
    }
}

// ---------------- S CSR count (+ g_fill reset) ----------------
__global__ void k_scount(){
    int d = blockIdx.x*blockDim.x + threadIdx.x;
    if (d >= N_) return;
    g_fill[d]=0;
    if (!g_sel[d]) return;
    int beg=g_rowptr[d], end=g_rowptr[d+1];
    for (int p=beg;p<end;p++) atomicAdd(&g_scnt[g_adj[p].x], 1);
}
// merged xp write + sfill scatter (exact + packed)
__global__ void k_xpsfill(const float* __restrict__ cx){
    int d = blockIdx.x, t = threadIdx.x;
    if (!g_sel[d]) return;
    int colk = g_col[d];
    g_xp[(size_t)colk*128 + t] = cx[(size_t)d*128 + t] * g_fit[d];
    int beg=g_rowptr[d], end=g_rowptr[d+1];
    for (int p=beg+t; p<end; p+=128){
        int s = g_adj[p].x;
        float a = g_alpha[p];
        int pos = g_srowptr[s] + atomicAdd(&g_fill[s],1);
        g_sp[pos] = make_int2(colk, __float_as_int(a));
        unsigned hb = (unsigned)__half_as_ushort(__float2half_rn(a));
        g_spp[pos] = (unsigned)colk | (hb << 16);
    }
}

// ---------------- W = A*S (packed) ----------------
__global__ void k_wcount(){
    int s = blockIdx.x*blockDim.x + threadIdx.x;
    if (s >= N_) return;
    int ob=g_orowptr[s], oe=g_orowptr[s+1];
    int total=0;
    for (int f=ob;f<oe;f++){
        int j = g_oadj[f];
        total += g_srowptr[j+1]-g_srowptr[j];
    }
    g_wcnt[s]=total;
}
__global__ void k_wfill(){
    int s = blockIdx.x*8 + (threadIdx.x>>5);
    int lane = threadIdx.x & 31;
    int wpos = g_wrowptr[s];
    int ob=g_orowptr[s], oe=g_orowptr[s+1];
    for (int f=ob;f<oe;f++){
        int j = g_oadj[f];
        int sb=g_srowptr[j], len=g_srowptr[j+1]-sb;
        for (int q=lane;q<len;q+=32) g_W[wpos+q]=g_spp[sb+q];
        wpos += len;
    }
}

// ---------------- Ac row gather (packed W) ----------------
__global__ void k_AcRow(){
    __shared__ __align__(16) float acc[K_];
    int k = blockIdx.x, tid = threadIdx.x;
    int lane = tid & 31, w = tid >> 5, nw = blockDim.x >> 5;
    {
        float4 z = make_float4(0,0,0,0);
        float4* a4 = (float4*)acc;
        #pragma unroll
        for (int m=0;m<2;m++) a4[tid + m*512] = z;
    }
    __syncthreads();
    int d = g_ncol[k];
    int ib = g_rowptr[d], ie = g_rowptr[d+1];
    for (int p=ib+w; p<ie; p+=nw){
        int s = g_adj[p].x;
        float ae = g_alpha[p];
        int wb = g_wrowptr[s], we = g_wrowptr[s+1];
        int q = wb + lane;
        for (; q+32 < we; q += 64){
            unsigned e0 = g_W[q];
            unsigned e1 = g_W[q+32];
            atomicAdd(&acc[e0 & 0xFFFFu], ae*unp_a(e0));
            atomicAdd(&acc[e1 & 0xFFFFu], ae*unp_a(e1));
        }
        if (q < we){
            unsigned e0 = g_W[q];
            atomicAdd(&acc[e0 & 0xFFFFu], ae*unp_a(e0));
        }
    }
    __syncthreads();
    __half2* orow = (__half2*)(g_Ach + (size_t)k*K_);
    #pragma unroll
    for (int m=0;m<4;m++){
        int i2 = tid + m*512;
        orow[i2] = __floats2half2_rn(acc[2*i2], acc[2*i2+1]);
    }
}

// ---------------- fused adjF: P-build (exact S) + j-loop (packed S) ----------------
__global__ void __launch_bounds__(1024, 1) k_adjF(float* __restrict__ adj){
    extern __shared__ __align__(16) char PshB[];
    int2* sc = (int2*)(PshB + 131072);
    int i0 = blockIdx.x*AR, tid = threadIdx.x;

    int qb0 = g_srowptr[i0];
    int qend = g_srowptr[i0+AR];
    int total = qend - qb0;
    int ncache = total < SCACHE ? total : SCACHE;
    for (int q=tid; q<ncache; q+=1024) sc[q] = g_sp[qb0+q];
    __syncthreads();

    #pragma unroll 1
    for (int rp=0;rp<8;rp++){
        float accA[4], accB[4];
        #pragma unroll
        for (int m=0;m<4;m++){ accA[m]=0.f; accB[m]=0.f; }
        #pragma unroll 1
        for (int half_i=0; half_i<2; half_i++){
            int i = i0 + 2*rp + half_i;
            float* acc = half_i ? accB : accA;
            int qb=g_srowptr[i], qe=g_srowptr[i+1];
            if (qe - qb0 <= ncache){
                int base = qb - qb0, len = qe - qb;
                #pragma unroll 2
                for (int q=0;q<len;q++){
                    int2 kp = sc[base+q];
                    float a = __int_as_float(kp.y);
                    const __half2* row = (const __half2*)(g_Ach + (size_t)kp.x*K_);
                    #pragma unroll
                    for (int m=0;m<2;m++){
                        float2 f = __half22float2(row[tid + 1024*m]);
                        acc[2*m]   += a*f.x;
                        acc[2*m+1] += a*f.y;
                    }
                }
            } else {
                for (int q=qb;q<qe;q++){
                    int2 kp = g_sp[q];
                    float a = __int_as_float(kp.y);
                    const __half2* row = (const __half2*)(g_Ach + (size_t)kp.x*K_);
                    #pragma unroll
                    for (int m=0;m<2;m++){
                        float2 f = __half22float2(row[tid + 1024*m]);
                        acc[2*m]   += a*f.x;
                        acc[2*m+1] += a*f.y;
                    }
                }
            }
        }
        char* region = PshB + ((rp<4)? 0 : 65536);
        int woff = (rp & 3)*4;
        #pragma unroll
        for (int m=0;m<2;m++){
            int k0 = 2*(tid + 1024*m);
            *(__half2*)(region + (size_t)k0*16 + woff)     = __floats2half2_rn(accA[2*m],   accB[2*m]);
            *(__half2*)(region + (size_t)(k0+1)*16 + woff) = __floats2half2_rn(accA[2*m+1], accB[2*m+1]);
        }
    }
    __syncthreads();
    for (int j=tid; j<N_; j+=1024){
        float b[16];
        #pragma unroll
        for (int r=0;r<16;r++) b[r]=0.f;
        int qb = g_srowptr[j], qe = g_srowptr[j+1];
        for (int q=qb;q<qe;q++){
            unsigned v = g_spp[q];
            int kk = v & 0xFFFFu;
            float a = unp_a(v);
            uint4 lo = *(const uint4*)(PshB + (size_t)kk*16);
            uint4 hi = *(const uint4*)(PshB + 65536 + (size_t)kk*16);
            float2 f;
            f = __half22float2(*(__half2*)&lo.x); b[0] += a*f.x; b[1] += a*f.y;
            f = __half22float2(*(__half2*)&lo.y); b[2] += a*f.x; b[3] += a*f.y;
            f = __half22float2(*(__half2*)&lo.z); b[4] += a*f.x; b[5] += a*f.y;
            f = __half22float2(*(__half2*)&lo.w); b[6] += a*f.x; b[7] += a*f.y;
            f = __half22float2(*(__half2*)&hi.x); b[8] += a*f.x; b[9] += a*f.y;
            f = __half22float2(*(__half2*)&hi.y); b[10]+= a*f.x; b[11]+= a*f.y;
            f = __half22float2(*(__half2*)&hi.z); b[12]+= a*f.x; b[13]+= a*f.y;
            f = __half22float2(*(__half2*)&hi.w); b[14]+= a*f.x; b[15]+= a*f.y;
        }
        #pragma unroll
        for (int r=0;r<16;r++) adj[(size_t)(i0+r)*N_ + j] = b[r];
    }
}

// x_out (exact alpha)
__global__ void k_xout(float* __restrict__ out){
    int i = blockIdx.x*8 + (threadIdx.x>>5);
    int lane = threadIdx.x & 31;
    const float4* xp4 = (const float4*)g_xp;
    float4 acc = make_float4(0,0,0,0);
    int beg=g_srowptr[i], end=g_srowptr[i+1];
    for (int q=beg;q<end;q++){
        int2 kp = g_sp[q];
        float a = __int_as_float(kp.y);
        float4 v = xp4[(size_t)kp.x*32 + lane];
        acc.x += a*v.x; acc.y += a*v.y; acc.z += a*v.z; acc.w += a*v.w;
    }
    ((float4*)out)[(size_t)i*32 + lane] = acc;
}

// ---------------- host ----------------
static cudaStream_t get_s2(){
    static cudaStream_t s = 0;
    if (!s) cudaStreamCreate(&s);
    return s;
}
static cudaEvent_t get_ev(int which){
    static cudaEvent_t ev[4] = {0,0,0,0};
    if (!ev[which]) cudaEventCreateWithFlags(&ev[which], cudaEventDisableTiming);
    return ev[which];
}

extern "C" void kernel_launch(void* const* d_in, const int* in_sizes, int n_in,
                              void* d_out, int out_size){
    const float* nodes = (const float*)d_in[0];
    const int*   edges = (const int*)d_in[1];
    const int* e0 = edges;
    const int* e1 = edges + E_;
    const float* w1 = (const float*)d_in[3];  const float* b1 = (const float*)d_in[4];
    const float* w2 = (const float*)d_in[5];  const float* b2 = (const float*)d_in[6];
    const float* w3 = (const float*)d_in[7];  const float* b3 = (const float*)d_in[8];
    const float* w4 = (const float*)d_in[9];  const float* b4 = (const float*)d_in[10];
    const float* w5 = (const float*)d_in[11]; const float* b5 = (const float*)d_in[12];
    const float* wq = (const float*)d_in[13]; const float* bq = (const float*)d_in[14];
    const float* att = (const float*)d_in[15];
    const float* lw1 = (const float*)d_in[16]; const float* lb1 = (const float*)d_in[17];
    const float* lw2 = (const float*)d_in[18]; const float* lw3 = (const float*)d_in[19];

    float* out = (float*)d_out;
    float* x2out = out;
    float* adj  = out + (size_t)N_*H_;

    float *A,*B,*C,*T; int *scnt,*srowptr,*wcnt,*wrowptr;
    cudaGetSymbolAddress((void**)&A, g_bufA);
    cudaGetSymbolAddress((void**)&B, g_bufB);
    cudaGetSymbolAddress((void**)&C, g_bufC);
    cudaGetSymbolAddress((void**)&T, g_bufT);
    cudaGetSymbolAddress((void**)&scnt, g_scnt);
    cudaGetSymbolAddress((void**)&srowptr, g_srowptr);
    cudaGetSymbolAddress((void**)&wcnt, g_wcnt);
    cudaGetSymbolAddress((void**)&wrowptr, g_wrowptr);

    const int TB = 256;
    const int MB = (M_ + TB - 1)/TB;
    const int NB = (N_ + TB - 1)/TB;

    cudaStream_t s2 = get_s2();
    cudaEvent_t evF0 = get_ev(0), evJ0 = get_ev(1), evF1 = get_ev(2), evJ1 = get_ev(3);

    // fork 0: prevec + first gemm overlap graph prep
    cudaEventRecord(evF0, 0);
    cudaStreamWaitEvent(s2, evF0, 0);
    k_prevec<<<1,128,0,s2>>>(wq, att, bq);
    k_gemm<<<128,256,0,s2>>>(nodes, w1, T);
    cudaEventRecord(evJ0, s2);

    // graph prep
    k_init0<<<NB, TB>>>();
    k_count<<<MB, TB>>>(e0, e1);
    k_scan2<<<2,1024>>>();
    k_fill<<<MB, TB>>>(e0, e1);

    // encoder
    cudaStreamWaitEvent(0, evJ0, 0);
    k_aggr<<<N_/8,256>>>(T, b1, A, 1);
    k_gemm<<<128,256>>>(A, w2, T);
    k_aggr<<<N_/8,256>>>(T, b2, B, 1);       // B = h

    // pooling
    k_segdots<<<N_/8,256>>>(B, att);
    k_alpha<<<N_/8,256>>>();
    k_cxle<<<N_/8,256>>>(B, C, lw1, lw2, lw3);
    k_fit<<<NB, TB>>>(lb1);
    k_topk<<<1,256>>>();

    // S CSR
    k_scount<<<NB, TB>>>();
    k_scan8192<<<1,1024>>>(scnt, srowptr);
    k_xpsfill<<<N_,128>>>(C);

    // fork 1: decoder branch overlaps W/Ac/adj
    cudaEventRecord(evF1, 0);
    cudaStreamWaitEvent(s2, evF1, 0);
    k_xout<<<N_/8,256,0,s2>>>(A);
    k_gemm<<<128,256,0,s2>>>(A, w3, T);
    k_aggr<<<N_/8,256,0,s2>>>(T, b3, B, 1);
    k_gemm<<<128,256,0,s2>>>(B, w4, T);
    k_aggr<<<N_/8,256,0,s2>>>(T, b4, A, 1);
    k_gemm<<<128,256,0,s2>>>(A, w5, T);
    k_aggr<<<N_/8,256,0,s2>>>(T, b5, x2out, 0);
    cudaEventRecord(evJ1, s2);

    // main: W (packed), Ac (fp16), adj
    k_wcount<<<NB, TB>>>();
    k_scan8192<<<1,1024>>>(wcnt, wrowptr);
    k_wfill<<<N_/8, 256>>>();
    k_AcRow<<<K_, 512>>>();
    cudaFuncSetAttribute(k_adjF, cudaFuncAttributeMaxDynamicSharedMemorySize, PSH_TOTAL);
    k_adjF<<<N_/AR, 1024, PSH_TOTAL>>>(adj);

    cudaStreamWaitEvent(0, evJ1, 0);
}

// round 16
// speedup vs baseline: 1.4453x; 1.0087x over previous
#include <cuda_runtime.h>
#include <cuda_fp16.h>
#include <math.h>
#include <stdint.h>

#define N_ 8192
#define E_ 131072
#define M_ (E_ + N_)
#define H_ 128
#define K_ 4096
#define WCAP_ 3000000

#define AR 16
#define SCACHE 1024
#define PSH_TOTAL (131072 + SCACHE*8)

// ---------------- device scratch ----------------
static __device__ float g_bufA[(size_t)N_*H_];
static __device__ float g_bufB[(size_t)N_*H_];
static __device__ float g_bufC[(size_t)N_*H_];
static __device__ float g_bufT[(size_t)N_*H_];
static __device__ int   g_cnt[N_];
static __device__ int   g_ocnt[N_];
static __device__ int   g_fill[N_];
static __device__ int   g_ofill[N_];
static __device__ int   g_rowptr[N_+1];
static __device__ int   g_orowptr[N_+1];
static __device__ int2  g_adj[M_];
static __device__ int   g_oadj[M_];
static __device__ float g_alpha[M_];
static __device__ float g_aq[N_];
static __device__ float g_ah[N_];
static __device__ float g_vq[H_];
static __device__ float g_cq;
static __device__ float g_cl1[N_], g_cl2[N_], g_cl3[N_];
static __device__ float g_fit[N_];
static __device__ int   g_sel[N_];
static __device__ int   g_col[N_];
static __device__ int   g_ncol[K_];
static __device__ float g_xp[(size_t)K_*H_];
static __device__ int   g_scnt[N_];
static __device__ int   g_srowptr[N_+1];
static __device__ int2  g_sp[M_];            // exact (col k, fp32 alpha bits)
static __device__ unsigned g_spp[M_];        // packed: k | half(alpha)<<16
static __device__ int   g_wcnt[N_];
static __device__ int   g_wrowptr[N_+1];
static __device__ unsigned g_W[WCAP_];
static __device__ __half g_Ach[(size_t)K_*K_];

__device__ __forceinline__ int esrc_f(const int* __restrict__ e0, int e){ return (e < E_) ? e0[e] : (e - E_); }
__device__ __forceinline__ int edst_f(const int* __restrict__ e1, int e){ return (e < E_) ? e1[e] : (e - E_); }
__device__ __forceinline__ float unp_a(unsigned v){ return __half2float(__ushort_as_half((unsigned short)(v>>16))); }

// ---------------- small utility kernels ----------------
__global__ void k_init0(){
    int i = blockIdx.x*blockDim.x + threadIdx.x;
    if (i < N_){ g_cnt[i]=0; g_ocnt[i]=0; g_fill[i]=0; g_ofill[i]=0; g_scnt[i]=0; }
}
__global__ void k_count(const int* __restrict__ e0, const int* __restrict__ e1){
    int e = blockIdx.x*blockDim.x + threadIdx.x;
    if (e < M_){
        atomicAdd(&g_cnt[edst_f(e1,e)], 1);
        atomicAdd(&g_ocnt[esrc_f(e0,e)], 1);
    }
}
__global__ void k_prevec(const float* __restrict__ wq, const float* __restrict__ att,
                         const float* __restrict__ bq){
    int k = threadIdx.x;
    float s = 0.f;
    for (int j=0;j<H_;j++) s += wq[k*H_+j]*att[j];
    g_vq[k] = s;
    if (k==0){
        float c = 0.f;
        for (int j=0;j<H_;j++) c += bq[j]*att[j];
        g_cq = c;
    }
}
__device__ __forceinline__ void scan8192_body(const int* __restrict__ in, int* __restrict__ out){
    __shared__ int wsum[32];
    int tid=threadIdx.x, lane=tid&31, wid=tid>>5;
    int4 a=((const int4*)in)[tid*2], b=((const int4*)in)[tid*2+1];
    int l[8]={a.x,a.y,a.z,a.w,b.x,b.y,b.z,b.w};
    int s=0;
    #pragma unroll
    for(int q=0;q<8;q++) s+=l[q];
    int inc=s;
    #pragma unroll
    for(int o=1;o<32;o<<=1){ int t=__shfl_up_sync(0xffffffffu,inc,o); if(lane>=o) inc+=t; }
    if(lane==31) wsum[wid]=inc;
    __syncthreads();
    if (wid==0){
        int v = wsum[lane];
        #pragma unroll
        for(int o=1;o<32;o<<=1){ int t=__shfl_up_sync(0xffffffffu,v,o); if(lane>=o) v+=t; }
        wsum[lane]=v;
    }
    __syncthreads();
    int r = inc - s + (wid? wsum[wid-1]:0);
    int4 o1,o2;
    o1.x=r; r+=l[0]; o1.y=r; r+=l[1]; o1.z=r; r+=l[2]; o1.w=r; r+=l[3];
    o2.x=r; r+=l[4]; o2.y=r; r+=l[5]; o2.z=r; r+=l[6]; o2.w=r; r+=l[7];
    ((int4*)out)[tid*2]=o1; ((int4*)out)[tid*2+1]=o2;
    if (tid==1023) out[8192]=r;
}
__global__ void k_scan8192(const int* __restrict__ in, int* __restrict__ out){
    scan8192_body(in, out);
}
__global__ void k_scan2(){
    if (blockIdx.x == 0) scan8192_body(g_cnt, g_rowptr);
    else                 scan8192_body(g_ocnt, g_orowptr);
}
__global__ void k_fill(const int* __restrict__ e0, const int* __restrict__ e1){
    int e = blockIdx.x*blockDim.x + threadIdx.x;
    if (e < M_){
        int s = esrc_f(e0,e);
        int d = edst_f(e1,e);
        float nm = rsqrtf((float)g_cnt[s]) * rsqrtf((float)g_cnt[d]);
        int pos = g_rowptr[d] + atomicAdd(&g_fill[d],1);
        g_adj[pos] = make_int2(s, __float_as_int(nm));
        int opos = g_orowptr[s] + atomicAdd(&g_ofill[s],1);
        g_oadj[opos] = d;
    }
}

// ---------------- 8192x128 @ 128x128 GEMM ----------------
__global__ void k_gemm(const float* __restrict__ x, const float* __restrict__ w, float* __restrict__ y){
    __shared__ __align__(16) float xs[128*64];
    int r0 = blockIdx.x*64;
    int tid = threadIdx.x;
    for (int idx=tid; idx<64*128; idx+=256){
        int r = idx >> 7;
        int kk = idx & 127;
        xs[kk*64 + r] = x[(size_t)(r0+r)*128 + kk];
    }
    __syncthreads();
    int cg = tid & 31;
    int rg = tid >> 5;
    float acc[8][4];
    #pragma unroll
    for(int r=0;r<8;r++){ acc[r][0]=0.f;acc[r][1]=0.f;acc[r][2]=0.f;acc[r][3]=0.f; }
    #pragma unroll 4
    for(int kk=0;kk<128;kk++){
        float4 wv = *(const float4*)(w + kk*128 + cg*4);
        float4 x0 = *(const float4*)(xs + kk*64 + rg*8);
        float4 x1 = *(const float4*)(xs + kk*64 + rg*8 + 4);
        float xv[8] = {x0.x,x0.y,x0.z,x0.w,x1.x,x1.y,x1.z,x1.w};
        #pragma unroll
        for(int r=0;r<8;r++){
            acc[r][0] += xv[r]*wv.x; acc[r][1] += xv[r]*wv.y;
            acc[r][2] += xv[r]*wv.z; acc[r][3] += xv[r]*wv.w;
        }
    }
    #pragma unroll
    for(int r=0;r<8;r++){
        float4 o = make_float4(acc[r][0],acc[r][1],acc[r][2],acc[r][3]);
        *(float4*)(y + (size_t)(r0+rg*8+r)*128 + cg*4) = o;
    }
}

// ---------------- GCN aggregation ----------------
__global__ void k_aggr(const float* __restrict__ y, const float* __restrict__ b,
                       float* __restrict__ out, int dotanh){
    int d = blockIdx.x*8 + (threadIdx.x>>5);
    int lane = threadIdx.x & 31;
    const float4* y4 = (const float4*)y;
    float4 acc = ((const float4*)b)[lane];
    int beg = g_rowptr[d], end = g_rowptr[d+1];
    int p = beg;
    for (; p+1 < end; p += 2){
        int2 a0 = g_adj[p], a1 = g_adj[p+1];
        float n0 = __int_as_float(a0.y), n1 = __int_as_float(a1.y);
        float4 v0 = y4[(size_t)a0.x*32 + lane];
        float4 v1 = y4[(size_t)a1.x*32 + lane];
        acc.x += n0*v0.x + n1*v1.x;
        acc.y += n0*v0.y + n1*v1.y;
        acc.z += n0*v0.z + n1*v1.z;
        acc.w += n0*v0.w + n1*v1.w;
    }
    if (p < end){
        int2 a0 = g_adj[p];
        float n0 = __int_as_float(a0.y);
        float4 v0 = y4[(size_t)a0.x*32 + lane];
        acc.x += n0*v0.x; acc.y += n0*v0.y; acc.z += n0*v0.z; acc.w += n0*v0.w;
    }
    if (dotanh){
        acc.x = tanhf(acc.x); acc.y = tanhf(acc.y);
        acc.z = tanhf(acc.z); acc.w = tanhf(acc.w);
    }
    ((float4*)out)[(size_t)d*32 + lane] = acc;
}

// ---------------- fused segmax + aq/ah dots ----------------
__global__ void k_segdots(const float* __restrict__ h, const float* __restrict__ att){
    int d = blockIdx.x*8 + (threadIdx.x>>5);
    int lane = threadIdx.x & 31;
    const float4* h4 = (const float4*)h;
    float4 mx = make_float4(-INFINITY,-INFINITY,-INFINITY,-INFINITY);
    int beg = g_rowptr[d], end = g_rowptr[d+1];
    for (int p=beg; p<end; p++){
        float4 v = h4[(size_t)g_adj[p].x*32 + lane];
        mx.x = fmaxf(mx.x,v.x); mx.y = fmaxf(mx.y,v.y);
        mx.z = fmaxf(mx.z,v.z); mx.w = fmaxf(mx.w,v.w);
    }
    float4 vv = ((const float4*)g_vq)[lane];
    float4 a2 = ((const float4*)att)[32+lane];
    float4 hd = h4[(size_t)d*32 + lane];
    float s1 = mx.x*vv.x + mx.y*vv.y + mx.z*vv.z + mx.w*vv.w;
    float s2 = hd.x*a2.x + hd.y*a2.y + hd.z*a2.z + hd.w*a2.w;
    #pragma unroll
    for (int o=16;o;o>>=1){
        s1 += __shfl_down_sync(0xffffffffu,s1,o);
        s2 += __shfl_down_sync(0xffffffffu,s2,o);
    }
    if (!lane){ g_aq[d]=s1+g_cq; g_ah[d]=s2; }
}

// ---------------- fused alpha softmax + cx + LE dots (warp per dst) ----------------
__global__ void k_acx(const float* __restrict__ h, float* __restrict__ cx,
                      const float* __restrict__ lw1, const float* __restrict__ lw2,
                      const float* __restrict__ lw3){
    int d = blockIdx.x*8 + (threadIdx.x>>5);
    int lane = threadIdx.x & 31;
    int beg = g_rowptr[d], end = g_rowptr[d+1];
    float aqd = g_aq[d];
    float mx = -INFINITY;
    for (int p=beg+lane; p<end; p+=32){
        float sc = aqd + g_ah[g_adj[p].x];
        sc = sc > 0.f ? sc : 0.2f*sc;
        mx = fmaxf(mx, sc);
    }
    #pragma unroll
    for (int o=16;o;o>>=1) mx = fmaxf(mx, __shfl_xor_sync(0xffffffffu, mx, o));
    float sm = 0.f;
    for (int p=beg+lane; p<end; p+=32){
        float sc = aqd + g_ah[g_adj[p].x];
        sc = sc > 0.f ? sc : 0.2f*sc;
        sm += __expf(sc - mx);
    }
    #pragma unroll
    for (int o=16;o;o>>=1) sm += __shfl_xor_sync(0xffffffffu, sm, o);
    float inv = 1.f/sm;
    for (int p=beg+lane; p<end; p+=32){
        float sc = aqd + g_ah[g_adj[p].x];
        sc = sc > 0.f ? sc : 0.2f*sc;
        g_alpha[p] = __expf(sc - mx)*inv;
    }
    __syncwarp();
    // cx pass (alpha re-reads hit L1)
    const float4* h4 = (const float4*)h;
    float4 acc = make_float4(0,0,0,0);
    int p = beg;
    for (; p+1 < end; p += 2){
        float a0 = g_alpha[p], a1 = g_alpha[p+1];
        float4 v0 = h4[(size_t)g_adj[p].x*32 + lane];
        float4 v1 = h4[(size_t)g_adj[p+1].x*32 + lane];
        acc.x += a0*v0.x + a1*v1.x;
        acc.y += a0*v0.y + a1*v1.y;
        acc.z += a0*v0.z + a1*v1.z;
        acc.w += a0*v0.w + a1*v1.w;
    }
    if (p < end){
        float a0 = g_alpha[p];
        float4 v0 = h4[(size_t)g_adj[p].x*32 + lane];
        acc.x += a0*v0.x; acc.y += a0*v0.y; acc.z += a0*v0.z; acc.w += a0*v0.w;
    }
    ((float4*)cx)[(size_t)d*32 + lane] = acc;
    float4 w1v = ((const float4*)lw1)[lane];
    float4 w2v = ((const float4*)lw2)[lane];
    float4 w3v = ((const float4*)lw3)[lane];
    float s1 = acc.x*w1v.x + acc.y*w1v.y + acc.z*w1v.z + acc.w*w1v.w;
    float s2 = acc.x*w2v.x + acc.y*w2v.y + acc.z*w2v.z + acc.w*w2v.w;
    float s3 = acc.x*w3v.x + acc.y*w3v.y + acc.z*w3v.z + acc.w*w3v.w;
    #pragma unroll
    for (int o=16;o;o>>=1){
        s1 += __shfl_down_sync(0xffffffffu,s1,o);
        s2 += __shfl_down_sync(0xffffffffu,s2,o);
        s3 += __shfl_down_sync(0xffffffffu,s3,o);
    }
    if (!lane){ g_cl1[d]=s1; g_cl2[d]=s2; g_cl3[d]=s3; }
}

// fit: warp per 4 dst (lanes 0-7 per dst -> better MLP than per-thread serial)
__global__ void k_fit(const float* __restrict__ lb1){
    int w = (blockIdx.x*blockDim.x + threadIdx.x) >> 5;
    int lane = threadIdx.x & 31;
    int d = w*4 + (lane>>3);
    int sub = lane & 7;
    if (d >= N_) return;
    int beg=g_rowptr[d], end=g_rowptr[d+1];
    float s = 0.f;
    for (int q=beg+sub;q<end;q+=8) s += g_cl3[g_adj[q].x];
    #pragma unroll
    for (int o=4;o;o>>=1) s += __shfl_down_sync(0xffffffffu, s, o, 8);
    if (!sub){
        float aggr = (float)(end-beg)*g_cl2[d] - s;
        float z = g_cl1[d] + lb1[0] + aggr;
        g_fit[d] = 1.f/(1.f + __expf(-z));
    }
}

// ---------------- top-K via 4x8-bit histogram radix select ----------------
__global__ void k_topk(){
    __shared__ int hist[256];
    __shared__ int wred[8];
    __shared__ unsigned s_pref;
    __shared__ int s_need;
    int tid=threadIdx.x, lane=tid&31, wid=tid>>5;
    if (tid==0){ s_pref=0u; s_need=K_; }
    unsigned keys[32];
    #pragma unroll
    for (int q=0;q<32;q++){
        unsigned u=__float_as_uint(g_fit[tid*32+q]);
        keys[q] = (u & 0x80000000u) ? ~u : (u | 0x80000000u);
    }
    __syncthreads();
    for (int round=0; round<4; round++){
        int shift = 24 - 8*round;
        hist[tid]=0;
        __syncthreads();
        unsigned pref = s_pref;
        #pragma unroll
        for (int q=0;q<32;q++){
            unsigned k = keys[q];
            bool match = (round==0) || ((k >> (shift+8)) == (pref >> (shift+8)));
            if (match) atomicAdd(&hist[(k>>shift)&0xFFu], 1);
        }
        __syncthreads();
        int mine = hist[255-tid];
        int v = mine;
        #pragma unroll
        for (int o=1;o<32;o<<=1){ int t2=__shfl_up_sync(0xffffffffu,v,o); if(lane>=o) v+=t2; }
        if (lane==31) wred[wid]=v;
        __syncthreads();
        int woff=0;
        #pragma unroll
        for (int w=0;w<8;w++) if (w<wid) woff+=wred[w];
        v += woff;
        int need0 = s_need;
        int vex = v - mine;
        if (v >= need0 && vex < need0){
            s_pref = s_pref | ((unsigned)(255-tid) << shift);
            s_need = need0 - vex;
        }
        __syncthreads();
    }
    unsigned thr = s_pref;
    int need = s_need;
    int tcnt=0;
    #pragma unroll
    for (int q=0;q<32;q++) tcnt += (keys[q]==thr);
    int v=tcnt;
    #pragma unroll
    for (int o=1;o<32;o<<=1){ int t2=__shfl_up_sync(0xffffffffu,v,o); if(lane>=o) v+=t2; }
    if (lane==31) wred[wid]=v;
    __syncthreads();
    int woff=0;
    #pragma unroll
    for (int w=0;w<8;w++) if (w<wid) woff+=wred[w];
    int rank = v - tcnt + woff;
    int scnt=0;
    int selq[32];
    #pragma unroll
    for (int q=0;q<32;q++){
        unsigned k=keys[q];
        bool eq = (k==thr);
        int s = (k>thr) || (eq && rank < need);
        if (eq) rank++;
        selq[q]=s;
        g_sel[tid*32+q]=s;
        scnt+=s;
    }
    __syncthreads();
    v=scnt;
    #pragma unroll
    for (int o=1;o<32;o<<=1){ int t2=__shfl_up_sync(0xffffffffu,v,o); if(lane>=o) v+=t2; }
    if (lane==31) wred[wid]=v;
    __syncthreads();
    woff=0;
    #pragma unroll
    for (int w=0;w<8;w++) if (w<wid) woff+=wred[w];
    int base = v - scnt + woff;
    #pragma unroll
    for (int q=0;q<32;q++){
        int i = tid*32+q;
        if (selq[q]){ g_col[i]=base; g_ncol[base]=i; base++; }
        else g_col[i]=-1;
    }
}

// ---------------- S CSR count (+ g_fill reset) ----------------
__global__ void k_scount(){
    int d = blockIdx.x*blockDim.x + threadIdx.x;
    if (d >= N_) return;
    g_fill[d]=0;
    if (!g_sel[d]) return;
    int beg=g_rowptr[d], end=g_rowptr[d+1];
    for (int p=beg;p<end;p++) atomicAdd(&g_scnt[g_adj[p].x], 1);
}
__global__ void k_xpsfill(const float* __restrict__ cx){
    int d = blockIdx.x, t = threadIdx.x;
    if (!g_sel[d]) return;
    int colk = g_col[d];
    g_xp[(size_t)colk*128 + t] = cx[(size_t)d*128 + t] * g_fit[d];
    int beg=g_rowptr[d], end=g_rowptr[d+1];
    for (int p=beg+t; p<end; p+=128){
        int s = g_adj[p].x;
        float a = g_alpha[p];
        int pos = g_srowptr[s] + atomicAdd(&g_fill[s],1);
        g_sp[pos] = make_int2(colk, __float_as_int(a));
        unsigned hb = (unsigned)__half_as_ushort(__float2half_rn(a));
        g_spp[pos] = (unsigned)colk | (hb << 16);
    }
}

// ---------------- W = A*S (packed) ----------------
__global__ void k_wcount(){
    int s = blockIdx.x*blockDim.x + threadIdx.x;
    if (s >= N_) return;
    int ob=g_orowptr[s], oe=g_orowptr[s+1];
    int total=0;
    for (int f=ob;f<oe;f++){
        int j = g_oadj[f];
        total += g_srowptr[j+1]-g_srowptr[j];
    }
    g_wcnt[s]=total;
}
__global__ void k_wfill(){
    int s = blockIdx.x*8 + (threadIdx.x>>5);
    int lane = threadIdx.x & 31;
    int wpos = g_wrowptr[s];
    int ob=g_orowptr[s], oe=g_orowptr[s+1];
    for (int f=ob;f<oe;f++){
        int j = g_oadj[f];
        int sb=g_srowptr[j], len=g_srowptr[j+1]-sb;
        for (int q=lane;q<len;q+=32) g_W[wpos+q]=g_spp[sb+q];
        wpos += len;
    }
}

// ---------------- Ac row gather (packed W) ----------------
__global__ void k_AcRow(){
    __shared__ __align__(16) float acc[K_];
    int k = blockIdx.x, tid = threadIdx.x;
    int lane = tid & 31, w = tid >> 5, nw = blockDim.x >> 5;
    {
        float4 z = make_float4(0,0,0,0);
        float4* a4 = (float4*)acc;
        #pragma unroll
        for (int m=0;m<2;m++) a4[tid + m*512] = z;
    }
    __syncthreads();
    int d = g_ncol[k];
    int ib = g_rowptr[d], ie = g_rowptr[d+1];
    for (int p=ib+w; p<ie; p+=nw){
        int s = g_adj[p].x;
        float ae = g_alpha[p];
        int wb = g_wrowptr[s], we = g_wrowptr[s+1];
        int q = wb + lane;
        for (; q+32 < we; q += 64){
            unsigned e0 = g_W[q];
            unsigned e1 = g_W[q+32];
            atomicAdd(&acc[e0 & 0xFFFFu], ae*unp_a(e0));
            atomicAdd(&acc[e1 & 0xFFFFu], ae*unp_a(e1));
        }
        if (q < we){
            unsigned e0 = g_W[q];
            atomicAdd(&acc[e0 & 0xFFFFu], ae*unp_a(e0));
        }
    }
    __syncthreads();
    __half2* orow = (__half2*)(g_Ach + (size_t)k*K_);
    #pragma unroll
    for (int m=0;m<4;m++){
        int i2 = tid + m*512;
        orow[i2] = __floats2half2_rn(acc[2*i2], acc[2*i2+1]);
    }
}

// ---------------- fused adjF ----------------
__global__ void __launch_bounds__(1024, 1) k_adjF(float* __restrict__ adj){
    extern __shared__ __align__(16) char PshB[];
    int2* sc = (int2*)(PshB + 131072);
    int i0 = blockIdx.x*AR, tid = threadIdx.x;

    int qb0 = g_srowptr[i0];
    int qend = g_srowptr[i0+AR];
    int total = qend - qb0;
    int ncache = total < SCACHE ? total : SCACHE;
    for (int q=tid; q<ncache; q+=1024) sc[q] = g_sp[qb0+q];
    __syncthreads();

    #pragma unroll 1
    for (int rp=0;rp<8;rp++){
        float accA[4], accB[4];
        #pragma unroll
        for (int m=0;m<4;m++){ accA[m]=0.f; accB[m]=0.f; }
        #pragma unroll 1
        for (int half_i=0; half_i<2; half_i++){
            int i = i0 + 2*rp + half_i;
            float* acc = half_i ? accB : accA;
            int qb=g_srowptr[i], qe=g_srowptr[i+1];
            if (qe - qb0 <= ncache){
                int base = qb - qb0, len = qe - qb;
                #pragma unroll 2
                for (int q=0;q<len;q++){
                    int2 kp = sc[base+q];
                    float a = __int_as_float(kp.y);
                    const __half2* row = (const __half2*)(g_Ach + (size_t)kp.x*K_);
                    #pragma unroll
                    for (int m=0;m<2;m++){
                        float2 f = __half22float2(row[tid + 1024*m]);
                        acc[2*m]   += a*f.x;
                        acc[2*m+1] += a*f.y;
                    }
                }
            } else {
                for (int q=qb;q<qe;q++){
                    int2 kp = g_sp[q];
                    float a = __int_as_float(kp.y);
                    const __half2* row = (const __half2*)(g_Ach + (size_t)kp.x*K_);
                    #pragma unroll
                    for (int m=0;m<2;m++){
                        float2 f = __half22float2(row[tid + 1024*m]);
                        acc[2*m]   += a*f.x;
                        acc[2*m+1] += a*f.y;
                    }
                }
            }
        }
        char* region = PshB + ((rp<4)? 0 : 65536);
        int woff = (rp & 3)*4;
        #pragma unroll
        for (int m=0;m<2;m++){
            int k0 = 2*(tid + 1024*m);
            *(__half2*)(region + (size_t)k0*16 + woff)     = __floats2half2_rn(accA[2*m],   accB[2*m]);
            *(__half2*)(region + (size_t)(k0+1)*16 + woff) = __floats2half2_rn(accA[2*m+1], accB[2*m+1]);
        }
    }
    __syncthreads();
    for (int j=tid; j<N_; j+=1024){
        float b[16];
        #pragma unroll
        for (int r=0;r<16;r++) b[r]=0.f;
        int qb = g_srowptr[j], qe = g_srowptr[j+1];
        for (int q=qb;q<qe;q++){
            unsigned v = g_spp[q];
            int kk = v & 0xFFFFu;
            float a = unp_a(v);
            uint4 lo = *(const uint4*)(PshB + (size_t)kk*16);
            uint4 hi = *(const uint4*)(PshB + 65536 + (size_t)kk*16);
            float2 f;
            f = __half22float2(*(__half2*)&lo.x); b[0] += a*f.x; b[1] += a*f.y;
            f = __half22float2(*(__half2*)&lo.y); b[2] += a*f.x; b[3] += a*f.y;
            f = __half22float2(*(__half2*)&lo.z); b[4] += a*f.x; b[5] += a*f.y;
            f = __half22float2(*(__half2*)&lo.w); b[6] += a*f.x; b[7] += a*f.y;
            f = __half22float2(*(__half2*)&hi.x); b[8] += a*f.x; b[9] += a*f.y;
            f = __half22float2(*(__half2*)&hi.y); b[10]+= a*f.x; b[11]+= a*f.y;
            f = __half22float2(*(__half2*)&hi.z); b[12]+= a*f.x; b[13]+= a*f.y;
            f = __half22float2(*(__half2*)&hi.w); b[14]+= a*f.x; b[15]+= a*f.y;
        }
        #pragma unroll
        for (int r=0;r<16;r++) adj[(size_t)(i0+r)*N_ + j] = b[r];
    }
}

// x_out (exact alpha)
__global__ void k_xout(float* __restrict__ out){
    int i = blockIdx.x*8 + (threadIdx.x>>5);
    int lane = threadIdx.x & 31;
    const float4* xp4 = (const float4*)g_xp;
    float4 acc = make_float4(0,0,0,0);
    int beg=g_srowptr[i], end=g_srowptr[i+1];
    for (int q=beg;q<end;q++){
        int2 kp = g_sp[q];
        float a = __int_as_float(kp.y);
        float4 v = xp4[(size_t)kp.x*32 + lane];
        acc.x += a*v.x; acc.y += a*v.y; acc.z += a*v.z; acc.w += a*v.w;
    }
    ((float4*)out)[(size_t)i*32 + lane] = acc;
}

// ---------------- host ----------------
static cudaStream_t get_stream(int i){
    static cudaStream_t s[2] = {0,0};
    if (!s[i]) cudaStreamCreate(&s[i]);
    return s[i];
}
static cudaEvent_t get_ev(int which){
    static cudaEvent_t ev[8] = {0,0,0,0,0,0,0,0};
    if (!ev[which]) cudaEventCreateWithFlags(&ev[which], cudaEventDisableTiming);
    return ev[which];
}

extern "C" void kernel_launch(void* const* d_in, const int* in_sizes, int n_in,
                              void* d_out, int out_size){
    const float* nodes = (const float*)d_in[0];
    const int*   edges = (const int*)d_in[1];
    const int* e0 = edges;
    const int* e1 = edges + E_;
    const float* w1 = (const float*)d_in[3];  const float* b1 = (const float*)d_in[4];
    const float* w2 = (const float*)d_in[5];  const float* b2 = (const float*)d_in[6];
    const float* w3 = (const float*)d_in[7];  const float* b3 = (const float*)d_in[8];
    const float* w4 = (const float*)d_in[9];  const float* b4 = (const float*)d_in[10];
    const float* w5 = (const float*)d_in[11]; const float* b5 = (const float*)d_in[12];
    const float* wq = (const float*)d_in[13]; const float* bq = (const float*)d_in[14];
    const float* att = (const float*)d_in[15];
    const float* lw1 = (const float*)d_in[16]; const float* lb1 = (const float*)d_in[17];
    const float* lw2 = (const float*)d_in[18]; const float* lw3 = (const float*)d_in[19];

    float* out = (float*)d_out;
    float* x2out = out;
    float* adj  = out + (size_t)N_*H_;

    float *A,*B,*C,*T; int *scnt,*srowptr,*wcnt,*wrowptr;
    cudaGetSymbolAddress((void**)&A, g_bufA);
    cudaGetSymbolAddress((void**)&B, g_bufB);
    cudaGetSymbolAddress((void**)&C, g_bufC);
    cudaGetSymbolAddress((void**)&T, g_bufT);
    cudaGetSymbolAddress((void**)&scnt, g_scnt);
    cudaGetSymbolAddress((void**)&srowptr, g_srowptr);
    cudaGetSymbolAddress((void**)&wcnt, g_wcnt);
    cudaGetSymbolAddress((void**)&wrowptr, g_wrowptr);

    const int TB = 256;
    const int MB = (M_ + TB - 1)/TB;
    const int NB = (N_ + TB - 1)/TB;

    cudaStream_t s2 = get_stream(0);
    cudaStream_t s3 = get_stream(1);
    cudaEvent_t evF0 = get_ev(0), evJ0 = get_ev(1), evF1 = get_ev(2), evJ1 = get_ev(3);
    cudaEvent_t evF2 = get_ev(4), evJ2 = get_ev(5);

    // fork 0: prevec + first gemm overlap graph prep
    cudaEventRecord(evF0, 0);
    cudaStreamWaitEvent(s2, evF0, 0);
    k_prevec<<<1,128,0,s2>>>(wq, att, bq);
    k_gemm<<<128,256,0,s2>>>(nodes, w1, T);
    cudaEventRecord(evJ0, s2);

    // graph prep
    k_init0<<<NB, TB>>>();
    k_count<<<MB, TB>>>(e0, e1);
    k_scan2<<<2,1024>>>();
    k_fill<<<MB, TB>>>(e0, e1);

    // encoder
    cudaStreamWaitEvent(0, evJ0, 0);
    k_aggr<<<N_/8,256>>>(T, b1, A, 1);
    k_gemm<<<128,256>>>(A, w2, T);
    k_aggr<<<N_/8,256>>>(T, b2, B, 1);       // B = h

    // pooling
    k_segdots<<<N_/8,256>>>(B, att);
    k_acx<<<N_/8,256>>>(B, C, lw1, lw2, lw3);   // fused alpha + cx + LE dots
    k_fit<<<(N_/4 + 7)/8 + 1, 256>>>(lb1);
    k_topk<<<1,256>>>();

    // S CSR
    k_scount<<<NB, TB>>>();
    k_scan8192<<<1,1024>>>(scnt, srowptr);

    // fork 2: wcount + scan(wcnt) depend only on srowptr/oadj — overlap xpsfill
    cudaEventRecord(evF2, 0);
    cudaStreamWaitEvent(s3, evF2, 0);
    k_wcount<<<NB, TB, 0, s3>>>();
    k_scan8192<<<1,1024,0,s3>>>(wcnt, wrowptr);
    cudaEventRecord(evJ2, s3);

    k_xpsfill<<<N_,128>>>(C);

    // fork 1: decoder branch overlaps W/Ac/adj
    cudaEventRecord(evF1, 0);
    cudaStreamWaitEvent(s2, evF1, 0);
    k_xout<<<N_/8,256,0,s2>>>(A);
    k_gemm<<<128,256,0,s2>>>(A, w3, T);
    k_aggr<<<N_/8,256,0,s2>>>(T, b3, B, 1);
    k_gemm<<<128,256,0,s2>>>(B, w4, T);
    k_aggr<<<N_/8,256,0,s2>>>(T, b4, A, 1);
    k_gemm<<<128,256,0,s2>>>(A, w5, T);
    k_aggr<<<N_/8,256,0,s2>>>(T, b5, x2out, 0);
    cudaEventRecord(evJ1, s2);

    // main: W fill (needs wrowptr from s3 + g_spp from xpsfill), Ac, adj
    cudaStreamWaitEvent(0, evJ2, 0);
    k_wfill<<<N_/8, 256>>>();
    k_AcRow<<<K_, 512>>>();
    cudaFuncSetAttribute(k_adjF, cudaFuncAttributeMaxDynamicSharedMemorySize, PSH_TOTAL);
    k_adjF<<<N_/AR, 1024, PSH_TOTAL>>>(adj);

    cudaStreamWaitEvent(0, evJ1, 0);
}

// round 17
// speedup vs baseline: 1.5208x; 1.0522x over previous
#include <cuda_runtime.h>
#include <cuda_fp16.h>
#include <math.h>
#include <stdint.h>

#define N_ 8192
#define E_ 131072
#define M_ (E_ + N_)
#define H_ 128
#define K_ 4096
#define WCAP_ 3000000

#define AR 16
#define SCACHE 1024
#define PSH_TOTAL (131072 + SCACHE*8)

__device__ __forceinline__ void stcs(float* p, float v){
    asm volatile("st.global.cs.f32 [%0], %1;" :: "l"(p), "f"(v) : "memory");
}
__device__ __forceinline__ void stcs4(float* p, float4 v){
    asm volatile("st.global.cs.v4.f32 [%0], {%1,%2,%3,%4};" :: "l"(p), "f"(v.x), "f"(v.y), "f"(v.z), "f"(v.w) : "memory");
}

// ---------------- device scratch ----------------
static __device__ float g_bufA[(size_t)N_*H_];
static __device__ float g_bufB[(size_t)N_*H_];
static __device__ float g_bufC[(size_t)N_*H_];
static __device__ float g_bufT[(size_t)N_*H_];
static __device__ int   g_cnt[N_];
static __device__ int   g_ocnt[N_];
static __device__ int   g_fill[N_];
static __device__ int   g_ofill[N_];
static __device__ int   g_rowptr[N_+1];
static __device__ int   g_orowptr[N_+1];
static __device__ int2  g_adj[M_];
static __device__ int   g_oadj[M_];
static __device__ float g_alpha[M_];
static __device__ float g_aq[N_];
static __device__ float g_ah[N_];
static __device__ float g_vq[H_];
static __device__ float g_cq;
static __device__ float g_cl1[N_], g_cl2[N_], g_cl3[N_];
static __device__ float g_fit[N_];
static __device__ int   g_sel[N_];
static __device__ int   g_col[N_];
static __device__ int   g_ncol[K_];
static __device__ float g_xp[(size_t)K_*H_];
static __device__ int   g_scnt[N_];
static __device__ int   g_srowptr[N_+1];
static __device__ int2  g_sp[M_];            // exact (col k, fp32 alpha bits)
static __device__ unsigned g_spp[M_];        // packed: k | half(alpha)<<16
static __device__ int   g_wcnt[N_];
static __device__ int   g_wrowptr[N_+1];
static __device__ unsigned g_W[WCAP_];
static __device__ __half g_Ach[(size_t)K_*K_];

__device__ __forceinline__ int esrc_f(const int* __restrict__ e0, int e){ return (e < E_) ? e0[e] : (e - E_); }
__device__ __forceinline__ int edst_f(const int* __restrict__ e1, int e){ return (e < E_) ? e1[e] : (e - E_); }
__device__ __forceinline__ float unp_a(unsigned v){ return __half2float(__ushort_as_half((unsigned short)(v>>16))); }

// ---------------- small utility kernels ----------------
__global__ void k_init0(){
    int i = blockIdx.x*blockDim.x + threadIdx.x;
    if (i < N_){ g_cnt[i]=0; g_ocnt[i]=0; g_fill[i]=0; g_ofill[i]=0; g_scnt[i]=0; }
}
__global__ void k_count(const int* __restrict__ e0, const int* __restrict__ e1){
    int e = blockIdx.x*blockDim.x + threadIdx.x;
    if (e < M_){
        atomicAdd(&g_cnt[edst_f(e1,e)], 1);
        atomicAdd(&g_ocnt[esrc_f(e0,e)], 1);
    }
}
__global__ void k_prevec(const float* __restrict__ wq, const float* __restrict__ att,
                         const float* __restrict__ bq){
    int k = threadIdx.x;
    float s = 0.f;
    for (int j=0;j<H_;j++) s += wq[k*H_+j]*att[j];
    g_vq[k] = s;
    if (k==0){
        float c = 0.f;
        for (int j=0;j<H_;j++) c += bq[j]*att[j];
        g_cq = c;
    }
}
__device__ __forceinline__ void scan8192_body(const int* __restrict__ in, int* __restrict__ out){
    __shared__ int wsum[32];
    int tid=threadIdx.x, lane=tid&31, wid=tid>>5;
    int4 a=((const int4*)in)[tid*2], b=((const int4*)in)[tid*2+1];
    int l[8]={a.x,a.y,a.z,a.w,b.x,b.y,b.z,b.w};
    int s=0;
    #pragma unroll
    for(int q=0;q<8;q++) s+=l[q];
    int inc=s;
    #pragma unroll
    for(int o=1;o<32;o<<=1){ int t=__shfl_up_sync(0xffffffffu,inc,o); if(lane>=o) inc+=t; }
    if(lane==31) wsum[wid]=inc;
    __syncthreads();
    if (wid==0){
        int v = wsum[lane];
        #pragma unroll
        for(int o=1;o<32;o<<=1){ int t=__shfl_up_sync(0xffffffffu,v,o); if(lane>=o) v+=t; }
        wsum[lane]=v;
    }
    __syncthreads();
    int r = inc - s + (wid? wsum[wid-1]:0);
    int4 o1,o2;
    o1.x=r; r+=l[0]; o1.y=r; r+=l[1]; o1.z=r; r+=l[2]; o1.w=r; r+=l[3];
    o2.x=r; r+=l[4]; o2.y=r; r+=l[5]; o2.z=r; r+=l[6]; o2.w=r; r+=l[7];
    ((int4*)out)[tid*2]=o1; ((int4*)out)[tid*2+1]=o2;
    if (tid==1023) out[8192]=r;
}
__global__ void k_scan8192(const int* __restrict__ in, int* __restrict__ out){
    scan8192_body(in, out);
}
__global__ void k_scan2(){
    if (blockIdx.x == 0) scan8192_body(g_cnt, g_rowptr);
    else                 scan8192_body(g_ocnt, g_orowptr);
}
__global__ void k_fill(const int* __restrict__ e0, const int* __restrict__ e1){
    int e = blockIdx.x*blockDim.x + threadIdx.x;
    if (e < M_){
        int s = esrc_f(e0,e);
        int d = edst_f(e1,e);
        float nm = rsqrtf((float)g_cnt[s]) * rsqrtf((float)g_cnt[d]);
        int pos = g_rowptr[d] + atomicAdd(&g_fill[d],1);
        g_adj[pos] = make_int2(s, __float_as_int(nm));
        int opos = g_orowptr[s] + atomicAdd(&g_ofill[s],1);
        g_oadj[opos] = d;
    }
}

// ---------------- 8192x128 @ 128x128 GEMM ----------------
__global__ void k_gemm(const float* __restrict__ x, const float* __restrict__ w, float* __restrict__ y){
    __shared__ __align__(16) float xs[128*64];
    int r0 = blockIdx.x*64;
    int tid = threadIdx.x;
    for (int idx=tid; idx<64*128; idx+=256){
        int r = idx >> 7;
        int kk = idx & 127;
        xs[kk*64 + r] = x[(size_t)(r0+r)*128 + kk];
    }
    __syncthreads();
    int cg = tid & 31;
    int rg = tid >> 5;
    float acc[8][4];
    #pragma unroll
    for(int r=0;r<8;r++){ acc[r][0]=0.f;acc[r][1]=0.f;acc[r][2]=0.f;acc[r][3]=0.f; }
    #pragma unroll 4
    for(int kk=0;kk<128;kk++){
        float4 wv = *(const float4*)(w + kk*128 + cg*4);
        float4 x0 = *(const float4*)(xs + kk*64 + rg*8);
        float4 x1 = *(const float4*)(xs + kk*64 + rg*8 + 4);
        float xv[8] = {x0.x,x0.y,x0.z,x0.w,x1.x,x1.y,x1.z,x1.w};
        #pragma unroll
        for(int r=0;r<8;r++){
            acc[r][0] += xv[r]*wv.x; acc[r][1] += xv[r]*wv.y;
            acc[r][2] += xv[r]*wv.z; acc[r][3] += xv[r]*wv.w;
        }
    }
    #pragma unroll
    for(int r=0;r<8;r++){
        float4 o = make_float4(acc[r][0],acc[r][1],acc[r][2],acc[r][3]);
        *(float4*)(y + (size_t)(r0+rg*8+r)*128 + cg*4) = o;
    }
}

// ---------------- GCN aggregation ----------------
__global__ void k_aggr(const float* __restrict__ y, const float* __restrict__ b,
                       float* __restrict__ out, int dotanh, int streamout){
    int d = blockIdx.x*8 + (threadIdx.x>>5);
    int lane = threadIdx.x & 31;
    const float4* y4 = (const float4*)y;
    float4 acc = ((const float4*)b)[lane];
    int beg = g_rowptr[d], end = g_rowptr[d+1];
    int p = beg;
    for (; p+1 < end; p += 2){
        int2 a0 = g_adj[p], a1 = g_adj[p+1];
        float n0 = __int_as_float(a0.y), n1 = __int_as_float(a1.y);
        float4 v0 = y4[(size_t)a0.x*32 + lane];
        float4 v1 = y4[(size_t)a1.x*32 + lane];
        acc.x += n0*v0.x + n1*v1.x;
        acc.y += n0*v0.y + n1*v1.y;
        acc.z += n0*v0.z + n1*v1.z;
        acc.w += n0*v0.w + n1*v1.w;
    }
    if (p < end){
        int2 a0 = g_adj[p];
        float n0 = __int_as_float(a0.y);
        float4 v0 = y4[(size_t)a0.x*32 + lane];
        acc.x += n0*v0.x; acc.y += n0*v0.y; acc.z += n0*v0.z; acc.w += n0*v0.w;
    }
    if (dotanh){
        acc.x = tanhf(acc.x); acc.y = tanhf(acc.y);
        acc.z = tanhf(acc.z); acc.w = tanhf(acc.w);
    }
    if (streamout) stcs4(((float*)out) + ((size_t)d*32 + lane)*4, acc);
    else ((float4*)out)[(size_t)d*32 + lane] = acc;
}

// ---------------- fused segmax + aq/ah dots ----------------
__global__ void k_segdots(const float* __restrict__ h, const float* __restrict__ att){
    int d = blockIdx.x*8 + (threadIdx.x>>5);
    int lane = threadIdx.x & 31;
    const float4* h4 = (const float4*)h;
    float4 mx = make_float4(-INFINITY,-INFINITY,-INFINITY,-INFINITY);
    int beg = g_rowptr[d], end = g_rowptr[d+1];
    for (int p=beg; p<end; p++){
        float4 v = h4[(size_t)g_adj[p].x*32 + lane];
        mx.x = fmaxf(mx.x,v.x); mx.y = fmaxf(mx.y,v.y);
        mx.z = fmaxf(mx.z,v.z); mx.w = fmaxf(mx.w,v.w);
    }
    float4 vv = ((const float4*)g_vq)[lane];
    float4 a2 = ((const float4*)att)[32+lane];
    float4 hd = h4[(size_t)d*32 + lane];
    float s1 = mx.x*vv.x + mx.y*vv.y + mx.z*vv.z + mx.w*vv.w;
    float s2 = hd.x*a2.x + hd.y*a2.y + hd.z*a2.z + hd.w*a2.w;
    #pragma unroll
    for (int o=16;o;o>>=1){
        s1 += __shfl_down_sync(0xffffffffu,s1,o);
        s2 += __shfl_down_sync(0xffffffffu,s2,o);
    }
    if (!lane){ g_aq[d]=s1+g_cq; g_ah[d]=s2; }
}

// ---------------- fused alpha softmax + cx + LE dots ----------------
__global__ void k_acx(const float* __restrict__ h, float* __restrict__ cx,
                      const float* __restrict__ lw1, const float* __restrict__ lw2,
                      const float* __restrict__ lw3){
    int d = blockIdx.x*8 + (threadIdx.x>>5);
    int lane = threadIdx.x & 31;
    int beg = g_rowptr[d], end = g_rowptr[d+1];
    float aqd = g_aq[d];
    float mx = -INFINITY;
    for (int p=beg+lane; p<end; p+=32){
        float sc = aqd + g_ah[g_adj[p].x];
        sc = sc > 0.f ? sc : 0.2f*sc;
        mx = fmaxf(mx, sc);
    }
    #pragma unroll
    for (int o=16;o;o>>=1) mx = fmaxf(mx, __shfl_xor_sync(0xffffffffu, mx, o));
    float sm = 0.f;
    for (int p=beg+lane; p<end; p+=32){
        float sc = aqd + g_ah[g_adj[p].x];
        sc = sc > 0.f ? sc : 0.2f*sc;
        sm += __expf(sc - mx);
    }
    #pragma unroll
    for (int o=16;o;o>>=1) sm += __shfl_xor_sync(0xffffffffu, sm, o);
    float inv = 1.f/sm;
    for (int p=beg+lane; p<end; p+=32){
        float sc = aqd + g_ah[g_adj[p].x];
        sc = sc > 0.f ? sc : 0.2f*sc;
        g_alpha[p] = __expf(sc - mx)*inv;
    }
    __syncwarp();
    const float4* h4 = (const float4*)h;
    float4 acc = make_float4(0,0,0,0);
    int p = beg;
    for (; p+1 < end; p += 2){
        float a0 = g_alpha[p], a1 = g_alpha[p+1];
        float4 v0 = h4[(size_t)g_adj[p].x*32 + lane];
        float4 v1 = h4[(size_t)g_adj[p+1].x*32 + lane];
        acc.x += a0*v0.x + a1*v1.x;
        acc.y += a0*v0.y + a1*v1.y;
        acc.z += a0*v0.z + a1*v1.z;
        acc.w += a0*v0.w + a1*v1.w;
    }
    if (p < end){
        float a0 = g_alpha[p];
        float4 v0 = h4[(size_t)g_adj[p].x*32 + lane];
        acc.x += a0*v0.x; acc.y += a0*v0.y; acc.z += a0*v0.z; acc.w += a0*v0.w;
    }
    ((float4*)cx)[(size_t)d*32 + lane] = acc;
    float4 w1v = ((const float4*)lw1)[lane];
    float4 w2v = ((const float4*)lw2)[lane];
    float4 w3v = ((const float4*)lw3)[lane];
    float s1 = acc.x*w1v.x + acc.y*w1v.y + acc.z*w1v.z + acc.w*w1v.w;
    float s2 = acc.x*w2v.x + acc.y*w2v.y + acc.z*w2v.z + acc.w*w2v.w;
    float s3 = acc.x*w3v.x + acc.y*w3v.y + acc.z*w3v.z + acc.w*w3v.w;
    #pragma unroll
    for (int o=16;o;o>>=1){
        s1 += __shfl_down_sync(0xffffffffu,s1,o);
        s2 += __shfl_down_sync(0xffffffffu,s2,o);
        s3 += __shfl_down_sync(0xffffffffu,s3,o);
    }
    if (!lane){ g_cl1[d]=s1; g_cl2[d]=s2; g_cl3[d]=s3; }
}

__global__ void k_fit(const float* __restrict__ lb1){
    int w = (blockIdx.x*blockDim.x + threadIdx.x) >> 5;
    int lane = threadIdx.x & 31;
    int d = w*4 + (lane>>3);
    int sub = lane & 7;
    if (d >= N_) return;
    int beg=g_rowptr[d], end=g_rowptr[d+1];
    float s = 0.f;
    for (int q=beg+sub;q<end;q+=8) s += g_cl3[g_adj[q].x];
    #pragma unroll
    for (int o=4;o;o>>=1) s += __shfl_down_sync(0xffffffffu, s, o, 8);
    if (!sub){
        float aggr = (float)(end-beg)*g_cl2[d] - s;
        float z = g_cl1[d] + lb1[0] + aggr;
        g_fit[d] = 1.f/(1.f + __expf(-z));
    }
}

// ---------------- top-K via 4x8-bit histogram radix select ----------------
__global__ void k_topk(){
    __shared__ int hist[256];
    __shared__ int wred[8];
    __shared__ unsigned s_pref;
    __shared__ int s_need;
    int tid=threadIdx.x, lane=tid&31, wid=tid>>5;
    if (tid==0){ s_pref=0u; s_need=K_; }
    unsigned keys[32];
    #pragma unroll
    for (int q=0;q<32;q++){
        unsigned u=__float_as_uint(g_fit[tid*32+q]);
        keys[q] = (u & 0x80000000u) ? ~u : (u | 0x80000000u);
    }
    __syncthreads();
    for (int round=0; round<4; round++){
        int shift = 24 - 8*round;
        hist[tid]=0;
        __syncthreads();
        unsigned pref = s_pref;
        #pragma unroll
        for (int q=0;q<32;q++){
            unsigned k = keys[q];
            bool match = (round==0) || ((k >> (shift+8)) == (pref >> (shift+8)));
            if (match) atomicAdd(&hist[(k>>shift)&0xFFu], 1);
        }
        __syncthreads();
        int mine = hist[255-tid];
        int v = mine;
        #pragma unroll
        for (int o=1;o<32;o<<=1){ int t2=__shfl_up_sync(0xffffffffu,v,o); if(lane>=o) v+=t2; }
        if (lane==31) wred[wid]=v;
        __syncthreads();
        int woff=0;
        #pragma unroll
        for (int w=0;w<8;w++) if (w<wid) woff+=wred[w];
        v += woff;
        int need0 = s_need;
        int vex = v - mine;
        if (v >= need0 && vex < need0){
            s_pref = s_pref | ((unsigned)(255-tid) << shift);
            s_need = need0 - vex;
        }
        __syncthreads();
    }
    unsigned thr = s_pref;
    int need = s_need;
    int tcnt=0;
    #pragma unroll
    for (int q=0;q<32;q++) tcnt += (keys[q]==thr);
    int v=tcnt;
    #pragma unroll
    for (int o=1;o<32;o<<=1){ int t2=__shfl_up_sync(0xffffffffu,v,o); if(lane>=o) v+=t2; }
    if (lane==31) wred[wid]=v;
    __syncthreads();
    int woff=0;
    #pragma unroll
    for (int w=0;w<8;w++) if (w<wid) woff+=wred[w];
    int rank = v - tcnt + woff;
    int scnt=0;
    int selq[32];
    #pragma unroll
    for (int q=0;q<32;q++){
        unsigned k=keys[q];
        bool eq = (k==thr);
        int s = (k>thr) || (eq && rank < need);
        if (eq) rank++;
        selq[q]=s;
        g_sel[tid*32+q]=s;
        scnt+=s;
    }
    __syncthreads();
    v=scnt;
    #pragma unroll
    for (int o=1;o<32;o<<=1){ int t2=__shfl_up_sync(0xffffffffu,v,o); if(lane>=o) v+=t2; }
    if (lane==31) wred[wid]=v;
    __syncthreads();
    woff=0;
    #pragma unroll
    for (int w=0;w<8;w++) if (w<wid) woff+=wred[w];
    int base = v - scnt + woff;
    #pragma unroll
    for (int q=0;q<32;q++){
        int i = tid*32+q;
        if (selq[q]){ g_col[i]=base; g_ncol[base]=i; base++; }
        else g_col[i]=-1;
    }
}

// ---------------- S CSR count (+ g_fill reset) ----------------
__global__ void k_scount(){
    int d = blockIdx.x*blockDim.x + threadIdx.x;
    if (d >= N_) return;
    g_fill[d]=0;
    if (!g_sel[d]) return;
    int beg=g_rowptr[d], end=g_rowptr[d+1];
    for (int p=beg;p<end;p++) atomicAdd(&g_scnt[g_adj[p].x], 1);
}
__global__ void k_xpsfill(const float* __restrict__ cx){
    int d = blockIdx.x, t = threadIdx.x;
    if (!g_sel[d]) return;
    int colk = g_col[d];
    g_xp[(size_t)colk*128 + t] = cx[(size_t)d*128 + t] * g_fit[d];
    int beg=g_rowptr[d], end=g_rowptr[d+1];
    for (int p=beg+t; p<end; p+=128){
        int s = g_adj[p].x;
        float a = g_alpha[p];
        int pos = g_srowptr[s] + atomicAdd(&g_fill[s],1);
        g_sp[pos] = make_int2(colk, __float_as_int(a));
        unsigned hb = (unsigned)__half_as_ushort(__float2half_rn(a));
        g_spp[pos] = (unsigned)colk | (hb << 16);
    }
}

// ---------------- W = A*S (packed) ----------------
__global__ void k_wcount(){
    int s = blockIdx.x*blockDim.x + threadIdx.x;
    if (s >= N_) return;
    int ob=g_orowptr[s], oe=g_orowptr[s+1];
    int total=0;
    for (int f=ob;f<oe;f++){
        int j = g_oadj[f];
        total += g_srowptr[j+1]-g_srowptr[j];
    }
    g_wcnt[s]=total;
}
__global__ void k_wfill(){
    int s = blockIdx.x*8 + (threadIdx.x>>5);
    int lane = threadIdx.x & 31;
    int wpos = g_wrowptr[s];
    int ob=g_orowptr[s], oe=g_orowptr[s+1];
    for (int f=ob;f<oe;f++){
        int j = g_oadj[f];
        int sb=g_srowptr[j], len=g_srowptr[j+1]-sb;
        for (int q=lane;q<len;q+=32) g_W[wpos+q]=g_spp[sb+q];
        wpos += len;
    }
}

// ---------------- Ac row gather (packed W) ----------------
__global__ void k_AcRow(){
    __shared__ __align__(16) float acc[K_];
    int k = blockIdx.x, tid = threadIdx.x;
    int lane = tid & 31, w = tid >> 5, nw = blockDim.x >> 5;
    {
        float4 z = make_float4(0,0,0,0);
        float4* a4 = (float4*)acc;
        #pragma unroll
        for (int m=0;m<2;m++) a4[tid + m*512] = z;
    }
    __syncthreads();
    int d = g_ncol[k];
    int ib = g_rowptr[d], ie = g_rowptr[d+1];
    for (int p=ib+w; p<ie; p+=nw){
        int s = g_adj[p].x;
        float ae = g_alpha[p];
        int wb = g_wrowptr[s], we = g_wrowptr[s+1];
        int q = wb + lane;
        for (; q+32 < we; q += 64){
            unsigned e0 = g_W[q];
            unsigned e1 = g_W[q+32];
            atomicAdd(&acc[e0 & 0xFFFFu], ae*unp_a(e0));
            atomicAdd(&acc[e1 & 0xFFFFu], ae*unp_a(e1));
        }
        if (q < we){
            unsigned e0 = g_W[q];
            atomicAdd(&acc[e0 & 0xFFFFu], ae*unp_a(e0));
        }
    }
    __syncthreads();
    __half2* orow = (__half2*)(g_Ach + (size_t)k*K_);
    #pragma unroll
    for (int m=0;m<4;m++){
        int i2 = tid + m*512;
        orow[i2] = __floats2half2_rn(acc[2*i2], acc[2*i2+1]);
    }
}

// ---------------- fused adjF (evict-first adj stores) ----------------
__global__ void __launch_bounds__(1024, 1) k_adjF(float* __restrict__ adj){
    extern __shared__ __align__(16) char PshB[];
    int2* sc = (int2*)(PshB + 131072);
    int i0 = blockIdx.x*AR, tid = threadIdx.x;

    int qb0 = g_srowptr[i0];
    int qend = g_srowptr[i0+AR];
    int total = qend - qb0;
    int ncache = total < SCACHE ? total : SCACHE;
    for (int q=tid; q<ncache; q+=1024) sc[q] = g_sp[qb0+q];
    __syncthreads();

    #pragma unroll 1
    for (int rp=0;rp<8;rp++){
        float accA[4], accB[4];
        #pragma unroll
        for (int m=0;m<4;m++){ accA[m]=0.f; accB[m]=0.f; }
        #pragma unroll 1
        for (int half_i=0; half_i<2; half_i++){
            int i = i0 + 2*rp + half_i;
            float* acc = half_i ? accB : accA;
            int qb=g_srowptr[i], qe=g_srowptr[i+1];
            if (qe - qb0 <= ncache){
                int base = qb - qb0, len = qe - qb;
                #pragma unroll 2
                for (int q=0;q<len;q++){
                    int2 kp = sc[base+q];
                    float a = __int_as_float(kp.y);
                    const __half2* row = (const __half2*)(g_Ach + (size_t)kp.x*K_);
                    #pragma unroll
                    for (int m=0;m<2;m++){
                        float2 f = __half22float2(row[tid + 1024*m]);
                        acc[2*m]   += a*f.x;
                        acc[2*m+1] += a*f.y;
                    }
                }
            } else {
                for (int q=qb;q<qe;q++){
                    int2 kp = g_sp[q];
                    float a = __int_as_float(kp.y);
                    const __half2* row = (const __half2*)(g_Ach + (size_t)kp.x*K_);
                    #pragma unroll
                    for (int m=0;m<2;m++){
                        float2 f = __half22float2(row[tid + 1024*m]);
                        acc[2*m]   += a*f.x;
                        acc[2*m+1] += a*f.y;
                    }
                }
            }
        }
        char* region = PshB + ((rp<4)? 0 : 65536);
        int woff = (rp & 3)*4;
        #pragma unroll
        for (int m=0;m<2;m++){
            int k0 = 2*(tid + 1024*m);
            *(__half2*)(region + (size_t)k0*16 + woff)     = __floats2half2_rn(accA[2*m],   accB[2*m]);
            *(__half2*)(region + (size_t)(k0+1)*16 + woff) = __floats2half2_rn(accA[2*m+1], accB[2*m+1]);
        }
    }
    __syncthreads();
    for (int j=tid; j<N_; j+=1024){
        float b[16];
        #pragma unroll
        for (int r=0;r<16;r++) b[r]=0.f;
        int qb = g_srowptr[j], qe = g_srowptr[j+1];
        #pragma unroll 2
        for (int q=qb;q<qe;q++){
            unsigned v = g_spp[q];
            int kk = v & 0xFFFFu;
            float a = unp_a(v);
            uint4 lo = *(const uint4*)(PshB + (size_t)kk*16);
            uint4 hi = *(const uint4*)(PshB + 65536 + (size_t)kk*16);
            float2 f;
            f = __half22float2(*(__half2*)&lo.x); b[0] += a*f.x; b[1] += a*f.y;
            f = __half22float2(*(__half2*)&lo.y); b[2] += a*f.x; b[3] += a*f.y;
            f = __half22float2(*(__half2*)&lo.z); b[4] += a*f.x; b[5] += a*f.y;
            f = __half22float2(*(__half2*)&lo.w); b[6] += a*f.x; b[7] += a*f.y;
            f = __half22float2(*(__half2*)&hi.x); b[8] += a*f.x; b[9] += a*f.y;
            f = __half22float2(*(__half2*)&hi.y); b[10]+= a*f.x; b[11]+= a*f.y;
            f = __half22float2(*(__half2*)&hi.z); b[12]+= a*f.x; b[13]+= a*f.y;
            f = __half22float2(*(__half2*)&hi.w); b[14]+= a*f.x; b[15]+= a*f.y;
        }
        #pragma unroll
        for (int r=0;r<16;r++) stcs(&adj[(size_t)(i0+r)*N_ + j], b[r]);
    }
}

// x_out (exact alpha)
__global__ void k_xout(float* __restrict__ out){
    int i = blockIdx.x*8 + (threadIdx.x>>5);
    int lane = threadIdx.x & 31;
    const float4* xp4 = (const float4*)g_xp;
    float4 acc = make_float4(0,0,0,0);
    int beg=g_srowptr[i], end=g_srowptr[i+1];
    for (int q=beg;q<end;q++){
        int2 kp = g_sp[q];
        float a = __int_as_float(kp.y);
        float4 v = xp4[(size_t)kp.x*32 + lane];
        acc.x += a*v.x; acc.y += a*v.y; acc.z += a*v.z; acc.w += a*v.w;
    }
    ((float4*)out)[(size_t)i*32 + lane] = acc;
}

// ---------------- host ----------------
static cudaStream_t get_stream(int i){
    static cudaStream_t s[2] = {0,0};
    if (!s[i]) cudaStreamCreate(&s[i]);
    return s[i];
}
static cudaEvent_t get_ev(int which){
    static cudaEvent_t ev[8] = {0,0,0,0,0,0,0,0};
    if (!ev[which]) cudaEventCreateWithFlags(&ev[which], cudaEventDisableTiming);
    return ev[which];
}

extern "C" void kernel_launch(void* const* d_in, const int* in_sizes, int n_in,
                              void* d_out, int out_size){
    const float* nodes = (const float*)d_in[0];
    const int*   edges = (const int*)d_in[1];
    const int* e0 = edges;
    const int* e1 = edges + E_;
    const float* w1 = (const float*)d_in[3];  const float* b1 = (const float*)d_in[4];
    const float* w2 = (const float*)d_in[5];  const float* b2 = (const float*)d_in[6];
    const float* w3 = (const float*)d_in[7];  const float* b3 = (const float*)d_in[8];
    const float* w4 = (const float*)d_in[9];  const float* b4 = (const float*)d_in[10];
    const float* w5 = (const float*)d_in[11]; const float* b5 = (const float*)d_in[12];
    const float* wq = (const float*)d_in[13]; const float* bq = (const float*)d_in[14];
    const float* att = (const float*)d_in[15];
    const float* lw1 = (const float*)d_in[16]; const float* lb1 = (const float*)d_in[17];
    const float* lw2 = (const float*)d_in[18]; const float* lw3 = (const float*)d_in[19];

    float* out = (float*)d_out;
    float* x2out = out;
    float* adj  = out + (size_t)N_*H_;

    float *A,*B,*C,*T; int *scnt,*srowptr,*wcnt,*wrowptr;
    cudaGetSymbolAddress((void**)&A, g_bufA);
    cudaGetSymbolAddress((void**)&B, g_bufB);
    cudaGetSymbolAddress((void**)&C, g_bufC);
    cudaGetSymbolAddress((void**)&T, g_bufT);
    cudaGetSymbolAddress((void**)&scnt, g_scnt);
    cudaGetSymbolAddress((void**)&srowptr, g_srowptr);
    cudaGetSymbolAddress((void**)&wcnt, g_wcnt);
    cudaGetSymbolAddress((void**)&wrowptr, g_wrowptr);

    const int TB = 256;
    const int MB = (M_ + TB - 1)/TB;
    const int NB = (N_ + TB - 1)/TB;

    cudaStream_t s2 = get_stream(0);
    cudaStream_t s3 = get_stream(1);
    cudaEvent_t evF0 = get_ev(0), evJ0 = get_ev(1), evF1 = get_ev(2), evJ1 = get_ev(3);
    cudaEvent_t evF2 = get_ev(4), evJ2 = get_ev(5);

    // fork 0: prevec + first gemm overlap graph prep
    cudaEventRecord(evF0, 0);
    cudaStreamWaitEvent(s2, evF0, 0);
    k_prevec<<<1,128,0,s2>>>(wq, att, bq);
    k_gemm<<<128,256,0,s2>>>(nodes, w1, T);
    cudaEventRecord(evJ0, s2);

    // graph prep
    k_init0<<<NB, TB>>>();
    k_count<<<MB, TB>>>(e0, e1);
    k_scan2<<<2,1024>>>();
    k_fill<<<MB, TB>>>(e0, e1);

    // encoder
    cudaStreamWaitEvent(0, evJ0, 0);
    k_aggr<<<N_/8,256>>>(T, b1, A, 1, 0);
    k_gemm<<<128,256>>>(A, w2, T);
    k_aggr<<<N_/8,256>>>(T, b2, B, 1, 0);    // B = h

    // pooling
    k_segdots<<<N_/8,256>>>(B, att);
    k_acx<<<N_/8,256>>>(B, C, lw1, lw2, lw3);
    k_fit<<<(N_/4 + 7)/8 + 1, 256>>>(lb1);
    k_topk<<<1,256>>>();

    // S CSR
    k_scount<<<NB, TB>>>();
    k_scan8192<<<1,1024>>>(scnt, srowptr);

    // fork 2: wcount + scan(wcnt) overlap xpsfill
    cudaEventRecord(evF2, 0);
    cudaStreamWaitEvent(s3, evF2, 0);
    k_wcount<<<NB, TB, 0, s3>>>();
    k_scan8192<<<1,1024,0,s3>>>(wcnt, wrowptr);
    cudaEventRecord(evJ2, s3);

    k_xpsfill<<<N_,128>>>(C);

    // fork 1: decoder branch overlaps W/Ac/adj
    cudaEventRecord(evF1, 0);
    cudaStreamWaitEvent(s2, evF1, 0);
    k_xout<<<N_/8,256,0,s2>>>(A);
    k_gemm<<<128,256,0,s2>>>(A, w3, T);
    k_aggr<<<N_/8,256,0,s2>>>(T, b3, B, 1, 0);
    k_gemm<<<128,256,0,s2>>>(B, w4, T);
    k_aggr<<<N_/8,256,0,s2>>>(T, b4, A, 1, 0);
    k_gemm<<<128,256,0,s2>>>(A, w5, T);
    k_aggr<<<N_/8,256,0,s2>>>(T, b5, x2out, 0, 1);   // final output: evict-first
    cudaEventRecord(evJ1, s2);

    // main: W fill, Ac (fp16), adj
    cudaStreamWaitEvent(0, evJ2, 0);
    k_wfill<<<N_/8, 256>>>();
    k_AcRow<<<K_, 512>>>();
    cudaFuncSetAttribute(k_adjF, cudaFuncAttributeMaxDynamicSharedMemorySize, PSH_TOTAL);
    k_adjF<<<N_/AR, 1024, PSH_TOTAL>>>(adj);

    cudaStreamWaitEvent(0, evJ1, 0);
}